// round 12
// baseline (speedup 1.0000x reference)
#include <cuda_runtime.h>
#include <cuda_bf16.h>
#include <math.h>

// ---------------- problem constants ----------------
#define BATCH   16
#define LSEQ    1024
#define DMODEL  64
#define DINNER  128
#define SSTATE  16
#define MROWS   (BATCH*LSEQ)   // 16384
#define HFFN    256
#define NNODE   1024
#define EDIM    10
#define PLOUT   96
#define NCHUNK  8
#define CHLEN   128

// ---------------- scratch (single static device buffer) ----------------
__device__ float g_scratch[57315328];

__device__ __forceinline__ float silu_(float x) { return x / (1.f + __expf(-x)); }

// ---------------- prep: fold weights (transposed bf16 hi/lo), A=-exp, x copy ------
__global__ void prep_k(const float* __restrict__ fw_in, const float* __restrict__ bw_in,
                       const float* __restrict__ fwx, const float* __restrict__ fwdt,
                       const float* __restrict__ bwx, const float* __restrict__ bwdt,
                       const float* __restrict__ fwA, const float* __restrict__ bwA,
                       const float* __restrict__ fw_out, const float* __restrict__ bw_out,
                       const float* __restrict__ x_in,
                       __nv_bfloat16* __restrict__ wcatTh, __nv_bfloat16* __restrict__ wcatTl,
                       __nv_bfloat16* __restrict__ wc0Th, __nv_bfloat16* __restrict__ wc0Tl,
                       __nv_bfloat16* __restrict__ wc1Th, __nv_bfloat16* __restrict__ wc1Tl,
                       float* __restrict__ A0, float* __restrict__ A1,
                       float* __restrict__ Wocat,
                       float* __restrict__ xbuf,
                       __nv_bfloat16* __restrict__ xbufh, __nv_bfloat16* __restrict__ xbufl)
{
    int g = blockIdx.x * 256 + threadIdx.x;
    if (g < 32768) {  // WcatT [512][64] bf16 hi/lo
        int j = g >> 6, k = g & 63;
        float v = (j < 256) ? fw_in[k*256 + j] : bw_in[k*256 + (j-256)];
        __nv_bfloat16 hh = __float2bfloat16(v);
        wcatTh[g] = hh;
        wcatTl[g] = __float2bfloat16(v - __bfloat162float(hh));
        return;
    }
    int h = g - 32768;
    if (h < 40960) {  // WcombT per dir: [160][128] bf16 hi/lo
        int dir = h / 20480; int r2 = h % 20480;
        int j = r2 >> 7, i = r2 & 127;   // j in [0,160) output col, i in [0,128) K
        const float* Wx  = dir ? bwx  : fwx;
        const float* Wdt = dir ? bwdt : fwdt;
        float v;
        if (j < 128) {
            v = 0.f;
            #pragma unroll
            for (int r = 0; r < 4; r++) v = fmaf(Wx[i*36 + r], Wdt[r*128 + j], v);
        } else {
            v = Wx[i*36 + 4 + (j - 128)];
        }
        __nv_bfloat16 hh = __float2bfloat16(v);
        __nv_bfloat16 ll = __float2bfloat16(v - __bfloat162float(hh));
        if (dir) { wc1Th[j*128 + i] = hh; wc1Tl[j*128 + i] = ll; }
        else     { wc0Th[j*128 + i] = hh; wc0Tl[j*128 + i] = ll; }
        return;
    }
    h -= 40960;
    if (h < 4096) {  // A
        int dir = h >> 11; int i = h & 2047;
        (dir ? A1 : A0)[i] = -__expf((dir ? bwA : fwA)[i]);
        return;
    }
    h -= 4096;
    if (h < 16384) {  // Wocat (256,64) fp32
        int r = h >> 6, c = h & 63;
        Wocat[h] = (r < 128) ? fw_out[r*64 + c] : bw_out[(r-128)*64 + c];
        return;
    }
    h -= 16384;
    if (h < MROWS*DMODEL) {  // xbuf fp32 + hi/lo
        float v = x_in[h];
        xbuf[h] = v;
        __nv_bfloat16 hh = __float2bfloat16(v);
        xbufh[h] = hh;
        xbufl[h] = __float2bfloat16(v - __bfloat162float(hh));
    }
}

// ---------------- generic tiled SGEMM, 64x64 tiles, double-buffered (fp32) --------
// EPI: 2 bias+relu, 6 +aux0(col), 7 +aux0(full)+LN, 8 +aux0(full)+aux1(col)+LN(+hi/lo out)
template<int EPI, int SPLIT>
__global__ void __launch_bounds__(256) sgemm_k(
    const float* __restrict__ A, const float* __restrict__ B, float* __restrict__ C,
    int M, int N, int K,
    const float* __restrict__ aux0, const float* __restrict__ aux1,
    float* __restrict__ o1, float* __restrict__ o2,
    const float* __restrict__ B2, const float* __restrict__ aux0b,
    __nv_bfloat16* __restrict__ ohi, __nv_bfloat16* __restrict__ olo)
{
    __shared__ float As[2][16][64];
    __shared__ float Bs[2][16][64];
    int row0 = blockIdx.y * 64, col0 = blockIdx.x * 64;
    if (SPLIT && row0 >= (M >> 1)) { B = B2; aux0 = aux0b; }
    int tid = threadIdx.x;
    int tx = tid & 15, ty = tid >> 4;
    int a_m = tid >> 2, a_k = (tid & 3) * 4;
    int b_k = tid >> 4, b_n = (tid & 15) * 4;
    const float* Aptr = A + (size_t)(row0 + a_m) * K + a_k;
    int bc = col0 + b_n;
    bool bok = bc < N;
    const float* Bptr = B + (size_t)b_k * N + bc;

    float acc[4][4];
    #pragma unroll
    for (int i = 0; i < 4; i++)
        #pragma unroll
        for (int j = 0; j < 4; j++) acc[i][j] = 0.f;

    {
        float4 av = *(const float4*)(Aptr);
        float4 bv = bok ? *(const float4*)(Bptr) : make_float4(0.f,0.f,0.f,0.f);
        As[0][a_k+0][a_m] = av.x; As[0][a_k+1][a_m] = av.y;
        As[0][a_k+2][a_m] = av.z; As[0][a_k+3][a_m] = av.w;
        *(float4*)&Bs[0][b_k][b_n] = bv;
    }
    __syncthreads();

    int buf = 0;
    for (int k0 = 16; ; k0 += 16) {
        bool has = (k0 < K);
        float4 av2, bv2;
        if (has) {
            av2 = *(const float4*)(Aptr + k0);
            bv2 = bok ? *(const float4*)(Bptr + (size_t)k0 * N) : make_float4(0.f,0.f,0.f,0.f);
        }
        #pragma unroll
        for (int kk = 0; kk < 16; kk++) {
            float am[4], bn[4];
            *(float4*)am = *(const float4*)&As[buf][kk][ty*4];
            *(float4*)bn = *(const float4*)&Bs[buf][kk][tx*4];
            #pragma unroll
            for (int i = 0; i < 4; i++)
                #pragma unroll
                for (int j = 0; j < 4; j++)
                    acc[i][j] = fmaf(am[i], bn[j], acc[i][j]);
        }
        if (!has) break;
        int nb = buf ^ 1;
        As[nb][a_k+0][a_m] = av2.x; As[nb][a_k+1][a_m] = av2.y;
        As[nb][a_k+2][a_m] = av2.z; As[nb][a_k+3][a_m] = av2.w;
        *(float4*)&Bs[nb][b_k][b_n] = bv2;
        __syncthreads();
        buf = nb;
    }

    if (EPI == 7 || EPI == 8) {
        float vv[4][4];
        #pragma unroll
        for (int i = 0; i < 4; i++) {
            int row = row0 + ty*4 + i;
            #pragma unroll
            for (int j = 0; j < 4; j++) {
                int col = tx*4 + j;
                float v = acc[i][j] + aux0[(size_t)row*64 + col];
                if (EPI == 8) v += aux1[col];
                vv[i][j] = v;
            }
        }
        #pragma unroll
        for (int i = 0; i < 4; i++) {
            float sm = vv[i][0] + vv[i][1] + vv[i][2] + vv[i][3];
            float sq = vv[i][0]*vv[i][0] + vv[i][1]*vv[i][1]
                     + vv[i][2]*vv[i][2] + vv[i][3]*vv[i][3];
            #pragma unroll
            for (int o = 8; o > 0; o >>= 1) {
                sm += __shfl_xor_sync(0xffffffffu, sm, o);
                sq += __shfl_xor_sync(0xffffffffu, sq, o);
            }
            float mean = sm * (1.f/64.f);
            float var  = sq * (1.f/64.f) - mean*mean;
            float r = rsqrtf(var + 1e-5f);
            int row = row0 + ty*4 + i;
            #pragma unroll
            for (int j = 0; j < 4; j++) {
                int col = tx*4 + j;
                float w = (vv[i][j] - mean) * r * o1[col] + o2[col];
                C[(size_t)row*64 + col] = w;
                if (EPI == 8) {
                    __nv_bfloat16 hh = __float2bfloat16(w);
                    ohi[(size_t)row*64 + col] = hh;
                    olo[(size_t)row*64 + col] = __float2bfloat16(w - __bfloat162float(hh));
                }
            }
        }
        return;
    }

    #pragma unroll
    for (int i = 0; i < 4; i++) {
        int row = row0 + ty*4 + i;
        #pragma unroll
        for (int j = 0; j < 4; j++) {
            int col = col0 + tx*4 + j;
            if (col >= N) continue;
            float v = acc[i][j];
            size_t idx = (size_t)row * N + col;
            if (EPI == 2) {
                float t = v + aux0[col];
                C[idx] = t > 0.f ? t : 0.f;
            } else if (EPI == 6) {
                C[idx] = v + aux0[col];
            }
        }
    }
}

// ================= generalized bf16 split GEMM via mma.sync =================
// C[M,N] = A @ B^T ; A row-major [M][K] hi/lo bf16 ; B given as [N][K] hi/lo bf16.
// 3-term split, fp32 accumulate. 64x64 tile, 128 threads, double-buffered.
// EPI 0: store C[row*Nact+col] (Nact multiple of 64).
// EPI 1: xproj split: col<128 softplus(dt+aux0) -> C[row*128+..]; 128..143 -> o1; 144..159 -> o2.
// SPLIT: rows >= M/2 use B2 and aux0b.
#define MMA_BF16(d, A0, A1, A2, A3, Bb0, Bb1) \
    asm volatile("mma.sync.aligned.m16n8k16.row.col.f32.bf16.bf16.f32 " \
                 "{%0,%1,%2,%3}, {%4,%5,%6,%7}, {%8,%9}, {%0,%1,%2,%3};" \
                 : "+f"((d)[0]), "+f"((d)[1]), "+f"((d)[2]), "+f"((d)[3]) \
                 : "r"(A0), "r"(A1), "r"(A2), "r"(A3), "r"(Bb0), "r"(Bb1))

template<int EPI, int SPLIT>
__global__ void __launch_bounds__(128) tcg_k(
    const __nv_bfloat16* __restrict__ Ahi, const __nv_bfloat16* __restrict__ Alo,
    const __nv_bfloat16* __restrict__ Bhi, const __nv_bfloat16* __restrict__ Blo,
    const __nv_bfloat16* __restrict__ B2hi, const __nv_bfloat16* __restrict__ B2lo,
    float* __restrict__ C, int M, int Nact, int K,
    const float* __restrict__ aux0, const float* __restrict__ aux0b,
    float* __restrict__ o1, float* __restrict__ o2)
{
    __shared__ __align__(16) __nv_bfloat16 As[2][2][64*16];
    __shared__ __align__(16) __nv_bfloat16 Bs[2][2][64*16];
    int tid = threadIdx.x, lane = tid & 31, warp = tid >> 5;
    int row0 = blockIdx.y * 64, col0 = blockIdx.x * 64;
    if (SPLIT && row0 >= (M >> 1)) { Bhi = B2hi; Blo = B2lo; aux0 = aux0b; }
    int wm = (warp & 1) * 32, wn = (warp >> 1) * 32;
    int lq = lane >> 2, kq = (lane & 3) * 2;

    float acc[2][4][4];
    #pragma unroll
    for (int mi = 0; mi < 2; mi++)
        #pragma unroll
        for (int ni = 0; ni < 4; ni++)
            #pragma unroll
            for (int q = 0; q < 4; q++) acc[mi][ni][q] = 0.f;

    int lr = tid >> 1, lseg = (tid & 1) * 8;
    const __nv_bfloat16* gAh = Ahi + (size_t)(row0 + lr)*K + lseg;
    const __nv_bfloat16* gAl = Alo + (size_t)(row0 + lr)*K + lseg;
    bool bok = (col0 + lr) < Nact;
    const __nv_bfloat16* gBh = Bhi + (size_t)(col0 + lr)*K + lseg;
    const __nv_bfloat16* gBl = Blo + (size_t)(col0 + lr)*K + lseg;
    int sidx = lr * 16 + lseg;
    uint4 z4 = make_uint4(0,0,0,0);

    *(uint4*)&As[0][0][sidx] = *(const uint4*)(gAh);
    *(uint4*)&As[0][1][sidx] = *(const uint4*)(gAl);
    *(uint4*)&Bs[0][0][sidx] = bok ? *(const uint4*)(gBh) : z4;
    *(uint4*)&Bs[0][1][sidx] = bok ? *(const uint4*)(gBl) : z4;
    __syncthreads();

    int nkc = K >> 4;
    int buf = 0;
    for (int kc = 1; ; kc++) {
        bool has = (kc < nkc);
        uint4 nAh, nAl, nBh = z4, nBl = z4;
        if (has) {
            int k0 = kc * 16;
            nAh = *(const uint4*)(gAh + k0);
            nAl = *(const uint4*)(gAl + k0);
            if (bok) { nBh = *(const uint4*)(gBh + k0); nBl = *(const uint4*)(gBl + k0); }
        }
        {
            const __nv_bfloat16* ah = As[buf][0];
            const __nv_bfloat16* al = As[buf][1];
            const __nv_bfloat16* bh = Bs[buf][0];
            const __nv_bfloat16* bl = Bs[buf][1];
            unsigned bfh[4][2], bfl[4][2];
            #pragma unroll
            for (int ni = 0; ni < 4; ni++) {
                int cb = (wn + ni*8 + lq) * 16;
                bfh[ni][0] = *(const unsigned*)(bh + cb + kq);
                bfh[ni][1] = *(const unsigned*)(bh + cb + kq + 8);
                bfl[ni][0] = *(const unsigned*)(bl + cb + kq);
                bfl[ni][1] = *(const unsigned*)(bl + cb + kq + 8);
            }
            #pragma unroll
            for (int mi = 0; mi < 2; mi++) {
                int rb = (wm + mi*16 + lq) * 16;
                unsigned ah0 = *(const unsigned*)(ah + rb + kq);
                unsigned ah1 = *(const unsigned*)(ah + rb + 128 + kq);
                unsigned ah2 = *(const unsigned*)(ah + rb + kq + 8);
                unsigned ah3 = *(const unsigned*)(ah + rb + 128 + kq + 8);
                unsigned al0 = *(const unsigned*)(al + rb + kq);
                unsigned al1 = *(const unsigned*)(al + rb + 128 + kq);
                unsigned al2 = *(const unsigned*)(al + rb + kq + 8);
                unsigned al3 = *(const unsigned*)(al + rb + 128 + kq + 8);
                #pragma unroll
                for (int ni = 0; ni < 4; ni++) {
                    MMA_BF16(acc[mi][ni], ah0, ah1, ah2, ah3, bfh[ni][0], bfh[ni][1]);
                    MMA_BF16(acc[mi][ni], ah0, ah1, ah2, ah3, bfl[ni][0], bfl[ni][1]);
                    MMA_BF16(acc[mi][ni], al0, al1, al2, al3, bfh[ni][0], bfh[ni][1]);
                }
            }
        }
        if (!has) break;
        int nb = buf ^ 1;
        *(uint4*)&As[nb][0][sidx] = nAh;
        *(uint4*)&As[nb][1][sidx] = nAl;
        *(uint4*)&Bs[nb][0][sidx] = nBh;
        *(uint4*)&Bs[nb][1][sidx] = nBl;
        __syncthreads();
        buf = nb;
    }

    #pragma unroll
    for (int mi = 0; mi < 2; mi++) {
        #pragma unroll
        for (int ni = 0; ni < 4; ni++) {
            int row = row0 + wm + mi*16 + lq;
            int col = col0 + wn + ni*8 + kq;
            float* d = acc[mi][ni];
            if (EPI == 0) {
                C[(size_t)row*Nact + col]       = d[0];
                C[(size_t)row*Nact + col + 1]   = d[1];
                C[(size_t)(row+8)*Nact + col]   = d[2];
                C[(size_t)(row+8)*Nact + col+1] = d[3];
            } else {
                #pragma unroll
                for (int q = 0; q < 4; q++) {
                    int r = row + (q >> 1) * 8;
                    int c = col + (q & 1);
                    float v = d[q];
                    if (c < 128) {
                        float t = v + aux0[c];
                        C[(size_t)r*128 + c] = (t > 20.f) ? t : log1pf(__expf(t));
                    } else if (c < 144) {
                        o1[(size_t)r*16 + (c - 128)] = v;
                    } else if (c < 160) {
                        o2[(size_t)r*16 + (c - 144)] = v;
                    }
                }
            }
        }
    }
}

// ================= bf16 split GEMM for graph (fixed 1024^3) =================
template<int WHICH>
__global__ void __launch_bounds__(128) tcmma_k(
    const __nv_bfloat16* __restrict__ Ahi, const __nv_bfloat16* __restrict__ Alo,
    const __nv_bfloat16* __restrict__ Bhi, const __nv_bfloat16* __restrict__ Blo,
    float* __restrict__ C, const float* __restrict__ xall)
{
    __shared__ __align__(16) __nv_bfloat16 As[2][2][64*16];
    __shared__ __align__(16) __nv_bfloat16 Bs[2][2][64*16];
    int tid = threadIdx.x, lane = tid & 31, warp = tid >> 5;
    int row0 = blockIdx.y * 64, col0 = blockIdx.x * 64;
    int wm = (warp & 1) * 32, wn = (warp >> 1) * 32;
    int lq = lane >> 2, kq = (lane & 3) * 2;

    float acc[2][4][4];
    #pragma unroll
    for (int mi = 0; mi < 2; mi++)
        #pragma unroll
        for (int ni = 0; ni < 4; ni++)
            #pragma unroll
            for (int q = 0; q < 4; q++) acc[mi][ni][q] = 0.f;

    int lr = tid >> 1, lseg = (tid & 1) * 8;
    const __nv_bfloat16* gAh = Ahi + (size_t)(row0 + lr)*1024 + lseg;
    const __nv_bfloat16* gAl = Alo + (size_t)(row0 + lr)*1024 + lseg;
    const __nv_bfloat16* gBh = Bhi + (size_t)(col0 + lr)*1024 + lseg;
    const __nv_bfloat16* gBl = Blo + (size_t)(col0 + lr)*1024 + lseg;
    int sidx = lr * 16 + lseg;

    *(uint4*)&As[0][0][sidx] = *(const uint4*)(gAh);
    *(uint4*)&As[0][1][sidx] = *(const uint4*)(gAl);
    *(uint4*)&Bs[0][0][sidx] = *(const uint4*)(gBh);
    *(uint4*)&Bs[0][1][sidx] = *(const uint4*)(gBl);
    __syncthreads();

    int buf = 0;
    for (int kc = 1; ; kc++) {
        bool has = (kc < 64);
        uint4 nAh, nAl, nBh, nBl;
        if (has) {
            int k0 = kc * 16;
            nAh = *(const uint4*)(gAh + k0);
            nAl = *(const uint4*)(gAl + k0);
            nBh = *(const uint4*)(gBh + k0);
            nBl = *(const uint4*)(gBl + k0);
        }
        {
            const __nv_bfloat16* ah = As[buf][0];
            const __nv_bfloat16* al = As[buf][1];
            const __nv_bfloat16* bh = Bs[buf][0];
            const __nv_bfloat16* bl = Bs[buf][1];
            unsigned bfh[4][2], bfl[4][2];
            #pragma unroll
            for (int ni = 0; ni < 4; ni++) {
                int cb = (wn + ni*8 + lq) * 16;
                bfh[ni][0] = *(const unsigned*)(bh + cb + kq);
                bfh[ni][1] = *(const unsigned*)(bh + cb + kq + 8);
                bfl[ni][0] = *(const unsigned*)(bl + cb + kq);
                bfl[ni][1] = *(const unsigned*)(bl + cb + kq + 8);
            }
            #pragma unroll
            for (int mi = 0; mi < 2; mi++) {
                int rb = (wm + mi*16 + lq) * 16;
                unsigned ah0 = *(const unsigned*)(ah + rb + kq);
                unsigned ah1 = *(const unsigned*)(ah + rb + 128 + kq);
                unsigned ah2 = *(const unsigned*)(ah + rb + kq + 8);
                unsigned ah3 = *(const unsigned*)(ah + rb + 128 + kq + 8);
                unsigned al0 = *(const unsigned*)(al + rb + kq);
                unsigned al1 = *(const unsigned*)(al + rb + 128 + kq);
                unsigned al2 = *(const unsigned*)(al + rb + kq + 8);
                unsigned al3 = *(const unsigned*)(al + rb + 128 + kq + 8);
                #pragma unroll
                for (int ni = 0; ni < 4; ni++) {
                    MMA_BF16(acc[mi][ni], ah0, ah1, ah2, ah3, bfh[ni][0], bfh[ni][1]);
                    MMA_BF16(acc[mi][ni], ah0, ah1, ah2, ah3, bfl[ni][0], bfl[ni][1]);
                    MMA_BF16(acc[mi][ni], al0, al1, al2, al3, bfh[ni][0], bfh[ni][1]);
                }
            }
        }
        if (!has) break;
        int nb = buf ^ 1;
        *(uint4*)&As[nb][0][sidx] = nAh;
        *(uint4*)&As[nb][1][sidx] = nAl;
        *(uint4*)&Bs[nb][0][sidx] = nBh;
        *(uint4*)&Bs[nb][1][sidx] = nBl;
        __syncthreads();
        buf = nb;
    }

    #pragma unroll
    for (int mi = 0; mi < 2; mi++) {
        #pragma unroll
        for (int ni = 0; ni < 4; ni++) {
            int row = row0 + wm + mi*16 + lq;
            int col = col0 + wn + ni*8 + kq;
            float* d = acc[mi][ni];
            if (WHICH == 1) {
                C[(size_t)row*1024 + col]       = d[0];
                C[(size_t)row*1024 + col + 1]   = d[1];
                C[(size_t)(row+8)*1024 + col]   = d[2];
                C[(size_t)(row+8)*1024 + col+1] = d[3];
            } else {
                C[(size_t)row*1024 + col]       = 2.f*d[0] - xall[(size_t)row*1024 + col];
                C[(size_t)row*1024 + col + 1]   = 2.f*d[1] - xall[(size_t)row*1024 + col + 1];
                C[(size_t)(row+8)*1024 + col]   = 2.f*d[2] - xall[(size_t)(row+8)*1024 + col];
                C[(size_t)(row+8)*1024 + col+1] = 2.f*d[3] - xall[(size_t)(row+8)*1024 + col+1];
            }
        }
    }
}

// ---------------- bf16 hi/lo split (elementwise) ----------------
__global__ void bfsplit_k(const float* __restrict__ in, __nv_bfloat16* __restrict__ hi,
                          __nv_bfloat16* __restrict__ lo, int n)
{
    int g = blockIdx.x * 256 + threadIdx.x;
    if (g >= n) return;
    float v = in[g];
    __nv_bfloat16 h = __float2bfloat16(v);
    hi[g] = h;
    lo[g] = __float2bfloat16(v - __bfloat162float(h));
}

// ---------------- transpose + split: in fp32 [1024][1024] -> hi/lo [c][r] ----------
__global__ void tsplit_k(const float* __restrict__ in, __nv_bfloat16* __restrict__ hi,
                         __nv_bfloat16* __restrict__ lo)
{
    __shared__ float t[32][33];
    int r0 = blockIdx.y * 32, c0 = blockIdx.x * 32;
    int tx = threadIdx.x, ty = threadIdx.y;   // 32 x 8
    #pragma unroll
    for (int i = 0; i < 4; i++) {
        int r = ty + i*8;
        t[r][tx] = in[(size_t)(r0 + r)*1024 + c0 + tx];
    }
    __syncthreads();
    #pragma unroll
    for (int i = 0; i < 4; i++) {
        int c = ty + i*8;
        float v = t[tx][c];
        __nv_bfloat16 h = __float2bfloat16(v);
        size_t o = (size_t)(c0 + c)*1024 + r0 + tx;
        hi[o] = h;
        lo[o] = __float2bfloat16(v - __bfloat162float(h));
    }
}

// ---------------- x (B,N,D) -> XallT hi/lo [bd,node] bf16, tiled transpose ------
__global__ void xallT_k(const float* __restrict__ x, __nv_bfloat16* __restrict__ hi,
                        __nv_bfloat16* __restrict__ lo)
{
    __shared__ float t[64*33];
    int b = blockIdx.y, n0 = blockIdx.x * 32;
    int tid = threadIdx.x;
    for (int idx = tid; idx < 2048; idx += 256) {
        int ni = idx >> 6, c = idx & 63;
        t[c*33 + ni] = x[(size_t)b*65536 + (size_t)(n0 + ni)*64 + c];
    }
    __syncthreads();
    for (int idx = tid; idx < 2048; idx += 256) {
        int ni = idx & 31, c = idx >> 5;
        float v = t[c*33 + ni];
        __nv_bfloat16 h = __float2bfloat16(v);
        size_t o = (size_t)(b*64 + c)*1024 + n0 + ni;
        hi[o] = h;
        lo[o] = __float2bfloat16(v - __bfloat162float(h));
    }
}

// ---------------- causal conv (both directions) + silu (+ bf16 hi/lo out) --------
__global__ void conv_silu_k(const float* __restrict__ xz,
                            const float* __restrict__ cw0, const float* __restrict__ cb0,
                            const float* __restrict__ cw1, const float* __restrict__ cb1,
                            float* __restrict__ xc0, float* __restrict__ xc1,
                            __nv_bfloat16* __restrict__ xch, __nv_bfloat16* __restrict__ xcl)
{
    int dir = blockIdx.y;
    int g = blockIdx.x * 256 + threadIdx.x;
    int d = g & 127; int m = g >> 7; int l = m & 1023;
    const float* cw = dir ? cw1 : cw0;
    const float* cb = dir ? cb1 : cb0;
    const float* src = xz + dir * 256 + d;
    float acc = cb[d];
    #pragma unroll
    for (int k = 0; k < 4; k++) {
        int ll = dir ? (l + 3 - k) : (l - 3 + k);
        if (ll >= 0 && ll < 1024)
            acc = fmaf(src[(size_t)(m - l + ll) * 512], cw[d*4 + k], acc);
    }
    float v = silu_(acc);
    (dir ? xc1 : xc0)[g] = v;
    size_t o = (size_t)dir * 2097152 + g;
    __nv_bfloat16 hh = __float2bfloat16(v);
    xch[o] = hh;
    xcl[o] = __float2bfloat16(v - __bfloat162float(hh));
}

// ---------------- chunked selective scan ----------------
__global__ void __launch_bounds__(512) scan_p1(
    const float* __restrict__ dt0, const float* __restrict__ dt1,
    const float* __restrict__ xc0, const float* __restrict__ xc1,
    const float* __restrict__ B0,  const float* __restrict__ B1,
    const float* __restrict__ A0,  const float* __restrict__ A1,
    float* __restrict__ Hc, float* __restrict__ Ec)
{
    int dir = blockIdx.z >> 4;
    int b   = blockIdx.z & 15;
    int c   = blockIdx.y;
    int t = threadIdx.x, s = t & 15, dl = t >> 4;
    int d = blockIdx.x * 32 + dl;
    const float* dt = dir ? dt1 : dt0;
    const float* xc = dir ? xc1 : xc0;
    const float* Bm = dir ? B1 : B0;
    float Ads = (dir ? A1 : A0)[d*16 + s];
    int l0  = dir ? (1023 - c*CHLEN) : c*CHLEN;
    int stp = dir ? -1 : 1;
    const float* pdt = dt + (size_t)b*131072 + (size_t)l0*128 + d;
    const float* pxc = xc + (size_t)b*131072 + (size_t)l0*128 + d;
    const float* pB  = Bm + (size_t)b*16384  + (size_t)l0*16  + s;
    int d128 = stp*128, d16 = stp*16;
    float h = 0.f, sdt = 0.f;
    float dtv = *pdt, xcv = *pxc, Bv = *pB;
    for (int tt = 0; tt < CHLEN; tt++) {
        float dtv2, xcv2, Bv2;
        if (tt < CHLEN-1) { dtv2 = pdt[d128]; xcv2 = pxc[d128]; Bv2 = pB[d16]; }
        else { dtv2 = xcv2 = Bv2 = 0.f; }
        float e = __expf(dtv * Ads);
        h = fmaf(h, e, dtv * Bv * xcv);
        sdt += dtv;
        pdt += d128; pxc += d128; pB += d16;
        dtv = dtv2; xcv = xcv2; Bv = Bv2;
    }
    size_t idx = ((((size_t)dir*16 + b)*NCHUNK + c)*128 + d)*16 + s;
    Hc[idx] = h;
    Ec[idx] = __expf(Ads * sdt);
}

__global__ void scan_comb(const float* __restrict__ Hc, const float* __restrict__ Ec,
                          float* __restrict__ h0arr)
{
    int g = blockIdx.x * 256 + threadIdx.x;
    int s = g & 15; int d = (g >> 4) & 127; int bb = g >> 11;
    float carry = 0.f;
    #pragma unroll
    for (int c = 0; c < NCHUNK; c++) {
        size_t idx = (((size_t)bb*NCHUNK + c)*128 + d)*16 + s;
        h0arr[idx] = carry;
        carry = fmaf(carry, Ec[idx], Hc[idx]);
    }
}

__global__ void __launch_bounds__(512) scan_p2(
    const float* __restrict__ dt0, const float* __restrict__ dt1,
    const float* __restrict__ xc0, const float* __restrict__ xc1,
    const float* __restrict__ B0,  const float* __restrict__ B1,
    const float* __restrict__ C0,  const float* __restrict__ C1,
    const float* __restrict__ xz,
    const float* __restrict__ A0,  const float* __restrict__ A1,
    const float* __restrict__ D0,  const float* __restrict__ D1,
    const float* __restrict__ h0arr, float* __restrict__ ycat)
{
    int dir = blockIdx.z >> 4;
    int b   = blockIdx.z & 15;
    int c   = blockIdx.y;
    int t = threadIdx.x, s = t & 15, dl = t >> 4;
    int d = blockIdx.x * 32 + dl;
    const float* dt = dir ? dt1 : dt0;
    const float* xc = dir ? xc1 : xc0;
    const float* Bm = dir ? B1 : B0;
    const float* Cm = dir ? C1 : C0;
    float Ads = (dir ? A1 : A0)[d*16 + s];
    float Dpd = (dir ? D1 : D0)[d];
    int l0  = dir ? (1023 - c*CHLEN) : c*CHLEN;
    int stp = dir ? -1 : 1;
    const float* pdt = dt + (size_t)b*131072 + (size_t)l0*128 + d;
    const float* pxc = xc + (size_t)b*131072 + (size_t)l0*128 + d;
    const float* pB  = Bm + (size_t)b*16384  + (size_t)l0*16  + s;
    const float* pC  = Cm + (size_t)b*16384  + (size_t)l0*16  + s;
    const float* pz  = xz + (size_t)b*524288 + (size_t)l0*512 + dir*256 + 128 + d;
    float* py        = ycat + (size_t)b*262144 + (size_t)l0*256 + dir*128 + d;
    int d128 = stp*128, d16 = stp*16, d512 = stp*512, d256 = stp*256;

    size_t idx = ((((size_t)dir*16 + b)*NCHUNK + c)*128 + d)*16 + s;
    float h = h0arr[idx];

    float dtv = *pdt, xcv = *pxc, Bv = *pB, Cv = *pC, zv = *pz;
    for (int tt = 0; tt < CHLEN; tt++) {
        float dtv2, xcv2, Bv2, Cv2, zv2;
        if (tt < CHLEN-1) {
            dtv2 = pdt[d128]; xcv2 = pxc[d128];
            Bv2  = pB[d16];   Cv2  = pC[d16];
            zv2  = pz[d512];
        } else { dtv2 = xcv2 = Bv2 = Cv2 = zv2 = 0.f; }
        float e = __expf(dtv * Ads);
        h = fmaf(h, e, dtv * Bv * xcv);
        float part = h * Cv;
        part += __shfl_xor_sync(0xffffffffu, part, 8);
        part += __shfl_xor_sync(0xffffffffu, part, 4);
        part += __shfl_xor_sync(0xffffffffu, part, 2);
        part += __shfl_xor_sync(0xffffffffu, part, 1);
        if (s == 0)
            py[0] = (part + Dpd * xcv) * silu_(zv);
        pdt += d128; pxc += d128; pB += d16; pC += d16; pz += d512; py += d256;
        dtv = dtv2; xcv = xcv2; Bv = Bv2; Cv = Cv2; zv = zv2;
    }
}

// ---------------- support matrix: softmax(relu(E E^T)) ----------------
__global__ void __launch_bounds__(256) sup_k(const float* __restrict__ emb, float* __restrict__ sup)
{
    __shared__ float se[NNODE * EDIM];
    __shared__ float red[256];
    int n = blockIdx.x, tid = threadIdx.x;
    for (int i = tid; i < NNODE*EDIM; i += 256) se[i] = emb[i];
    __syncthreads();
    float en[EDIM];
    #pragma unroll
    for (int e = 0; e < EDIM; e++) en[e] = se[n*EDIM + e];
    float vals[4]; float mx = -1e30f;
    #pragma unroll
    for (int jj = 0; jj < 4; jj++) {
        int j = jj*256 + tid;
        float v = 0.f;
        #pragma unroll
        for (int e = 0; e < EDIM; e++) v = fmaf(en[e], se[j*EDIM + e], v);
        v = v > 0.f ? v : 0.f;
        vals[jj] = v; mx = fmaxf(mx, v);
    }
    red[tid] = mx; __syncthreads();
    for (int o = 128; o > 0; o >>= 1) { if (tid < o) red[tid] = fmaxf(red[tid], red[tid+o]); __syncthreads(); }
    mx = red[0]; __syncthreads();
    float s = 0.f;
    #pragma unroll
    for (int jj = 0; jj < 4; jj++) { vals[jj] = __expf(vals[jj] - mx); s += vals[jj]; }
    red[tid] = s; __syncthreads();
    for (int o = 128; o > 0; o >>= 1) { if (tid < o) red[tid] += red[tid+o]; __syncthreads(); }
    float inv = 1.f / red[0];
    #pragma unroll
    for (int jj = 0; jj < 4; jj++) sup[(size_t)n*1024 + jj*256 + tid] = vals[jj] * inv;
}

// ---------------- x (B,N,D) -> Xall (N, B*D) fp32 ----------------
__global__ void xall_k(const float* __restrict__ x, float* __restrict__ xall)
{
    int g = blockIdx.x * 256 + threadIdx.x;
    int c = g & 63, n = (g >> 6) & 1023, b = g >> 16;
    xall[(size_t)n*1024 + b*64 + c] = x[g];
}

// ---------------- W[n,k,c,o] = sum_e emb[n,e] W_pool[e,k,c,o] ----------------
__global__ void wmix_k(const float* __restrict__ emb, const float* __restrict__ wp,
                       float* __restrict__ W)
{
    int n = blockIdx.y;
    int j = blockIdx.x * 256 + threadIdx.x;
    float acc = 0.f;
    #pragma unroll
    for (int e = 0; e < EDIM; e++) acc = fmaf(emb[n*EDIM + e], wp[(size_t)e*12288 + j], acc);
    W[(size_t)n*12288 + j] = acc;
}

// ---------------- per-node graph conv ----------------
__global__ void __launch_bounds__(256) gconv_k(
    const float* __restrict__ x,  const float* __restrict__ xg1,
    const float* __restrict__ xg2, const float* __restrict__ W,
    const float* __restrict__ emb, const float* __restrict__ bp,
    float* __restrict__ go)
{
    __shared__ float xs[3072];
    __shared__ float bs[64];
    int n = blockIdx.x, tid = threadIdx.x;
    const float* Wn = W + (size_t)n * 12288;
    for (int i = tid; i < 3072; i += 256) {
        int k = i >> 10; int rem = i & 1023; int b = rem >> 6; int c = rem & 63;
        float v;
        if (k == 0) v = x[(size_t)b*65536 + (size_t)n*64 + c];
        else        v = (k == 1 ? xg1 : xg2)[(size_t)n*1024 + b*64 + c];
        xs[i] = v;
    }
    if (tid < 64) {
        float a = 0.f;
        #pragma unroll
        for (int e = 0; e < EDIM; e++) a = fmaf(emb[n*EDIM + e], bp[e*64 + tid], a);
        bs[tid] = a;
    }
    __syncthreads();
    int o = tid & 63, bq = tid >> 6;
    float acc[4];
    #pragma unroll
    for (int q = 0; q < 4; q++) acc[q] = bs[o];
    #pragma unroll 4
    for (int kc = 0; kc < 192; kc++) {
        float w = __ldg(Wn + kc*64 + o);
        int k = kc >> 6, c = kc & 63;
        #pragma unroll
        for (int q = 0; q < 4; q++)
            acc[q] = fmaf(xs[(k*16 + bq + q*4)*64 + c], w, acc[q]);
    }
    #pragma unroll
    for (int q = 0; q < 4; q++) {
        int b = bq + q*4;
        go[(size_t)b*65536 + (size_t)n*64 + o] = acc[q];
    }
}

// ---------------- launch ----------------
extern "C" void kernel_launch(void* const* d_in, const int* in_sizes, int n_in,
                              void* d_out, int out_size)
{
    const float* x_in     = (const float*)d_in[0];
    const float* fw_in    = (const float*)d_in[1];
    const float* fw_cw    = (const float*)d_in[2];
    const float* fw_cb    = (const float*)d_in[3];
    const float* fw_xp    = (const float*)d_in[4];
    const float* fw_dtw   = (const float*)d_in[5];
    const float* fw_dtb   = (const float*)d_in[6];
    const float* fw_Alog  = (const float*)d_in[7];
    const float* fw_D     = (const float*)d_in[8];
    const float* fw_out   = (const float*)d_in[9];
    const float* bw_in    = (const float*)d_in[10];
    const float* bw_cw    = (const float*)d_in[11];
    const float* bw_cb    = (const float*)d_in[12];
    const float* bw_xp    = (const float*)d_in[13];
    const float* bw_dtw   = (const float*)d_in[14];
    const float* bw_dtb   = (const float*)d_in[15];
    const float* bw_Alog  = (const float*)d_in[16];
    const float* bw_D     = (const float*)d_in[17];
    const float* bw_out   = (const float*)d_in[18];
    const float* ln1_g    = (const float*)d_in[19];
    const float* ln1_b    = (const float*)d_in[20];
    const float* ffn_w1   = (const float*)d_in[21];
    const float* ffn_b1   = (const float*)d_in[22];
    const float* ffn_w2   = (const float*)d_in[23];
    const float* ffn_b2   = (const float*)d_in[24];
    const float* ln2_g    = (const float*)d_in[25];
    const float* ln2_b    = (const float*)d_in[26];
    const float* node_emb = (const float*)d_in[27];
    const float* W_pool   = (const float*)d_in[28];
    const float* b_pool   = (const float*)d_in[29];
    const float* proj_w   = (const float*)d_in[30];
    const float* proj_b   = (const float*)d_in[31];
    float* outp = (float*)d_out;

    float* S = nullptr;
    cudaGetSymbolAddress((void**)&S, g_scratch);

    float* A0     = S + 73728;
    float* A1     = S + 75776;
    float* xz     = S + 77824;
    float* xc0    = S + 8466432;
    float* xc1    = S + 10563584;
    float* dt0    = S + 12660736;
    float* dt1    = S + 14757888;
    float* Bm0    = S + 16855040;
    float* Bm1    = S + 17117184;
    float* Cm0    = S + 17379328;
    float* Cm1    = S + 17641472;
    float* ycat   = S + 17903616;
    float* xbuf   = S + 22097920;
    float* xln    = S + 23146496;
    float* xall   = S + 24195072;
    float* hbuf   = S + 25243648;
    float* sup    = S + 29437952;
    float* xg1    = S + 31535104;
    float* xg2    = S + 32583680;
    float* Wbig   = S + 33632256;
    float* go     = S + 46215168;
    float* Wocat  = S + 47263744;
    float* Hc     = S + 47280128;
    float* Ec     = S + 47804416;
    float* h0arr  = S + 48328704;
    __nv_bfloat16* sup_hi  = (__nv_bfloat16*)(S + 48852992);
    __nv_bfloat16* sup_lo  = (__nv_bfloat16*)(S + 49377280);
    __nv_bfloat16* xaT_hi  = (__nv_bfloat16*)(S + 49901568);
    __nv_bfloat16* xaT_lo  = (__nv_bfloat16*)(S + 50425856);
    __nv_bfloat16* xg1t_hi = (__nv_bfloat16*)(S + 50950144);
    __nv_bfloat16* xg1t_lo = (__nv_bfloat16*)(S + 51474432);
    __nv_bfloat16* wcatTh  = (__nv_bfloat16*)(S + 51998720);
    __nv_bfloat16* wcatTl  = (__nv_bfloat16*)(S + 52015104);
    __nv_bfloat16* wc0Th   = (__nv_bfloat16*)(S + 52031488);
    __nv_bfloat16* wc0Tl   = (__nv_bfloat16*)(S + 52041728);
    __nv_bfloat16* wc1Th   = (__nv_bfloat16*)(S + 52051968);
    __nv_bfloat16* wc1Tl   = (__nv_bfloat16*)(S + 52062208);
    __nv_bfloat16* xbufh   = (__nv_bfloat16*)(S + 52072448);
    __nv_bfloat16* xbufl   = (__nv_bfloat16*)(S + 52596736);
    __nv_bfloat16* xch     = (__nv_bfloat16*)(S + 53121024);
    __nv_bfloat16* xcl     = (__nv_bfloat16*)(S + 55218176);

    // prep
    {
        int total = 32768 + 40960 + 4096 + 16384 + MROWS*DMODEL;  // 1142784
        prep_k<<<(total + 255)/256, 256>>>(fw_in, bw_in, fw_xp, fw_dtw, bw_xp, bw_dtw,
                                           fw_Alog, bw_Alog, fw_out, bw_out, x_in,
                                           wcatTh, wcatTl, wc0Th, wc0Tl, wc1Th, wc1Tl,
                                           A0, A1, Wocat, xbuf, xbufh, xbufl);
    }

    for (int layer = 0; layer < 2; layer++) {
        // xz = x @ [fw_in | bw_in]  -- tensor cores, split bf16 (16384 x 512 x 64)
        tcg_k<0,0><<<dim3(8, 256), 128>>>(xbufh, xbufl, wcatTh, wcatTl, nullptr, nullptr,
                                          xz, MROWS, 512, 64,
                                          nullptr, nullptr, nullptr, nullptr);
        // conv + silu, both dirs (+ bf16 hi/lo for xproj)
        conv_silu_k<<<dim3((MROWS*128)/256, 2), 256>>>(xz, fw_cw, fw_cb, bw_cw, bw_cb,
                                                       xc0, xc1, xch, xcl);
        // xproj both dirs in ONE tensor-core launch (M=32768, N=160(pad 192), K=128)
        tcg_k<1,1><<<dim3(3, 512), 128>>>(xch, xcl, wc0Th, wc0Tl, wc1Th, wc1Tl,
                                          dt0, 2*MROWS, 160, 128,
                                          fw_dtb, bw_dtb, Bm0, Cm0);
        // chunked selective scan
        scan_p1<<<dim3(4, NCHUNK, 32), 512>>>(dt0, dt1, xc0, xc1, Bm0, Bm1, A0, A1, Hc, Ec);
        scan_comb<<<256, 256>>>(Hc, Ec, h0arr);
        scan_p2<<<dim3(4, NCHUNK, 32), 512>>>(dt0, dt1, xc0, xc1, Bm0, Bm1, Cm0, Cm1,
                                              xz, A0, A1, fw_D, bw_D, h0arr, ycat);
        // x + [yf|yb]@Wocat, fused LN1 -> xln
        sgemm_k<7,0><<<dim3(1, 256), 256>>>(ycat, Wocat, xln, MROWS, 64, 256,
                                            xbuf, nullptr, (float*)ln1_g, (float*)ln1_b,
                                            nullptr, nullptr, nullptr, nullptr);
        // FFN1: relu(xln@W1 + b1)
        sgemm_k<2,0><<<dim3(4, 256), 256>>>(xln, ffn_w1, hbuf, MROWS, 256, 64,
                                            ffn_b1, nullptr, nullptr, nullptr,
                                            nullptr, nullptr, nullptr, nullptr);
        // FFN2 + residual + b2, fused LN2 -> xbuf (+ bf16 hi/lo for next xz)
        sgemm_k<8,0><<<dim3(1, 256), 256>>>(hbuf, ffn_w2, xbuf, MROWS, 64, 256,
                                            xln, ffn_b2, (float*)ln2_g, (float*)ln2_b,
                                            nullptr, nullptr, xbufh, xbufl);
    }

    // graph part
    sup_k<<<NNODE, 256>>>(node_emb, sup);
    bfsplit_k<<<4096, 256>>>(sup, sup_hi, sup_lo, NNODE*NNODE);
    xall_k<<<4096, 256>>>(xbuf, xall);
    xallT_k<<<dim3(32, 16), 256>>>(xbuf, xaT_hi, xaT_lo);

    // XG1 = sup @ Xall  (tensor cores, split bf16)
    tcmma_k<1><<<dim3(16, 16), 128>>>(sup_hi, sup_lo, xaT_hi, xaT_lo, xg1, nullptr);
    tsplit_k<<<dim3(32, 32), dim3(32, 8)>>>(xg1, xg1t_hi, xg1t_lo);
    // XG2 = 2*sup@XG1 - Xall
    tcmma_k<2><<<dim3(16, 16), 128>>>(sup_hi, sup_lo, xg1t_hi, xg1t_lo, xg2, xall);

    wmix_k<<<dim3(48, 1024), 256>>>(node_emb, W_pool, Wbig);
    gconv_k<<<NNODE, 256>>>(xbuf, xg1, xg2, Wbig, node_emb, b_pool, go);
    sgemm_k<6,0><<<dim3(2, 256), 256>>>(go, proj_w, outp, MROWS, 96, 64,
                                        proj_b, nullptr, nullptr, nullptr,
                                        nullptr, nullptr, nullptr, nullptr);
}

// round 14
// speedup vs baseline: 1.0141x; 1.0141x over previous
#include <cuda_runtime.h>
#include <cuda_bf16.h>
#include <math.h>

// ---------------- problem constants ----------------
#define BATCH   16
#define LSEQ    1024
#define DMODEL  64
#define DINNER  128
#define SSTATE  16
#define MROWS   (BATCH*LSEQ)   // 16384
#define HFFN    256
#define NNODE   1024
#define EDIM    10
#define PLOUT   96
#define NCHUNK  8
#define CHLEN   128

// ---------------- scratch (single static device buffer) ----------------
__device__ float g_scratch[57315328];

__device__ __forceinline__ float silu_(float x) { return x / (1.f + __expf(-x)); }

// ---------------- prep: Wcat fp32, WcombT bf16 hi/lo, A=-exp, Wocat, x copy ------
__global__ void prep_k(const float* __restrict__ fw_in, const float* __restrict__ bw_in,
                       const float* __restrict__ fwx, const float* __restrict__ fwdt,
                       const float* __restrict__ bwx, const float* __restrict__ bwdt,
                       const float* __restrict__ fwA, const float* __restrict__ bwA,
                       const float* __restrict__ fw_out, const float* __restrict__ bw_out,
                       const float* __restrict__ x_in,
                       float* __restrict__ Wcat,
                       __nv_bfloat16* __restrict__ wc0Th, __nv_bfloat16* __restrict__ wc0Tl,
                       __nv_bfloat16* __restrict__ wc1Th, __nv_bfloat16* __restrict__ wc1Tl,
                       float* __restrict__ A0, float* __restrict__ A1,
                       float* __restrict__ Wocat,
                       float* __restrict__ xbuf)
{
    int g = blockIdx.x * 256 + threadIdx.x;
    if (g < 32768) {  // Wcat (64,512) fp32
        int k = g >> 9, j = g & 511;
        Wcat[g] = (j < 256) ? fw_in[k*256 + j] : bw_in[k*256 + (j-256)];
        return;
    }
    int h = g - 32768;
    if (h < 40960) {  // WcombT per dir: [160][128] bf16 hi/lo
        int dir = h / 20480; int r2 = h % 20480;
        int j = r2 >> 7, i = r2 & 127;   // j = output col, i = K index
        const float* Wx  = dir ? bwx  : fwx;
        const float* Wdt = dir ? bwdt : fwdt;
        float v;
        if (j < 128) {
            v = 0.f;
            #pragma unroll
            for (int r = 0; r < 4; r++) v = fmaf(Wx[i*36 + r], Wdt[r*128 + j], v);
        } else {
            v = Wx[i*36 + 4 + (j - 128)];
        }
        __nv_bfloat16 hh = __float2bfloat16(v);
        __nv_bfloat16 ll = __float2bfloat16(v - __bfloat162float(hh));
        if (dir) { wc1Th[j*128 + i] = hh; wc1Tl[j*128 + i] = ll; }
        else     { wc0Th[j*128 + i] = hh; wc0Tl[j*128 + i] = ll; }
        return;
    }
    h -= 40960;
    if (h < 4096) {  // A
        int dir = h >> 11; int i = h & 2047;
        (dir ? A1 : A0)[i] = -__expf((dir ? bwA : fwA)[i]);
        return;
    }
    h -= 4096;
    if (h < 16384) {  // Wocat (256,64) fp32
        int r = h >> 6, c = h & 63;
        Wocat[h] = (r < 128) ? fw_out[r*64 + c] : bw_out[(r-128)*64 + c];
        return;
    }
    h -= 16384;
    if (h < MROWS*DMODEL) xbuf[h] = x_in[h];
}

// ---------------- generic tiled SGEMM, 64x64 tiles, double-buffered (fp32) --------
// EPI: 0 store, 2 bias+relu, 6 +aux0(col), 7 +aux0(full)+LN, 8 +aux0(full)+aux1(col)+LN
template<int EPI, int SPLIT>
__global__ void __launch_bounds__(256) sgemm_k(
    const float* __restrict__ A, const float* __restrict__ B, float* __restrict__ C,
    int M, int N, int K,
    const float* __restrict__ aux0, const float* __restrict__ aux1,
    float* __restrict__ o1, float* __restrict__ o2,
    const float* __restrict__ B2, const float* __restrict__ aux0b)
{
    __shared__ float As[2][16][64];
    __shared__ float Bs[2][16][64];
    int row0 = blockIdx.y * 64, col0 = blockIdx.x * 64;
    if (SPLIT && row0 >= (M >> 1)) { B = B2; aux0 = aux0b; }
    int tid = threadIdx.x;
    int tx = tid & 15, ty = tid >> 4;
    int a_m = tid >> 2, a_k = (tid & 3) * 4;
    int b_k = tid >> 4, b_n = (tid & 15) * 4;
    const float* Aptr = A + (size_t)(row0 + a_m) * K + a_k;
    int bc = col0 + b_n;
    bool bok = bc < N;
    const float* Bptr = B + (size_t)b_k * N + bc;

    float acc[4][4];
    #pragma unroll
    for (int i = 0; i < 4; i++)
        #pragma unroll
        for (int j = 0; j < 4; j++) acc[i][j] = 0.f;

    {
        float4 av = *(const float4*)(Aptr);
        float4 bv = bok ? *(const float4*)(Bptr) : make_float4(0.f,0.f,0.f,0.f);
        As[0][a_k+0][a_m] = av.x; As[0][a_k+1][a_m] = av.y;
        As[0][a_k+2][a_m] = av.z; As[0][a_k+3][a_m] = av.w;
        *(float4*)&Bs[0][b_k][b_n] = bv;
    }
    __syncthreads();

    int buf = 0;
    for (int k0 = 16; ; k0 += 16) {
        bool has = (k0 < K);
        float4 av2, bv2;
        if (has) {
            av2 = *(const float4*)(Aptr + k0);
            bv2 = bok ? *(const float4*)(Bptr + (size_t)k0 * N) : make_float4(0.f,0.f,0.f,0.f);
        }
        #pragma unroll
        for (int kk = 0; kk < 16; kk++) {
            float am[4], bn[4];
            *(float4*)am = *(const float4*)&As[buf][kk][ty*4];
            *(float4*)bn = *(const float4*)&Bs[buf][kk][tx*4];
            #pragma unroll
            for (int i = 0; i < 4; i++)
                #pragma unroll
                for (int j = 0; j < 4; j++)
                    acc[i][j] = fmaf(am[i], bn[j], acc[i][j]);
        }
        if (!has) break;
        int nb = buf ^ 1;
        As[nb][a_k+0][a_m] = av2.x; As[nb][a_k+1][a_m] = av2.y;
        As[nb][a_k+2][a_m] = av2.z; As[nb][a_k+3][a_m] = av2.w;
        *(float4*)&Bs[nb][b_k][b_n] = bv2;
        __syncthreads();
        buf = nb;
    }

    if (EPI == 7 || EPI == 8) {
        float vv[4][4];
        #pragma unroll
        for (int i = 0; i < 4; i++) {
            int row = row0 + ty*4 + i;
            #pragma unroll
            for (int j = 0; j < 4; j++) {
                int col = tx*4 + j;
                float v = acc[i][j] + aux0[(size_t)row*64 + col];
                if (EPI == 8) v += aux1[col];
                vv[i][j] = v;
            }
        }
        #pragma unroll
        for (int i = 0; i < 4; i++) {
            float sm = vv[i][0] + vv[i][1] + vv[i][2] + vv[i][3];
            float sq = vv[i][0]*vv[i][0] + vv[i][1]*vv[i][1]
                     + vv[i][2]*vv[i][2] + vv[i][3]*vv[i][3];
            #pragma unroll
            for (int o = 8; o > 0; o >>= 1) {
                sm += __shfl_xor_sync(0xffffffffu, sm, o);
                sq += __shfl_xor_sync(0xffffffffu, sq, o);
            }
            float mean = sm * (1.f/64.f);
            float var  = sq * (1.f/64.f) - mean*mean;
            float r = rsqrtf(var + 1e-5f);
            int row = row0 + ty*4 + i;
            #pragma unroll
            for (int j = 0; j < 4; j++) {
                int col = tx*4 + j;
                C[(size_t)row*64 + col] = (vv[i][j] - mean) * r * o1[col] + o2[col];
            }
        }
        return;
    }

    #pragma unroll
    for (int i = 0; i < 4; i++) {
        int row = row0 + ty*4 + i;
        #pragma unroll
        for (int j = 0; j < 4; j++) {
            int col = col0 + tx*4 + j;
            if (col >= N) continue;
            float v = acc[i][j];
            size_t idx = (size_t)row * N + col;
            if (EPI == 0) {
                C[idx] = v;
            } else if (EPI == 2) {
                float t = v + aux0[col];
                C[idx] = t > 0.f ? t : 0.f;
            } else if (EPI == 6) {
                C[idx] = v + aux0[col];
            }
        }
    }
}

// ================= generalized bf16 split GEMM via mma.sync =================
// C[M,N] = A @ B^T ; A row-major [M][K] hi/lo bf16 ; B as [N][K] hi/lo bf16.
// 3-term split, fp32 accumulate. 64x64 tile, 128 threads, double-buffered.
// EPI 1: xproj split epilogue.  SPLIT: rows >= M/2 use B2/aux0b.
#define MMA_BF16(d, A0, A1, A2, A3, Bb0, Bb1) \
    asm volatile("mma.sync.aligned.m16n8k16.row.col.f32.bf16.bf16.f32 " \
                 "{%0,%1,%2,%3}, {%4,%5,%6,%7}, {%8,%9}, {%0,%1,%2,%3};" \
                 : "+f"((d)[0]), "+f"((d)[1]), "+f"((d)[2]), "+f"((d)[3]) \
                 : "r"(A0), "r"(A1), "r"(A2), "r"(A3), "r"(Bb0), "r"(Bb1))

template<int EPI, int SPLIT>
__global__ void __launch_bounds__(128) tcg_k(
    const __nv_bfloat16* __restrict__ Ahi, const __nv_bfloat16* __restrict__ Alo,
    const __nv_bfloat16* __restrict__ Bhi, const __nv_bfloat16* __restrict__ Blo,
    const __nv_bfloat16* __restrict__ B2hi, const __nv_bfloat16* __restrict__ B2lo,
    float* __restrict__ C, int M, int Nact, int K,
    const float* __restrict__ aux0, const float* __restrict__ aux0b,
    float* __restrict__ o1, float* __restrict__ o2)
{
    __shared__ __align__(16) __nv_bfloat16 As[2][2][64*16];
    __shared__ __align__(16) __nv_bfloat16 Bs[2][2][64*16];
    int tid = threadIdx.x, lane = tid & 31, warp = tid >> 5;
    int row0 = blockIdx.y * 64, col0 = blockIdx.x * 64;
    if (SPLIT && row0 >= (M >> 1)) { Bhi = B2hi; Blo = B2lo; aux0 = aux0b; }
    int wm = (warp & 1) * 32, wn = (warp >> 1) * 32;
    int lq = lane >> 2, kq = (lane & 3) * 2;

    float acc[2][4][4];
    #pragma unroll
    for (int mi = 0; mi < 2; mi++)
        #pragma unroll
        for (int ni = 0; ni < 4; ni++)
            #pragma unroll
            for (int q = 0; q < 4; q++) acc[mi][ni][q] = 0.f;

    int lr = tid >> 1, lseg = (tid & 1) * 8;
    const __nv_bfloat16* gAh = Ahi + (size_t)(row0 + lr)*K + lseg;
    const __nv_bfloat16* gAl = Alo + (size_t)(row0 + lr)*K + lseg;
    bool bok = (col0 + lr) < Nact;
    const __nv_bfloat16* gBh = Bhi + (size_t)(col0 + lr)*K + lseg;
    const __nv_bfloat16* gBl = Blo + (size_t)(col0 + lr)*K + lseg;
    int sidx = lr * 16 + lseg;
    uint4 z4 = make_uint4(0,0,0,0);

    *(uint4*)&As[0][0][sidx] = *(const uint4*)(gAh);
    *(uint4*)&As[0][1][sidx] = *(const uint4*)(gAl);
    *(uint4*)&Bs[0][0][sidx] = bok ? *(const uint4*)(gBh) : z4;
    *(uint4*)&Bs[0][1][sidx] = bok ? *(const uint4*)(gBl) : z4;
    __syncthreads();

    int nkc = K >> 4;
    int buf = 0;
    for (int kc = 1; ; kc++) {
        bool has = (kc < nkc);
        uint4 nAh, nAl, nBh = z4, nBl = z4;
        if (has) {
            int k0 = kc * 16;
            nAh = *(const uint4*)(gAh + k0);
            nAl = *(const uint4*)(gAl + k0);
            if (bok) { nBh = *(const uint4*)(gBh + k0); nBl = *(const uint4*)(gBl + k0); }
        }
        {
            const __nv_bfloat16* ah = As[buf][0];
            const __nv_bfloat16* al = As[buf][1];
            const __nv_bfloat16* bh = Bs[buf][0];
            const __nv_bfloat16* bl = Bs[buf][1];
            unsigned bfh[4][2], bfl[4][2];
            #pragma unroll
            for (int ni = 0; ni < 4; ni++) {
                int cb = (wn + ni*8 + lq) * 16;
                bfh[ni][0] = *(const unsigned*)(bh + cb + kq);
                bfh[ni][1] = *(const unsigned*)(bh + cb + kq + 8);
                bfl[ni][0] = *(const unsigned*)(bl + cb + kq);
                bfl[ni][1] = *(const unsigned*)(bl + cb + kq + 8);
            }
            #pragma unroll
            for (int mi = 0; mi < 2; mi++) {
                int rb = (wm + mi*16 + lq) * 16;
                unsigned ah0 = *(const unsigned*)(ah + rb + kq);
                unsigned ah1 = *(const unsigned*)(ah + rb + 128 + kq);
                unsigned ah2 = *(const unsigned*)(ah + rb + kq + 8);
                unsigned ah3 = *(const unsigned*)(ah + rb + 128 + kq + 8);
                unsigned al0 = *(const unsigned*)(al + rb + kq);
                unsigned al1 = *(const unsigned*)(al + rb + 128 + kq);
                unsigned al2 = *(const unsigned*)(al + rb + kq + 8);
                unsigned al3 = *(const unsigned*)(al + rb + 128 + kq + 8);
                #pragma unroll
                for (int ni = 0; ni < 4; ni++) {
                    MMA_BF16(acc[mi][ni], ah0, ah1, ah2, ah3, bfh[ni][0], bfh[ni][1]);
                    MMA_BF16(acc[mi][ni], ah0, ah1, ah2, ah3, bfl[ni][0], bfl[ni][1]);
                    MMA_BF16(acc[mi][ni], al0, al1, al2, al3, bfh[ni][0], bfh[ni][1]);
                }
            }
        }
        if (!has) break;
        int nb = buf ^ 1;
        *(uint4*)&As[nb][0][sidx] = nAh;
        *(uint4*)&As[nb][1][sidx] = nAl;
        *(uint4*)&Bs[nb][0][sidx] = nBh;
        *(uint4*)&Bs[nb][1][sidx] = nBl;
        __syncthreads();
        buf = nb;
    }

    #pragma unroll
    for (int mi = 0; mi < 2; mi++) {
        #pragma unroll
        for (int ni = 0; ni < 4; ni++) {
            int row = row0 + wm + mi*16 + lq;
            int col = col0 + wn + ni*8 + kq;
            float* d = acc[mi][ni];
            #pragma unroll
            for (int q = 0; q < 4; q++) {
                int r = row + (q >> 1) * 8;
                int c = col + (q & 1);
                float v = d[q];
                if (c < 128) {
                    float t = v + aux0[c];
                    C[(size_t)r*128 + c] = (t > 20.f) ? t : log1pf(__expf(t));
                } else if (c < 144) {
                    o1[(size_t)r*16 + (c - 128)] = v;
                } else if (c < 160) {
                    o2[(size_t)r*16 + (c - 144)] = v;
                }
            }
        }
    }
}

// ================= bf16 split GEMM for graph (fixed 1024^3) =================
template<int WHICH>
__global__ void __launch_bounds__(128) tcmma_k(
    const __nv_bfloat16* __restrict__ Ahi, const __nv_bfloat16* __restrict__ Alo,
    const __nv_bfloat16* __restrict__ Bhi, const __nv_bfloat16* __restrict__ Blo,
    float* __restrict__ C, const float* __restrict__ xall)
{
    __shared__ __align__(16) __nv_bfloat16 As[2][2][64*16];
    __shared__ __align__(16) __nv_bfloat16 Bs[2][2][64*16];
    int tid = threadIdx.x, lane = tid & 31, warp = tid >> 5;
    int row0 = blockIdx.y * 64, col0 = blockIdx.x * 64;
    int wm = (warp & 1) * 32, wn = (warp >> 1) * 32;
    int lq = lane >> 2, kq = (lane & 3) * 2;

    float acc[2][4][4];
    #pragma unroll
    for (int mi = 0; mi < 2; mi++)
        #pragma unroll
        for (int ni = 0; ni < 4; ni++)
            #pragma unroll
            for (int q = 0; q < 4; q++) acc[mi][ni][q] = 0.f;

    int lr = tid >> 1, lseg = (tid & 1) * 8;
    const __nv_bfloat16* gAh = Ahi + (size_t)(row0 + lr)*1024 + lseg;
    const __nv_bfloat16* gAl = Alo + (size_t)(row0 + lr)*1024 + lseg;
    const __nv_bfloat16* gBh = Bhi + (size_t)(col0 + lr)*1024 + lseg;
    const __nv_bfloat16* gBl = Blo + (size_t)(col0 + lr)*1024 + lseg;
    int sidx = lr * 16 + lseg;

    *(uint4*)&As[0][0][sidx] = *(const uint4*)(gAh);
    *(uint4*)&As[0][1][sidx] = *(const uint4*)(gAl);
    *(uint4*)&Bs[0][0][sidx] = *(const uint4*)(gBh);
    *(uint4*)&Bs[0][1][sidx] = *(const uint4*)(gBl);
    __syncthreads();

    int buf = 0;
    for (int kc = 1; ; kc++) {
        bool has = (kc < 64);
        uint4 nAh, nAl, nBh, nBl;
        if (has) {
            int k0 = kc * 16;
            nAh = *(const uint4*)(gAh + k0);
            nAl = *(const uint4*)(gAl + k0);
            nBh = *(const uint4*)(gBh + k0);
            nBl = *(const uint4*)(gBl + k0);
        }
        {
            const __nv_bfloat16* ah = As[buf][0];
            const __nv_bfloat16* al = As[buf][1];
            const __nv_bfloat16* bh = Bs[buf][0];
            const __nv_bfloat16* bl = Bs[buf][1];
            unsigned bfh[4][2], bfl[4][2];
            #pragma unroll
            for (int ni = 0; ni < 4; ni++) {
                int cb = (wn + ni*8 + lq) * 16;
                bfh[ni][0] = *(const unsigned*)(bh + cb + kq);
                bfh[ni][1] = *(const unsigned*)(bh + cb + kq + 8);
                bfl[ni][0] = *(const unsigned*)(bl + cb + kq);
                bfl[ni][1] = *(const unsigned*)(bl + cb + kq + 8);
            }
            #pragma unroll
            for (int mi = 0; mi < 2; mi++) {
                int rb = (wm + mi*16 + lq) * 16;
                unsigned ah0 = *(const unsigned*)(ah + rb + kq);
                unsigned ah1 = *(const unsigned*)(ah + rb + 128 + kq);
                unsigned ah2 = *(const unsigned*)(ah + rb + kq + 8);
                unsigned ah3 = *(const unsigned*)(ah + rb + 128 + kq + 8);
                unsigned al0 = *(const unsigned*)(al + rb + kq);
                unsigned al1 = *(const unsigned*)(al + rb + 128 + kq);
                unsigned al2 = *(const unsigned*)(al + rb + kq + 8);
                unsigned al3 = *(const unsigned*)(al + rb + 128 + kq + 8);
                #pragma unroll
                for (int ni = 0; ni < 4; ni++) {
                    MMA_BF16(acc[mi][ni], ah0, ah1, ah2, ah3, bfh[ni][0], bfh[ni][1]);
                    MMA_BF16(acc[mi][ni], ah0, ah1, ah2, ah3, bfl[ni][0], bfl[ni][1]);
                    MMA_BF16(acc[mi][ni], al0, al1, al2, al3, bfh[ni][0], bfh[ni][1]);
                }
            }
        }
        if (!has) break;
        int nb = buf ^ 1;
        *(uint4*)&As[nb][0][sidx] = nAh;
        *(uint4*)&As[nb][1][sidx] = nAl;
        *(uint4*)&Bs[nb][0][sidx] = nBh;
        *(uint4*)&Bs[nb][1][sidx] = nBl;
        __syncthreads();
        buf = nb;
    }

    #pragma unroll
    for (int mi = 0; mi < 2; mi++) {
        #pragma unroll
        for (int ni = 0; ni < 4; ni++) {
            int row = row0 + wm + mi*16 + lq;
            int col = col0 + wn + ni*8 + kq;
            float* d = acc[mi][ni];
            if (WHICH == 1) {
                C[(size_t)row*1024 + col]       = d[0];
                C[(size_t)row*1024 + col + 1]   = d[1];
                C[(size_t)(row+8)*1024 + col]   = d[2];
                C[(size_t)(row+8)*1024 + col+1] = d[3];
            } else {
                C[(size_t)row*1024 + col]       = 2.f*d[0] - xall[(size_t)row*1024 + col];
                C[(size_t)row*1024 + col + 1]   = 2.f*d[1] - xall[(size_t)row*1024 + col + 1];
                C[(size_t)(row+8)*1024 + col]   = 2.f*d[2] - xall[(size_t)(row+8)*1024 + col];
                C[(size_t)(row+8)*1024 + col+1] = 2.f*d[3] - xall[(size_t)(row+8)*1024 + col+1];
            }
        }
    }
}

// ---------------- bf16 hi/lo split (elementwise) ----------------
__global__ void bfsplit_k(const float* __restrict__ in, __nv_bfloat16* __restrict__ hi,
                          __nv_bfloat16* __restrict__ lo, int n)
{
    int g = blockIdx.x * 256 + threadIdx.x;
    if (g >= n) return;
    float v = in[g];
    __nv_bfloat16 h = __float2bfloat16(v);
    hi[g] = h;
    lo[g] = __float2bfloat16(v - __bfloat162float(h));
}

// ---------------- transpose + split: in fp32 [1024][1024] -> hi/lo [c][r] ----------
__global__ void tsplit_k(const float* __restrict__ in, __nv_bfloat16* __restrict__ hi,
                         __nv_bfloat16* __restrict__ lo)
{
    __shared__ float t[32][33];
    int r0 = blockIdx.y * 32, c0 = blockIdx.x * 32;
    int tx = threadIdx.x, ty = threadIdx.y;   // 32 x 8
    #pragma unroll
    for (int i = 0; i < 4; i++) {
        int r = ty + i*8;
        t[r][tx] = in[(size_t)(r0 + r)*1024 + c0 + tx];
    }
    __syncthreads();
    #pragma unroll
    for (int i = 0; i < 4; i++) {
        int c = ty + i*8;
        float v = t[tx][c];
        __nv_bfloat16 h = __float2bfloat16(v);
        size_t o = (size_t)(c0 + c)*1024 + r0 + tx;
        hi[o] = h;
        lo[o] = __float2bfloat16(v - __bfloat162float(h));
    }
}

// ---------------- x (B,N,D) -> XallT hi/lo [bd,node] bf16, tiled transpose ------
__global__ void xallT_k(const float* __restrict__ x, __nv_bfloat16* __restrict__ hi,
                        __nv_bfloat16* __restrict__ lo)
{
    __shared__ float t[64*33];
    int b = blockIdx.y, n0 = blockIdx.x * 32;
    int tid = threadIdx.x;
    for (int idx = tid; idx < 2048; idx += 256) {
        int ni = idx >> 6, c = idx & 63;
        t[c*33 + ni] = x[(size_t)b*65536 + (size_t)(n0 + ni)*64 + c];
    }
    __syncthreads();
    for (int idx = tid; idx < 2048; idx += 256) {
        int ni = idx & 31, c = idx >> 5;
        float v = t[c*33 + ni];
        __nv_bfloat16 h = __float2bfloat16(v);
        size_t o = (size_t)(b*64 + c)*1024 + n0 + ni;
        hi[o] = h;
        lo[o] = __float2bfloat16(v - __bfloat162float(h));
    }
}

// ---------------- causal conv (both directions) + silu (+ bf16 hi/lo out) --------
__global__ void conv_silu_k(const float* __restrict__ xz,
                            const float* __restrict__ cw0, const float* __restrict__ cb0,
                            const float* __restrict__ cw1, const float* __restrict__ cb1,
                            float* __restrict__ xc0, float* __restrict__ xc1,
                            __nv_bfloat16* __restrict__ xch, __nv_bfloat16* __restrict__ xcl)
{
    int dir = blockIdx.y;
    int g = blockIdx.x * 256 + threadIdx.x;
    int d = g & 127; int m = g >> 7; int l = m & 1023;
    const float* cw = dir ? cw1 : cw0;
    const float* cb = dir ? cb1 : cb0;
    const float* src = xz + dir * 256 + d;
    float acc = cb[d];
    #pragma unroll
    for (int k = 0; k < 4; k++) {
        int ll = dir ? (l + 3 - k) : (l - 3 + k);
        if (ll >= 0 && ll < 1024)
            acc = fmaf(src[(size_t)(m - l + ll) * 512], cw[d*4 + k], acc);
    }
    float v = silu_(acc);
    (dir ? xc1 : xc0)[g] = v;
    size_t o = (size_t)dir * 2097152 + g;
    __nv_bfloat16 hh = __float2bfloat16(v);
    xch[o] = hh;
    xcl[o] = __float2bfloat16(v - __bfloat162float(hh));
}

// ---------------- chunked selective scan ----------------
__global__ void __launch_bounds__(512) scan_p1(
    const float* __restrict__ dt0, const float* __restrict__ dt1,
    const float* __restrict__ xc0, const float* __restrict__ xc1,
    const float* __restrict__ B0,  const float* __restrict__ B1,
    const float* __restrict__ A0,  const float* __restrict__ A1,
    float* __restrict__ Hc, float* __restrict__ Ec)
{
    int dir = blockIdx.z >> 4;
    int b   = blockIdx.z & 15;
    int c   = blockIdx.y;
    int t = threadIdx.x, s = t & 15, dl = t >> 4;
    int d = blockIdx.x * 32 + dl;
    const float* dt = dir ? dt1 : dt0;
    const float* xc = dir ? xc1 : xc0;
    const float* Bm = dir ? B1 : B0;
    float Ads = (dir ? A1 : A0)[d*16 + s];
    int l0  = dir ? (1023 - c*CHLEN) : c*CHLEN;
    int stp = dir ? -1 : 1;
    const float* pdt = dt + (size_t)b*131072 + (size_t)l0*128 + d;
    const float* pxc = xc + (size_t)b*131072 + (size_t)l0*128 + d;
    const float* pB  = Bm + (size_t)b*16384  + (size_t)l0*16  + s;
    int d128 = stp*128, d16 = stp*16;
    float h = 0.f, sdt = 0.f;
    float dtv = *pdt, xcv = *pxc, Bv = *pB;
    for (int tt = 0; tt < CHLEN; tt++) {
        float dtv2, xcv2, Bv2;
        if (tt < CHLEN-1) { dtv2 = pdt[d128]; xcv2 = pxc[d128]; Bv2 = pB[d16]; }
        else { dtv2 = xcv2 = Bv2 = 0.f; }
        float e = __expf(dtv * Ads);
        h = fmaf(h, e, dtv * Bv * xcv);
        sdt += dtv;
        pdt += d128; pxc += d128; pB += d16;
        dtv = dtv2; xcv = xcv2; Bv = Bv2;
    }
    size_t idx = ((((size_t)dir*16 + b)*NCHUNK + c)*128 + d)*16 + s;
    Hc[idx] = h;
    Ec[idx] = __expf(Ads * sdt);
}

__global__ void scan_comb(const float* __restrict__ Hc, const float* __restrict__ Ec,
                          float* __restrict__ h0arr)
{
    int g = blockIdx.x * 256 + threadIdx.x;
    int s = g & 15; int d = (g >> 4) & 127; int bb = g >> 11;
    float carry = 0.f;
    #pragma unroll
    for (int c = 0; c < NCHUNK; c++) {
        size_t idx = (((size_t)bb*NCHUNK + c)*128 + d)*16 + s;
        h0arr[idx] = carry;
        carry = fmaf(carry, Ec[idx], Hc[idx]);
    }
}

__global__ void __launch_bounds__(512) scan_p2(
    const float* __restrict__ dt0, const float* __restrict__ dt1,
    const float* __restrict__ xc0, const float* __restrict__ xc1,
    const float* __restrict__ B0,  const float* __restrict__ B1,
    const float* __restrict__ C0,  const float* __restrict__ C1,
    const float* __restrict__ xz,
    const float* __restrict__ A0,  const float* __restrict__ A1,
    const float* __restrict__ D0,  const float* __restrict__ D1,
    const float* __restrict__ h0arr, float* __restrict__ ycat)
{
    int dir = blockIdx.z >> 4;
    int b   = blockIdx.z & 15;
    int c   = blockIdx.y;
    int t = threadIdx.x, s = t & 15, dl = t >> 4;
    int d = blockIdx.x * 32 + dl;
    const float* dt = dir ? dt1 : dt0;
    const float* xc = dir ? xc1 : xc0;
    const float* Bm = dir ? B1 : B0;
    const float* Cm = dir ? C1 : C0;
    float Ads = (dir ? A1 : A0)[d*16 + s];
    float Dpd = (dir ? D1 : D0)[d];
    int l0  = dir ? (1023 - c*CHLEN) : c*CHLEN;
    int stp = dir ? -1 : 1;
    const float* pdt = dt + (size_t)b*131072 + (size_t)l0*128 + d;
    const float* pxc = xc + (size_t)b*131072 + (size_t)l0*128 + d;
    const float* pB  = Bm + (size_t)b*16384  + (size_t)l0*16  + s;
    const float* pC  = Cm + (size_t)b*16384  + (size_t)l0*16  + s;
    const float* pz  = xz + (size_t)b*524288 + (size_t)l0*512 + dir*256 + 128 + d;
    float* py        = ycat + (size_t)b*262144 + (size_t)l0*256 + dir*128 + d;
    int d128 = stp*128, d16 = stp*16, d512 = stp*512, d256 = stp*256;

    size_t idx = ((((size_t)dir*16 + b)*NCHUNK + c)*128 + d)*16 + s;
    float h = h0arr[idx];

    float dtv = *pdt, xcv = *pxc, Bv = *pB, Cv = *pC, zv = *pz;
    for (int tt = 0; tt < CHLEN; tt++) {
        float dtv2, xcv2, Bv2, Cv2, zv2;
        if (tt < CHLEN-1) {
            dtv2 = pdt[d128]; xcv2 = pxc[d128];
            Bv2  = pB[d16];   Cv2  = pC[d16];
            zv2  = pz[d512];
        } else { dtv2 = xcv2 = Bv2 = Cv2 = zv2 = 0.f; }
        float e = __expf(dtv * Ads);
        h = fmaf(h, e, dtv * Bv * xcv);
        float part = h * Cv;
        part += __shfl_xor_sync(0xffffffffu, part, 8);
        part += __shfl_xor_sync(0xffffffffu, part, 4);
        part += __shfl_xor_sync(0xffffffffu, part, 2);
        part += __shfl_xor_sync(0xffffffffu, part, 1);
        if (s == 0)
            py[0] = (part + Dpd * xcv) * silu_(zv);
        pdt += d128; pxc += d128; pB += d16; pC += d16; pz += d512; py += d256;
        dtv = dtv2; xcv = xcv2; Bv = Bv2; Cv = Cv2; zv = zv2;
    }
}

// ---------------- support matrix: softmax(relu(E E^T)) ----------------
__global__ void __launch_bounds__(256) sup_k(const float* __restrict__ emb, float* __restrict__ sup)
{
    __shared__ float se[NNODE * EDIM];
    __shared__ float red[256];
    int n = blockIdx.x, tid = threadIdx.x;
    for (int i = tid; i < NNODE*EDIM; i += 256) se[i] = emb[i];
    __syncthreads();
    float en[EDIM];
    #pragma unroll
    for (int e = 0; e < EDIM; e++) en[e] = se[n*EDIM + e];
    float vals[4]; float mx = -1e30f;
    #pragma unroll
    for (int jj = 0; jj < 4; jj++) {
        int j = jj*256 + tid;
        float v = 0.f;
        #pragma unroll
        for (int e = 0; e < EDIM; e++) v = fmaf(en[e], se[j*EDIM + e], v);
        v = v > 0.f ? v : 0.f;
        vals[jj] = v; mx = fmaxf(mx, v);
    }
    red[tid] = mx; __syncthreads();
    for (int o = 128; o > 0; o >>= 1) { if (tid < o) red[tid] = fmaxf(red[tid], red[tid+o]); __syncthreads(); }
    mx = red[0]; __syncthreads();
    float s = 0.f;
    #pragma unroll
    for (int jj = 0; jj < 4; jj++) { vals[jj] = __expf(vals[jj] - mx); s += vals[jj]; }
    red[tid] = s; __syncthreads();
    for (int o = 128; o > 0; o >>= 1) { if (tid < o) red[tid] += red[tid+o]; __syncthreads(); }
    float inv = 1.f / red[0];
    #pragma unroll
    for (int jj = 0; jj < 4; jj++) sup[(size_t)n*1024 + jj*256 + tid] = vals[jj] * inv;
}

// ---------------- x (B,N,D) -> Xall (N, B*D) fp32 ----------------
__global__ void xall_k(const float* __restrict__ x, float* __restrict__ xall)
{
    int g = blockIdx.x * 256 + threadIdx.x;
    int c = g & 63, n = (g >> 6) & 1023, b = g >> 16;
    xall[(size_t)n*1024 + b*64 + c] = x[g];
}

// ---------------- W[n,k,c,o] = sum_e emb[n,e] W_pool[e,k,c,o] ----------------
__global__ void wmix_k(const float* __restrict__ emb, const float* __restrict__ wp,
                       float* __restrict__ W)
{
    int n = blockIdx.y;
    int j = blockIdx.x * 256 + threadIdx.x;
    float acc = 0.f;
    #pragma unroll
    for (int e = 0; e < EDIM; e++) acc = fmaf(emb[n*EDIM + e], wp[(size_t)e*12288 + j], acc);
    W[(size_t)n*12288 + j] = acc;
}

// ---------------- per-node graph conv ----------------
__global__ void __launch_bounds__(256) gconv_k(
    const float* __restrict__ x,  const float* __restrict__ xg1,
    const float* __restrict__ xg2, const float* __restrict__ W,
    const float* __restrict__ emb, const float* __restrict__ bp,
    float* __restrict__ go)
{
    __shared__ float xs[3072];
    __shared__ float bs[64];
    int n = blockIdx.x, tid = threadIdx.x;
    const float* Wn = W + (size_t)n * 12288;
    for (int i = tid; i < 3072; i += 256) {
        int k = i >> 10; int rem = i & 1023; int b = rem >> 6; int c = rem & 63;
        float v;
        if (k == 0) v = x[(size_t)b*65536 + (size_t)n*64 + c];
        else        v = (k == 1 ? xg1 : xg2)[(size_t)n*1024 + b*64 + c];
        xs[i] = v;
    }
    if (tid < 64) {
        float a = 0.f;
        #pragma unroll
        for (int e = 0; e < EDIM; e++) a = fmaf(emb[n*EDIM + e], bp[e*64 + tid], a);
        bs[tid] = a;
    }
    __syncthreads();
    int o = tid & 63, bq = tid >> 6;
    float acc[4];
    #pragma unroll
    for (int q = 0; q < 4; q++) acc[q] = bs[o];
    #pragma unroll 4
    for (int kc = 0; kc < 192; kc++) {
        float w = __ldg(Wn + kc*64 + o);
        int k = kc >> 6, c = kc & 63;
        #pragma unroll
        for (int q = 0; q < 4; q++)
            acc[q] = fmaf(xs[(k*16 + bq + q*4)*64 + c], w, acc[q]);
    }
    #pragma unroll
    for (int q = 0; q < 4; q++) {
        int b = bq + q*4;
        go[(size_t)b*65536 + (size_t)n*64 + o] = acc[q];
    }
}

// ---------------- launch ----------------
extern "C" void kernel_launch(void* const* d_in, const int* in_sizes, int n_in,
                              void* d_out, int out_size)
{
    const float* x_in     = (const float*)d_in[0];
    const float* fw_in    = (const float*)d_in[1];
    const float* fw_cw    = (const float*)d_in[2];
    const float* fw_cb    = (const float*)d_in[3];
    const float* fw_xp    = (const float*)d_in[4];
    const float* fw_dtw   = (const float*)d_in[5];
    const float* fw_dtb   = (const float*)d_in[6];
    const float* fw_Alog  = (const float*)d_in[7];
    const float* fw_D     = (const float*)d_in[8];
    const float* fw_out   = (const float*)d_in[9];
    const float* bw_in    = (const float*)d_in[10];
    const float* bw_cw    = (const float*)d_in[11];
    const float* bw_cb    = (const float*)d_in[12];
    const float* bw_xp    = (const float*)d_in[13];
    const float* bw_dtw   = (const float*)d_in[14];
    const float* bw_dtb   = (const float*)d_in[15];
    const float* bw_Alog  = (const float*)d_in[16];
    const float* bw_D     = (const float*)d_in[17];
    const float* bw_out   = (const float*)d_in[18];
    const float* ln1_g    = (const float*)d_in[19];
    const float* ln1_b    = (const float*)d_in[20];
    const float* ffn_w1   = (const float*)d_in[21];
    const float* ffn_b1   = (const float*)d_in[22];
    const float* ffn_w2   = (const float*)d_in[23];
    const float* ffn_b2   = (const float*)d_in[24];
    const float* ln2_g    = (const float*)d_in[25];
    const float* ln2_b    = (const float*)d_in[26];
    const float* node_emb = (const float*)d_in[27];
    const float* W_pool   = (const float*)d_in[28];
    const float* b_pool   = (const float*)d_in[29];
    const float* proj_w   = (const float*)d_in[30];
    const float* proj_b   = (const float*)d_in[31];
    float* outp = (float*)d_out;

    float* S = nullptr;
    cudaGetSymbolAddress((void**)&S, g_scratch);

    float* Wcat   = S;
    float* A0     = S + 73728;
    float* A1     = S + 75776;
    float* xz     = S + 77824;
    float* xc0    = S + 8466432;
    float* xc1    = S + 10563584;
    float* dt0    = S + 12660736;
    float* dt1    = S + 14757888;
    float* Bm0    = S + 16855040;
    float* Bm1    = S + 17117184;
    float* Cm0    = S + 17379328;
    float* Cm1    = S + 17641472;
    float* ycat   = S + 17903616;
    float* xbuf   = S + 22097920;
    float* xln    = S + 23146496;
    float* xall   = S + 24195072;
    float* hbuf   = S + 25243648;
    float* sup    = S + 29437952;
    float* xg1    = S + 31535104;
    float* xg2    = S + 32583680;
    float* Wbig   = S + 33632256;
    float* go     = S + 46215168;
    float* Wocat  = S + 47263744;
    float* Hc     = S + 47280128;
    float* Ec     = S + 47804416;
    float* h0arr  = S + 48328704;
    __nv_bfloat16* sup_hi  = (__nv_bfloat16*)(S + 48852992);
    __nv_bfloat16* sup_lo  = (__nv_bfloat16*)(S + 49377280);
    __nv_bfloat16* xaT_hi  = (__nv_bfloat16*)(S + 49901568);
    __nv_bfloat16* xaT_lo  = (__nv_bfloat16*)(S + 50425856);
    __nv_bfloat16* xg1t_hi = (__nv_bfloat16*)(S + 50950144);
    __nv_bfloat16* xg1t_lo = (__nv_bfloat16*)(S + 51474432);
    __nv_bfloat16* wc0Th   = (__nv_bfloat16*)(S + 52031488);
    __nv_bfloat16* wc0Tl   = (__nv_bfloat16*)(S + 52041728);
    __nv_bfloat16* wc1Th   = (__nv_bfloat16*)(S + 52051968);
    __nv_bfloat16* wc1Tl   = (__nv_bfloat16*)(S + 52062208);
    __nv_bfloat16* xch     = (__nv_bfloat16*)(S + 53121024);
    __nv_bfloat16* xcl     = (__nv_bfloat16*)(S + 55218176);

    // prep
    {
        int total = 32768 + 40960 + 4096 + 16384 + MROWS*DMODEL;
        prep_k<<<(total + 255)/256, 256>>>(fw_in, bw_in, fw_xp, fw_dtw, bw_xp, bw_dtw,
                                           fw_Alog, bw_Alog, fw_out, bw_out, x_in,
                                           Wcat, wc0Th, wc0Tl, wc1Th, wc1Tl,
                                           A0, A1, Wocat, xbuf);
    }

    for (int layer = 0; layer < 2; layer++) {
        // xz = x @ [fw_in | bw_in]  (fp32 engine — better for K=64)
        sgemm_k<0,0><<<dim3(8, 256), 256>>>(xbuf, Wcat, xz, MROWS, 512, 64,
                                            nullptr, nullptr, nullptr, nullptr, nullptr, nullptr);
        // conv + silu, both dirs (+ bf16 hi/lo for xproj tensor GEMM)
        conv_silu_k<<<dim3((MROWS*128)/256, 2), 256>>>(xz, fw_cw, fw_cb, bw_cw, bw_cb,
                                                       xc0, xc1, xch, xcl);
        // xproj both dirs in ONE tensor-core launch (M=32768, N=160(pad 192), K=128)
        tcg_k<1,1><<<dim3(3, 512), 128>>>(xch, xcl, wc0Th, wc0Tl, wc1Th, wc1Tl,
                                          dt0, 2*MROWS, 160, 128,
                                          fw_dtb, bw_dtb, Bm0, Cm0);
        // chunked selective scan
        scan_p1<<<dim3(4, NCHUNK, 32), 512>>>(dt0, dt1, xc0, xc1, Bm0, Bm1, A0, A1, Hc, Ec);
        scan_comb<<<256, 256>>>(Hc, Ec, h0arr);
        scan_p2<<<dim3(4, NCHUNK, 32), 512>>>(dt0, dt1, xc0, xc1, Bm0, Bm1, Cm0, Cm1,
                                              xz, A0, A1, fw_D, bw_D, h0arr, ycat);
        // x + [yf|yb]@Wocat, fused LN1 -> xln
        sgemm_k<7,0><<<dim3(1, 256), 256>>>(ycat, Wocat, xln, MROWS, 64, 256,
                                            xbuf, nullptr, (float*)ln1_g, (float*)ln1_b,
                                            nullptr, nullptr);
        // FFN1: relu(xln@W1 + b1)
        sgemm_k<2,0><<<dim3(4, 256), 256>>>(xln, ffn_w1, hbuf, MROWS, 256, 64,
                                            ffn_b1, nullptr, nullptr, nullptr, nullptr, nullptr);
        // FFN2 + residual + b2, fused LN2 -> xbuf
        sgemm_k<8,0><<<dim3(1, 256), 256>>>(hbuf, ffn_w2, xbuf, MROWS, 64, 256,
                                            xln, ffn_b2, (float*)ln2_g, (float*)ln2_b,
                                            nullptr, nullptr);
    }

    // graph part
    sup_k<<<NNODE, 256>>>(node_emb, sup);
    bfsplit_k<<<4096, 256>>>(sup, sup_hi, sup_lo, NNODE*NNODE);
    xall_k<<<4096, 256>>>(xbuf, xall);
    xallT_k<<<dim3(32, 16), 256>>>(xbuf, xaT_hi, xaT_lo);

    // XG1 = sup @ Xall  (tensor cores, split bf16)
    tcmma_k<1><<<dim3(16, 16), 128>>>(sup_hi, sup_lo, xaT_hi, xaT_lo, xg1, nullptr);
    tsplit_k<<<dim3(32, 32), dim3(32, 8)>>>(xg1, xg1t_hi, xg1t_lo);
    // XG2 = 2*sup@XG1 - Xall
    tcmma_k<2><<<dim3(16, 16), 128>>>(sup_hi, sup_lo, xg1t_hi, xg1t_lo, xg2, xall);

    wmix_k<<<dim3(48, 1024), 256>>>(node_emb, W_pool, Wbig);
    gconv_k<<<NNODE, 256>>>(xbuf, xg1, xg2, Wbig, node_emb, b_pool, go);
    sgemm_k<6,0><<<dim3(2, 256), 256>>>(go, proj_w, outp, MROWS, 96, 64,
                                        proj_b, nullptr, nullptr, nullptr, nullptr, nullptr);
}

// round 15
// speedup vs baseline: 1.4025x; 1.3831x over previous
#include <cuda_runtime.h>
#include <cuda_bf16.h>
#include <math.h>

// ---------------- problem constants ----------------
#define BATCH   16
#define LSEQ    1024
#define DMODEL  64
#define DINNER  128
#define SSTATE  16
#define MROWS   (BATCH*LSEQ)   // 16384
#define HFFN    256
#define NNODE   1024
#define EDIM    10
#define PLOUT   96
#define NCHUNK  8
#define CHLEN   128

// ---------------- scratch (single static device buffer) ----------------
__device__ float g_scratch[57315328];

__device__ __forceinline__ float silu_(float x) { return x / (1.f + __expf(-x)); }

// ---------------- prep: Wcat fp32, WcombT bf16 hi/lo, A=-exp, Wocat, x copy ------
__global__ void prep_k(const float* __restrict__ fw_in, const float* __restrict__ bw_in,
                       const float* __restrict__ fwx, const float* __restrict__ fwdt,
                       const float* __restrict__ bwx, const float* __restrict__ bwdt,
                       const float* __restrict__ fwA, const float* __restrict__ bwA,
                       const float* __restrict__ fw_out, const float* __restrict__ bw_out,
                       const float* __restrict__ x_in,
                       float* __restrict__ Wcat,
                       __nv_bfloat16* __restrict__ wc0Th, __nv_bfloat16* __restrict__ wc0Tl,
                       __nv_bfloat16* __restrict__ wc1Th, __nv_bfloat16* __restrict__ wc1Tl,
                       float* __restrict__ A0, float* __restrict__ A1,
                       float* __restrict__ Wocat,
                       float* __restrict__ xbuf)
{
    int g = blockIdx.x * 256 + threadIdx.x;
    if (g < 32768) {  // Wcat (64,512) fp32
        int k = g >> 9, j = g & 511;
        Wcat[g] = (j < 256) ? fw_in[k*256 + j] : bw_in[k*256 + (j-256)];
        return;
    }
    int h = g - 32768;
    if (h < 40960) {  // WcombT per dir: [160][128] bf16 hi/lo
        int dir = h / 20480; int r2 = h % 20480;
        int j = r2 >> 7, i = r2 & 127;
        const float* Wx  = dir ? bwx  : fwx;
        const float* Wdt = dir ? bwdt : fwdt;
        float v;
        if (j < 128) {
            v = 0.f;
            #pragma unroll
            for (int r = 0; r < 4; r++) v = fmaf(Wx[i*36 + r], Wdt[r*128 + j], v);
        } else {
            v = Wx[i*36 + 4 + (j - 128)];
        }
        __nv_bfloat16 hh = __float2bfloat16(v);
        __nv_bfloat16 ll = __float2bfloat16(v - __bfloat162float(hh));
        if (dir) { wc1Th[j*128 + i] = hh; wc1Tl[j*128 + i] = ll; }
        else     { wc0Th[j*128 + i] = hh; wc0Tl[j*128 + i] = ll; }
        return;
    }
    h -= 40960;
    if (h < 4096) {  // A
        int dir = h >> 11; int i = h & 2047;
        (dir ? A1 : A0)[i] = -__expf((dir ? bwA : fwA)[i]);
        return;
    }
    h -= 4096;
    if (h < 16384) {  // Wocat (256,64) fp32
        int r = h >> 6, c = h & 63;
        Wocat[h] = (r < 128) ? fw_out[r*64 + c] : bw_out[(r-128)*64 + c];
        return;
    }
    h -= 16384;
    if (h < MROWS*DMODEL) xbuf[h] = x_in[h];
}

// ---------------- generic tiled SGEMM, 64x64 tiles, double-buffered (fp32) --------
// EPI: 0 store, 2 bias+relu, 6 +aux0(col), 7 +aux0(full)+LN, 8 +aux0(full)+aux1(col)+LN
template<int EPI, int SPLIT>
__global__ void __launch_bounds__(256) sgemm_k(
    const float* __restrict__ A, const float* __restrict__ B, float* __restrict__ C,
    int M, int N, int K,
    const float* __restrict__ aux0, const float* __restrict__ aux1,
    float* __restrict__ o1, float* __restrict__ o2,
    const float* __restrict__ B2, const float* __restrict__ aux0b)
{
    __shared__ float As[2][16][64];
    __shared__ float Bs[2][16][64];
    int row0 = blockIdx.y * 64, col0 = blockIdx.x * 64;
    if (SPLIT && row0 >= (M >> 1)) { B = B2; aux0 = aux0b; }
    int tid = threadIdx.x;
    int tx = tid & 15, ty = tid >> 4;
    int a_m = tid >> 2, a_k = (tid & 3) * 4;
    int b_k = tid >> 4, b_n = (tid & 15) * 4;
    const float* Aptr = A + (size_t)(row0 + a_m) * K + a_k;
    int bc = col0 + b_n;
    bool bok = bc < N;
    const float* Bptr = B + (size_t)b_k * N + bc;

    float acc[4][4];
    #pragma unroll
    for (int i = 0; i < 4; i++)
        #pragma unroll
        for (int j = 0; j < 4; j++) acc[i][j] = 0.f;

    {
        float4 av = *(const float4*)(Aptr);
        float4 bv = bok ? *(const float4*)(Bptr) : make_float4(0.f,0.f,0.f,0.f);
        As[0][a_k+0][a_m] = av.x; As[0][a_k+1][a_m] = av.y;
        As[0][a_k+2][a_m] = av.z; As[0][a_k+3][a_m] = av.w;
        *(float4*)&Bs[0][b_k][b_n] = bv;
    }
    __syncthreads();

    int buf = 0;
    for (int k0 = 16; ; k0 += 16) {
        bool has = (k0 < K);
        float4 av2, bv2;
        if (has) {
            av2 = *(const float4*)(Aptr + k0);
            bv2 = bok ? *(const float4*)(Bptr + (size_t)k0 * N) : make_float4(0.f,0.f,0.f,0.f);
        }
        #pragma unroll
        for (int kk = 0; kk < 16; kk++) {
            float am[4], bn[4];
            *(float4*)am = *(const float4*)&As[buf][kk][ty*4];
            *(float4*)bn = *(const float4*)&Bs[buf][kk][tx*4];
            #pragma unroll
            for (int i = 0; i < 4; i++)
                #pragma unroll
                for (int j = 0; j < 4; j++)
                    acc[i][j] = fmaf(am[i], bn[j], acc[i][j]);
        }
        if (!has) break;
        int nb = buf ^ 1;
        As[nb][a_k+0][a_m] = av2.x; As[nb][a_k+1][a_m] = av2.y;
        As[nb][a_k+2][a_m] = av2.z; As[nb][a_k+3][a_m] = av2.w;
        *(float4*)&Bs[nb][b_k][b_n] = bv2;
        __syncthreads();
        buf = nb;
    }

    if (EPI == 7 || EPI == 8) {
        float vv[4][4];
        #pragma unroll
        for (int i = 0; i < 4; i++) {
            int row = row0 + ty*4 + i;
            #pragma unroll
            for (int j = 0; j < 4; j++) {
                int col = tx*4 + j;
                float v = acc[i][j] + aux0[(size_t)row*64 + col];
                if (EPI == 8) v += aux1[col];
                vv[i][j] = v;
            }
        }
        #pragma unroll
        for (int i = 0; i < 4; i++) {
            float sm = vv[i][0] + vv[i][1] + vv[i][2] + vv[i][3];
            float sq = vv[i][0]*vv[i][0] + vv[i][1]*vv[i][1]
                     + vv[i][2]*vv[i][2] + vv[i][3]*vv[i][3];
            #pragma unroll
            for (int o = 8; o > 0; o >>= 1) {
                sm += __shfl_xor_sync(0xffffffffu, sm, o);
                sq += __shfl_xor_sync(0xffffffffu, sq, o);
            }
            float mean = sm * (1.f/64.f);
            float var  = sq * (1.f/64.f) - mean*mean;
            float r = rsqrtf(var + 1e-5f);
            int row = row0 + ty*4 + i;
            #pragma unroll
            for (int j = 0; j < 4; j++) {
                int col = tx*4 + j;
                C[(size_t)row*64 + col] = (vv[i][j] - mean) * r * o1[col] + o2[col];
            }
        }
        return;
    }

    #pragma unroll
    for (int i = 0; i < 4; i++) {
        int row = row0 + ty*4 + i;
        #pragma unroll
        for (int j = 0; j < 4; j++) {
            int col = col0 + tx*4 + j;
            if (col >= N) continue;
            float v = acc[i][j];
            size_t idx = (size_t)row * N + col;
            if (EPI == 0) {
                C[idx] = v;
            } else if (EPI == 2) {
                float t = v + aux0[col];
                C[idx] = t > 0.f ? t : 0.f;
            } else if (EPI == 6) {
                C[idx] = v + aux0[col];
            }
        }
    }
}

// ================= generalized bf16 split GEMM via mma.sync =================
#define MMA_BF16(d, A0, A1, A2, A3, Bb0, Bb1) \
    asm volatile("mma.sync.aligned.m16n8k16.row.col.f32.bf16.bf16.f32 " \
                 "{%0,%1,%2,%3}, {%4,%5,%6,%7}, {%8,%9}, {%0,%1,%2,%3};" \
                 : "+f"((d)[0]), "+f"((d)[1]), "+f"((d)[2]), "+f"((d)[3]) \
                 : "r"(A0), "r"(A1), "r"(A2), "r"(A3), "r"(Bb0), "r"(Bb1))

template<int EPI, int SPLIT>
__global__ void __launch_bounds__(128) tcg_k(
    const __nv_bfloat16* __restrict__ Ahi, const __nv_bfloat16* __restrict__ Alo,
    const __nv_bfloat16* __restrict__ Bhi, const __nv_bfloat16* __restrict__ Blo,
    const __nv_bfloat16* __restrict__ B2hi, const __nv_bfloat16* __restrict__ B2lo,
    float* __restrict__ C, int M, int Nact, int K,
    const float* __restrict__ aux0, const float* __restrict__ aux0b,
    float* __restrict__ o1, float* __restrict__ o2)
{
    __shared__ __align__(16) __nv_bfloat16 As[2][2][64*16];
    __shared__ __align__(16) __nv_bfloat16 Bs[2][2][64*16];
    int tid = threadIdx.x, lane = tid & 31, warp = tid >> 5;
    int row0 = blockIdx.y * 64, col0 = blockIdx.x * 64;
    if (SPLIT && row0 >= (M >> 1)) { Bhi = B2hi; Blo = B2lo; aux0 = aux0b; }
    int wm = (warp & 1) * 32, wn = (warp >> 1) * 32;
    int lq = lane >> 2, kq = (lane & 3) * 2;

    float acc[2][4][4];
    #pragma unroll
    for (int mi = 0; mi < 2; mi++)
        #pragma unroll
        for (int ni = 0; ni < 4; ni++)
            #pragma unroll
            for (int q = 0; q < 4; q++) acc[mi][ni][q] = 0.f;

    int lr = tid >> 1, lseg = (tid & 1) * 8;
    const __nv_bfloat16* gAh = Ahi + (size_t)(row0 + lr)*K + lseg;
    const __nv_bfloat16* gAl = Alo + (size_t)(row0 + lr)*K + lseg;
    bool bok = (col0 + lr) < Nact;
    const __nv_bfloat16* gBh = Bhi + (size_t)(col0 + lr)*K + lseg;
    const __nv_bfloat16* gBl = Blo + (size_t)(col0 + lr)*K + lseg;
    int sidx = lr * 16 + lseg;
    uint4 z4 = make_uint4(0,0,0,0);

    *(uint4*)&As[0][0][sidx] = *(const uint4*)(gAh);
    *(uint4*)&As[0][1][sidx] = *(const uint4*)(gAl);
    *(uint4*)&Bs[0][0][sidx] = bok ? *(const uint4*)(gBh) : z4;
    *(uint4*)&Bs[0][1][sidx] = bok ? *(const uint4*)(gBl) : z4;
    __syncthreads();

    int nkc = K >> 4;
    int buf = 0;
    for (int kc = 1; ; kc++) {
        bool has = (kc < nkc);
        uint4 nAh, nAl, nBh = z4, nBl = z4;
        if (has) {
            int k0 = kc * 16;
            nAh = *(const uint4*)(gAh + k0);
            nAl = *(const uint4*)(gAl + k0);
            if (bok) { nBh = *(const uint4*)(gBh + k0); nBl = *(const uint4*)(gBl + k0); }
        }
        {
            const __nv_bfloat16* ah = As[buf][0];
            const __nv_bfloat16* al = As[buf][1];
            const __nv_bfloat16* bh = Bs[buf][0];
            const __nv_bfloat16* bl = Bs[buf][1];
            unsigned bfh[4][2], bfl[4][2];
            #pragma unroll
            for (int ni = 0; ni < 4; ni++) {
                int cb = (wn + ni*8 + lq) * 16;
                bfh[ni][0] = *(const unsigned*)(bh + cb + kq);
                bfh[ni][1] = *(const unsigned*)(bh + cb + kq + 8);
                bfl[ni][0] = *(const unsigned*)(bl + cb + kq);
                bfl[ni][1] = *(const unsigned*)(bl + cb + kq + 8);
            }
            #pragma unroll
            for (int mi = 0; mi < 2; mi++) {
                int rb = (wm + mi*16 + lq) * 16;
                unsigned ah0 = *(const unsigned*)(ah + rb + kq);
                unsigned ah1 = *(const unsigned*)(ah + rb + 128 + kq);
                unsigned ah2 = *(const unsigned*)(ah + rb + kq + 8);
                unsigned ah3 = *(const unsigned*)(ah + rb + 128 + kq + 8);
                unsigned al0 = *(const unsigned*)(al + rb + kq);
                unsigned al1 = *(const unsigned*)(al + rb + 128 + kq);
                unsigned al2 = *(const unsigned*)(al + rb + kq + 8);
                unsigned al3 = *(const unsigned*)(al + rb + 128 + kq + 8);
                #pragma unroll
                for (int ni = 0; ni < 4; ni++) {
                    MMA_BF16(acc[mi][ni], ah0, ah1, ah2, ah3, bfh[ni][0], bfh[ni][1]);
                    MMA_BF16(acc[mi][ni], ah0, ah1, ah2, ah3, bfl[ni][0], bfl[ni][1]);
                    MMA_BF16(acc[mi][ni], al0, al1, al2, al3, bfh[ni][0], bfh[ni][1]);
                }
            }
        }
        if (!has) break;
        int nb = buf ^ 1;
        *(uint4*)&As[nb][0][sidx] = nAh;
        *(uint4*)&As[nb][1][sidx] = nAl;
        *(uint4*)&Bs[nb][0][sidx] = nBh;
        *(uint4*)&Bs[nb][1][sidx] = nBl;
        __syncthreads();
        buf = nb;
    }

    #pragma unroll
    for (int mi = 0; mi < 2; mi++) {
        #pragma unroll
        for (int ni = 0; ni < 4; ni++) {
            int row = row0 + wm + mi*16 + lq;
            int col = col0 + wn + ni*8 + kq;
            float* d = acc[mi][ni];
            #pragma unroll
            for (int q = 0; q < 4; q++) {
                int r = row + (q >> 1) * 8;
                int c = col + (q & 1);
                float v = d[q];
                if (c < 128) {
                    float t = v + aux0[c];
                    C[(size_t)r*128 + c] = (t > 20.f) ? t : log1pf(__expf(t));
                } else if (c < 144) {
                    o1[(size_t)r*16 + (c - 128)] = v;
                } else if (c < 160) {
                    o2[(size_t)r*16 + (c - 144)] = v;
                }
            }
        }
    }
}

// ================= bf16 split GEMM for graph (fixed 1024^3) =================
template<int WHICH>
__global__ void __launch_bounds__(128) tcmma_k(
    const __nv_bfloat16* __restrict__ Ahi, const __nv_bfloat16* __restrict__ Alo,
    const __nv_bfloat16* __restrict__ Bhi, const __nv_bfloat16* __restrict__ Blo,
    float* __restrict__ C, const float* __restrict__ xall)
{
    __shared__ __align__(16) __nv_bfloat16 As[2][2][64*16];
    __shared__ __align__(16) __nv_bfloat16 Bs[2][2][64*16];
    int tid = threadIdx.x, lane = tid & 31, warp = tid >> 5;
    int row0 = blockIdx.y * 64, col0 = blockIdx.x * 64;
    int wm = (warp & 1) * 32, wn = (warp >> 1) * 32;
    int lq = lane >> 2, kq = (lane & 3) * 2;

    float acc[2][4][4];
    #pragma unroll
    for (int mi = 0; mi < 2; mi++)
        #pragma unroll
        for (int ni = 0; ni < 4; ni++)
            #pragma unroll
            for (int q = 0; q < 4; q++) acc[mi][ni][q] = 0.f;

    int lr = tid >> 1, lseg = (tid & 1) * 8;
    const __nv_bfloat16* gAh = Ahi + (size_t)(row0 + lr)*1024 + lseg;
    const __nv_bfloat16* gAl = Alo + (size_t)(row0 + lr)*1024 + lseg;
    const __nv_bfloat16* gBh = Bhi + (size_t)(col0 + lr)*1024 + lseg;
    const __nv_bfloat16* gBl = Blo + (size_t)(col0 + lr)*1024 + lseg;
    int sidx = lr * 16 + lseg;

    *(uint4*)&As[0][0][sidx] = *(const uint4*)(gAh);
    *(uint4*)&As[0][1][sidx] = *(const uint4*)(gAl);
    *(uint4*)&Bs[0][0][sidx] = *(const uint4*)(gBh);
    *(uint4*)&Bs[0][1][sidx] = *(const uint4*)(gBl);
    __syncthreads();

    int buf = 0;
    for (int kc = 1; ; kc++) {
        bool has = (kc < 64);
        uint4 nAh, nAl, nBh, nBl;
        if (has) {
            int k0 = kc * 16;
            nAh = *(const uint4*)(gAh + k0);
            nAl = *(const uint4*)(gAl + k0);
            nBh = *(const uint4*)(gBh + k0);
            nBl = *(const uint4*)(gBl + k0);
        }
        {
            const __nv_bfloat16* ah = As[buf][0];
            const __nv_bfloat16* al = As[buf][1];
            const __nv_bfloat16* bh = Bs[buf][0];
            const __nv_bfloat16* bl = Bs[buf][1];
            unsigned bfh[4][2], bfl[4][2];
            #pragma unroll
            for (int ni = 0; ni < 4; ni++) {
                int cb = (wn + ni*8 + lq) * 16;
                bfh[ni][0] = *(const unsigned*)(bh + cb + kq);
                bfh[ni][1] = *(const unsigned*)(bh + cb + kq + 8);
                bfl[ni][0] = *(const unsigned*)(bl + cb + kq);
                bfl[ni][1] = *(const unsigned*)(bl + cb + kq + 8);
            }
            #pragma unroll
            for (int mi = 0; mi < 2; mi++) {
                int rb = (wm + mi*16 + lq) * 16;
                unsigned ah0 = *(const unsigned*)(ah + rb + kq);
                unsigned ah1 = *(const unsigned*)(ah + rb + 128 + kq);
                unsigned ah2 = *(const unsigned*)(ah + rb + kq + 8);
                unsigned ah3 = *(const unsigned*)(ah + rb + 128 + kq + 8);
                unsigned al0 = *(const unsigned*)(al + rb + kq);
                unsigned al1 = *(const unsigned*)(al + rb + 128 + kq);
                unsigned al2 = *(const unsigned*)(al + rb + kq + 8);
                unsigned al3 = *(const unsigned*)(al + rb + 128 + kq + 8);
                #pragma unroll
                for (int ni = 0; ni < 4; ni++) {
                    MMA_BF16(acc[mi][ni], ah0, ah1, ah2, ah3, bfh[ni][0], bfh[ni][1]);
                    MMA_BF16(acc[mi][ni], ah0, ah1, ah2, ah3, bfl[ni][0], bfl[ni][1]);
                    MMA_BF16(acc[mi][ni], al0, al1, al2, al3, bfh[ni][0], bfh[ni][1]);
                }
            }
        }
        if (!has) break;
        int nb = buf ^ 1;
        *(uint4*)&As[nb][0][sidx] = nAh;
        *(uint4*)&As[nb][1][sidx] = nAl;
        *(uint4*)&Bs[nb][0][sidx] = nBh;
        *(uint4*)&Bs[nb][1][sidx] = nBl;
        __syncthreads();
        buf = nb;
    }

    #pragma unroll
    for (int mi = 0; mi < 2; mi++) {
        #pragma unroll
        for (int ni = 0; ni < 4; ni++) {
            int row = row0 + wm + mi*16 + lq;
            int col = col0 + wn + ni*8 + kq;
            float* d = acc[mi][ni];
            if (WHICH == 1) {
                C[(size_t)row*1024 + col]       = d[0];
                C[(size_t)row*1024 + col + 1]   = d[1];
                C[(size_t)(row+8)*1024 + col]   = d[2];
                C[(size_t)(row+8)*1024 + col+1] = d[3];
            } else {
                C[(size_t)row*1024 + col]       = 2.f*d[0] - xall[(size_t)row*1024 + col];
                C[(size_t)row*1024 + col + 1]   = 2.f*d[1] - xall[(size_t)row*1024 + col + 1];
                C[(size_t)(row+8)*1024 + col]   = 2.f*d[2] - xall[(size_t)(row+8)*1024 + col];
                C[(size_t)(row+8)*1024 + col+1] = 2.f*d[3] - xall[(size_t)(row+8)*1024 + col+1];
            }
        }
    }
}

// ---------------- bf16 hi/lo split (elementwise) ----------------
__global__ void bfsplit_k(const float* __restrict__ in, __nv_bfloat16* __restrict__ hi,
                          __nv_bfloat16* __restrict__ lo, int n)
{
    int g = blockIdx.x * 256 + threadIdx.x;
    if (g >= n) return;
    float v = in[g];
    __nv_bfloat16 h = __float2bfloat16(v);
    hi[g] = h;
    lo[g] = __float2bfloat16(v - __bfloat162float(h));
}

// ---------------- transpose + split: in fp32 [1024][1024] -> hi/lo [c][r] ----------
__global__ void tsplit_k(const float* __restrict__ in, __nv_bfloat16* __restrict__ hi,
                         __nv_bfloat16* __restrict__ lo)
{
    __shared__ float t[32][33];
    int r0 = blockIdx.y * 32, c0 = blockIdx.x * 32;
    int tx = threadIdx.x, ty = threadIdx.y;   // 32 x 8
    #pragma unroll
    for (int i = 0; i < 4; i++) {
        int r = ty + i*8;
        t[r][tx] = in[(size_t)(r0 + r)*1024 + c0 + tx];
    }
    __syncthreads();
    #pragma unroll
    for (int i = 0; i < 4; i++) {
        int c = ty + i*8;
        float v = t[tx][c];
        __nv_bfloat16 h = __float2bfloat16(v);
        size_t o = (size_t)(c0 + c)*1024 + r0 + tx;
        hi[o] = h;
        lo[o] = __float2bfloat16(v - __bfloat162float(h));
    }
}

// ---------------- x (B,N,D) -> XallT hi/lo [bd,node] bf16, tiled transpose ------
__global__ void xallT_k(const float* __restrict__ x, __nv_bfloat16* __restrict__ hi,
                        __nv_bfloat16* __restrict__ lo)
{
    __shared__ float t[64*33];
    int b = blockIdx.y, n0 = blockIdx.x * 32;
    int tid = threadIdx.x;
    for (int idx = tid; idx < 2048; idx += 256) {
        int ni = idx >> 6, c = idx & 63;
        t[c*33 + ni] = x[(size_t)b*65536 + (size_t)(n0 + ni)*64 + c];
    }
    __syncthreads();
    for (int idx = tid; idx < 2048; idx += 256) {
        int ni = idx & 31, c = idx >> 5;
        float v = t[c*33 + ni];
        __nv_bfloat16 h = __float2bfloat16(v);
        size_t o = (size_t)(b*64 + c)*1024 + n0 + ni;
        hi[o] = h;
        lo[o] = __float2bfloat16(v - __bfloat162float(h));
    }
}

// ---------------- causal conv (both directions) + silu (+ bf16 hi/lo out) --------
__global__ void conv_silu_k(const float* __restrict__ xz,
                            const float* __restrict__ cw0, const float* __restrict__ cb0,
                            const float* __restrict__ cw1, const float* __restrict__ cb1,
                            float* __restrict__ xc0, float* __restrict__ xc1,
                            __nv_bfloat16* __restrict__ xch, __nv_bfloat16* __restrict__ xcl)
{
    int dir = blockIdx.y;
    int g = blockIdx.x * 256 + threadIdx.x;
    int d = g & 127; int m = g >> 7; int l = m & 1023;
    const float* cw = dir ? cw1 : cw0;
    const float* cb = dir ? cb1 : cb0;
    const float* src = xz + dir * 256 + d;
    float acc = cb[d];
    #pragma unroll
    for (int k = 0; k < 4; k++) {
        int ll = dir ? (l + 3 - k) : (l - 3 + k);
        if (ll >= 0 && ll < 1024)
            acc = fmaf(src[(size_t)(m - l + ll) * 512], cw[d*4 + k], acc);
    }
    float v = silu_(acc);
    (dir ? xc1 : xc0)[g] = v;
    size_t o = (size_t)dir * 2097152 + g;
    __nv_bfloat16 hh = __float2bfloat16(v);
    xch[o] = hh;
    xcl[o] = __float2bfloat16(v - __bfloat162float(hh));
}

// ---------------- chunked selective scan: smem-staged, tile-prefetched ------------
// Pass 1: per-chunk local scan; coalesced tile loads (16 steps) into smem.
__global__ void __launch_bounds__(512) scan_p1(
    const float* __restrict__ dt0, const float* __restrict__ dt1,
    const float* __restrict__ xc0, const float* __restrict__ xc1,
    const float* __restrict__ B0,  const float* __restrict__ B1,
    const float* __restrict__ A0,  const float* __restrict__ A1,
    float* __restrict__ Hc, float* __restrict__ Ec)
{
    __shared__ float sdt[16][32], sxc[16][32], sB[16][16];
    int dir = blockIdx.z >> 4;
    int b   = blockIdx.z & 15;
    int c   = blockIdx.y;
    int t = threadIdx.x, s = t & 15, dl = t >> 4;
    int dbase = blockIdx.x * 32;
    int d = dbase + dl;
    const float* dt = (dir ? dt1 : dt0) + (size_t)b*131072 + dbase;
    const float* xc = (dir ? xc1 : xc0) + (size_t)b*131072 + dbase;
    const float* Bm = (dir ? B1 : B0)   + (size_t)b*16384;
    float Ads = (dir ? A1 : A0)[d*16 + s];
    int l0  = dir ? (1023 - c*CHLEN) : c*CHLEN;
    int stp = dir ? -1 : 1;

    int ltl = t >> 5, ldd = t & 31;      // dt/xc loader: one elem/thread
    int btl = t >> 4, bss = t & 15;      // B loader: threads < 256

    {   // preload tile 0
        int l = l0 + stp * ltl;
        sdt[ltl][ldd] = dt[(size_t)l*128 + ldd];
        sxc[ltl][ldd] = xc[(size_t)l*128 + ldd];
        if (t < 256) {
            int l2 = l0 + stp * btl;
            sB[btl][bss] = Bm[(size_t)l2*16 + bss];
        }
    }
    __syncthreads();

    float h = 0.f, sacc = 0.f;
    for (int j = 0; j < 8; j++) {
        float pdt = 0.f, pxc = 0.f, pB = 0.f;
        if (j < 7) {
            int l = l0 + stp * ((j+1)*16 + ltl);
            pdt = dt[(size_t)l*128 + ldd];
            pxc = xc[(size_t)l*128 + ldd];
            if (t < 256) {
                int l2 = l0 + stp * ((j+1)*16 + btl);
                pB = Bm[(size_t)l2*16 + bss];
            }
        }
        #pragma unroll
        for (int tl = 0; tl < 16; tl++) {
            float dtv = sdt[tl][dl];
            float xcv = sxc[tl][dl];
            float Bv  = sB[tl][s];
            float e = __expf(dtv * Ads);
            h = fmaf(h, e, dtv * Bv * xcv);
            sacc += dtv;
        }
        __syncthreads();
        if (j < 7) {
            sdt[ltl][ldd] = pdt;
            sxc[ltl][ldd] = pxc;
            if (t < 256) sB[btl][bss] = pB;
        }
        __syncthreads();
    }
    size_t idx = ((((size_t)dir*16 + b)*NCHUNK + c)*128 + d)*16 + s;
    Hc[idx] = h;
    Ec[idx] = __expf(Ads * sacc);
}

__global__ void scan_comb(const float* __restrict__ Hc, const float* __restrict__ Ec,
                          float* __restrict__ h0arr)
{
    int g = blockIdx.x * 256 + threadIdx.x;
    int s = g & 15; int d = (g >> 4) & 127; int bb = g >> 11;
    float carry = 0.f;
    #pragma unroll
    for (int c = 0; c < NCHUNK; c++) {
        size_t idx = (((size_t)bb*NCHUNK + c)*128 + d)*16 + s;
        h0arr[idx] = carry;
        carry = fmaf(carry, Ec[idx], Hc[idx]);
    }
}

// Pass 2: replay from correct initial state; smem-staged loads, staged y writes.
__global__ void __launch_bounds__(512) scan_p2(
    const float* __restrict__ dt0, const float* __restrict__ dt1,
    const float* __restrict__ xc0, const float* __restrict__ xc1,
    const float* __restrict__ B0,  const float* __restrict__ B1,
    const float* __restrict__ C0,  const float* __restrict__ C1,
    const float* __restrict__ xz,
    const float* __restrict__ A0,  const float* __restrict__ A1,
    const float* __restrict__ D0,  const float* __restrict__ D1,
    const float* __restrict__ h0arr, float* __restrict__ ycat)
{
    __shared__ float sdt[16][32], sxc[16][32], sz[16][32], sB[16][16], sC[16][16];
    __shared__ float sy[16][32];
    int dir = blockIdx.z >> 4;
    int b   = blockIdx.z & 15;
    int c   = blockIdx.y;
    int t = threadIdx.x, s = t & 15, dl = t >> 4;
    int dbase = blockIdx.x * 32;
    int d = dbase + dl;
    const float* dt = (dir ? dt1 : dt0) + (size_t)b*131072 + dbase;
    const float* xc = (dir ? xc1 : xc0) + (size_t)b*131072 + dbase;
    const float* Bm = (dir ? B1 : B0)   + (size_t)b*16384;
    const float* Cm = (dir ? C1 : C0)   + (size_t)b*16384;
    const float* zb = xz + (size_t)b*524288 + dir*256 + 128 + dbase;
    float* yb       = ycat + (size_t)b*262144 + dir*128 + dbase;
    float Ads = (dir ? A1 : A0)[d*16 + s];
    float Dpd = (dir ? D1 : D0)[d];
    int l0  = dir ? (1023 - c*CHLEN) : c*CHLEN;
    int stp = dir ? -1 : 1;

    int ltl = t >> 5, ldd = t & 31;
    int btl = t >> 4, bss = t & 15;

    {   // preload tile 0
        int l = l0 + stp * ltl;
        sdt[ltl][ldd] = dt[(size_t)l*128 + ldd];
        sxc[ltl][ldd] = xc[(size_t)l*128 + ldd];
        sz[ltl][ldd]  = zb[(size_t)l*512 + ldd];
        if (t < 256) {
            int l2 = l0 + stp * btl;
            sB[btl][bss] = Bm[(size_t)l2*16 + bss];
            sC[btl][bss] = Cm[(size_t)l2*16 + bss];
        }
    }
    __syncthreads();

    size_t idx = ((((size_t)dir*16 + b)*NCHUNK + c)*128 + d)*16 + s;
    float h = h0arr[idx];

    for (int j = 0; j < 8; j++) {
        float pdt = 0.f, pxc = 0.f, pz = 0.f, pB = 0.f, pC = 0.f;
        if (j < 7) {
            int l = l0 + stp * ((j+1)*16 + ltl);
            pdt = dt[(size_t)l*128 + ldd];
            pxc = xc[(size_t)l*128 + ldd];
            pz  = zb[(size_t)l*512 + ldd];
            if (t < 256) {
                int l2 = l0 + stp * ((j+1)*16 + btl);
                pB = Bm[(size_t)l2*16 + bss];
                pC = Cm[(size_t)l2*16 + bss];
            }
        }
        #pragma unroll
        for (int tl = 0; tl < 16; tl++) {
            float dtv = sdt[tl][dl];
            float xcv = sxc[tl][dl];
            float Bv  = sB[tl][s];
            float Cv  = sC[tl][s];
            float e = __expf(dtv * Ads);
            h = fmaf(h, e, dtv * Bv * xcv);
            float part = h * Cv;
            part += __shfl_xor_sync(0xffffffffu, part, 8);
            part += __shfl_xor_sync(0xffffffffu, part, 4);
            part += __shfl_xor_sync(0xffffffffu, part, 2);
            part += __shfl_xor_sync(0xffffffffu, part, 1);
            if (s == 0)
                sy[tl][dl] = (part + Dpd * xcv) * silu_(sz[tl][dl]);
        }
        __syncthreads();
        {   // coalesced y write for this tile
            int l = l0 + stp * (j*16 + ltl);
            yb[(size_t)l*256 + ldd] = sy[ltl][ldd];
        }
        if (j < 7) {
            sdt[ltl][ldd] = pdt;
            sxc[ltl][ldd] = pxc;
            sz[ltl][ldd]  = pz;
            if (t < 256) { sB[btl][bss] = pB; sC[btl][bss] = pC; }
        }
        __syncthreads();
    }
}

// ---------------- support matrix: softmax(relu(E E^T)) ----------------
__global__ void __launch_bounds__(256) sup_k(const float* __restrict__ emb, float* __restrict__ sup)
{
    __shared__ float se[NNODE * EDIM];
    __shared__ float red[256];
    int n = blockIdx.x, tid = threadIdx.x;
    for (int i = tid; i < NNODE*EDIM; i += 256) se[i] = emb[i];
    __syncthreads();
    float en[EDIM];
    #pragma unroll
    for (int e = 0; e < EDIM; e++) en[e] = se[n*EDIM + e];
    float vals[4]; float mx = -1e30f;
    #pragma unroll
    for (int jj = 0; jj < 4; jj++) {
        int j = jj*256 + tid;
        float v = 0.f;
        #pragma unroll
        for (int e = 0; e < EDIM; e++) v = fmaf(en[e], se[j*EDIM + e], v);
        v = v > 0.f ? v : 0.f;
        vals[jj] = v; mx = fmaxf(mx, v);
    }
    red[tid] = mx; __syncthreads();
    for (int o = 128; o > 0; o >>= 1) { if (tid < o) red[tid] = fmaxf(red[tid], red[tid+o]); __syncthreads(); }
    mx = red[0]; __syncthreads();
    float s = 0.f;
    #pragma unroll
    for (int jj = 0; jj < 4; jj++) { vals[jj] = __expf(vals[jj] - mx); s += vals[jj]; }
    red[tid] = s; __syncthreads();
    for (int o = 128; o > 0; o >>= 1) { if (tid < o) red[tid] += red[tid+o]; __syncthreads(); }
    float inv = 1.f / red[0];
    #pragma unroll
    for (int jj = 0; jj < 4; jj++) sup[(size_t)n*1024 + jj*256 + tid] = vals[jj] * inv;
}

// ---------------- x (B,N,D) -> Xall (N, B*D) fp32 ----------------
__global__ void xall_k(const float* __restrict__ x, float* __restrict__ xall)
{
    int g = blockIdx.x * 256 + threadIdx.x;
    int c = g & 63, n = (g >> 6) & 1023, b = g >> 16;
    xall[(size_t)n*1024 + b*64 + c] = x[g];
}

// ---------------- W[n,k,c,o] = sum_e emb[n,e] W_pool[e,k,c,o] ----------------
__global__ void wmix_k(const float* __restrict__ emb, const float* __restrict__ wp,
                       float* __restrict__ W)
{
    int n = blockIdx.y;
    int j = blockIdx.x * 256 + threadIdx.x;
    float acc = 0.f;
    #pragma unroll
    for (int e = 0; e < EDIM; e++) acc = fmaf(emb[n*EDIM + e], wp[(size_t)e*12288 + j], acc);
    W[(size_t)n*12288 + j] = acc;
}

// ---------------- per-node graph conv ----------------
__global__ void __launch_bounds__(256) gconv_k(
    const float* __restrict__ x,  const float* __restrict__ xg1,
    const float* __restrict__ xg2, const float* __restrict__ W,
    const float* __restrict__ emb, const float* __restrict__ bp,
    float* __restrict__ go)
{
    __shared__ float xs[3072];
    __shared__ float bs[64];
    int n = blockIdx.x, tid = threadIdx.x;
    const float* Wn = W + (size_t)n * 12288;
    for (int i = tid; i < 3072; i += 256) {
        int k = i >> 10; int rem = i & 1023; int b = rem >> 6; int c = rem & 63;
        float v;
        if (k == 0) v = x[(size_t)b*65536 + (size_t)n*64 + c];
        else        v = (k == 1 ? xg1 : xg2)[(size_t)n*1024 + b*64 + c];
        xs[i] = v;
    }
    if (tid < 64) {
        float a = 0.f;
        #pragma unroll
        for (int e = 0; e < EDIM; e++) a = fmaf(emb[n*EDIM + e], bp[e*64 + tid], a);
        bs[tid] = a;
    }
    __syncthreads();
    int o = tid & 63, bq = tid >> 6;
    float acc[4];
    #pragma unroll
    for (int q = 0; q < 4; q++) acc[q] = bs[o];
    #pragma unroll 4
    for (int kc = 0; kc < 192; kc++) {
        float w = __ldg(Wn + kc*64 + o);
        int k = kc >> 6, c = kc & 63;
        #pragma unroll
        for (int q = 0; q < 4; q++)
            acc[q] = fmaf(xs[(k*16 + bq + q*4)*64 + c], w, acc[q]);
    }
    #pragma unroll
    for (int q = 0; q < 4; q++) {
        int b = bq + q*4;
        go[(size_t)b*65536 + (size_t)n*64 + o] = acc[q];
    }
}

// ---------------- launch ----------------
extern "C" void kernel_launch(void* const* d_in, const int* in_sizes, int n_in,
                              void* d_out, int out_size)
{
    const float* x_in     = (const float*)d_in[0];
    const float* fw_in    = (const float*)d_in[1];
    const float* fw_cw    = (const float*)d_in[2];
    const float* fw_cb    = (const float*)d_in[3];
    const float* fw_xp    = (const float*)d_in[4];
    const float* fw_dtw   = (const float*)d_in[5];
    const float* fw_dtb   = (const float*)d_in[6];
    const float* fw_Alog  = (const float*)d_in[7];
    const float* fw_D     = (const float*)d_in[8];
    const float* fw_out   = (const float*)d_in[9];
    const float* bw_in    = (const float*)d_in[10];
    const float* bw_cw    = (const float*)d_in[11];
    const float* bw_cb    = (const float*)d_in[12];
    const float* bw_xp    = (const float*)d_in[13];
    const float* bw_dtw   = (const float*)d_in[14];
    const float* bw_dtb   = (const float*)d_in[15];
    const float* bw_Alog  = (const float*)d_in[16];
    const float* bw_D     = (const float*)d_in[17];
    const float* bw_out   = (const float*)d_in[18];
    const float* ln1_g    = (const float*)d_in[19];
    const float* ln1_b    = (const float*)d_in[20];
    const float* ffn_w1   = (const float*)d_in[21];
    const float* ffn_b1   = (const float*)d_in[22];
    const float* ffn_w2   = (const float*)d_in[23];
    const float* ffn_b2   = (const float*)d_in[24];
    const float* ln2_g    = (const float*)d_in[25];
    const float* ln2_b    = (const float*)d_in[26];
    const float* node_emb = (const float*)d_in[27];
    const float* W_pool   = (const float*)d_in[28];
    const float* b_pool   = (const float*)d_in[29];
    const float* proj_w   = (const float*)d_in[30];
    const float* proj_b   = (const float*)d_in[31];
    float* outp = (float*)d_out;

    float* S = nullptr;
    cudaGetSymbolAddress((void**)&S, g_scratch);

    float* Wcat   = S;
    float* A0     = S + 73728;
    float* A1     = S + 75776;
    float* xz     = S + 77824;
    float* xc0    = S + 8466432;
    float* xc1    = S + 10563584;
    float* dt0    = S + 12660736;
    float* dt1    = S + 14757888;
    float* Bm0    = S + 16855040;
    float* Bm1    = S + 17117184;
    float* Cm0    = S + 17379328;
    float* Cm1    = S + 17641472;
    float* ycat   = S + 17903616;
    float* xbuf   = S + 22097920;
    float* xln    = S + 23146496;
    float* xall   = S + 24195072;
    float* hbuf   = S + 25243648;
    float* sup    = S + 29437952;
    float* xg1    = S + 31535104;
    float* xg2    = S + 32583680;
    float* Wbig   = S + 33632256;
    float* go     = S + 46215168;
    float* Wocat  = S + 47263744;
    float* Hc     = S + 47280128;
    float* Ec     = S + 47804416;
    float* h0arr  = S + 48328704;
    __nv_bfloat16* sup_hi  = (__nv_bfloat16*)(S + 48852992);
    __nv_bfloat16* sup_lo  = (__nv_bfloat16*)(S + 49377280);
    __nv_bfloat16* xaT_hi  = (__nv_bfloat16*)(S + 49901568);
    __nv_bfloat16* xaT_lo  = (__nv_bfloat16*)(S + 50425856);
    __nv_bfloat16* xg1t_hi = (__nv_bfloat16*)(S + 50950144);
    __nv_bfloat16* xg1t_lo = (__nv_bfloat16*)(S + 51474432);
    __nv_bfloat16* wc0Th   = (__nv_bfloat16*)(S + 52031488);
    __nv_bfloat16* wc0Tl   = (__nv_bfloat16*)(S + 52041728);
    __nv_bfloat16* wc1Th   = (__nv_bfloat16*)(S + 52051968);
    __nv_bfloat16* wc1Tl   = (__nv_bfloat16*)(S + 52062208);
    __nv_bfloat16* xch     = (__nv_bfloat16*)(S + 53121024);
    __nv_bfloat16* xcl     = (__nv_bfloat16*)(S + 55218176);

    // prep
    {
        int total = 32768 + 40960 + 4096 + 16384 + MROWS*DMODEL;
        prep_k<<<(total + 255)/256, 256>>>(fw_in, bw_in, fw_xp, fw_dtw, bw_xp, bw_dtw,
                                           fw_Alog, bw_Alog, fw_out, bw_out, x_in,
                                           Wcat, wc0Th, wc0Tl, wc1Th, wc1Tl,
                                           A0, A1, Wocat, xbuf);
    }

    for (int layer = 0; layer < 2; layer++) {
        // xz = x @ [fw_in | bw_in]  (fp32 engine — better for K=64)
        sgemm_k<0,0><<<dim3(8, 256), 256>>>(xbuf, Wcat, xz, MROWS, 512, 64,
                                            nullptr, nullptr, nullptr, nullptr, nullptr, nullptr);
        // conv + silu, both dirs (+ bf16 hi/lo for xproj tensor GEMM)
        conv_silu_k<<<dim3((MROWS*128)/256, 2), 256>>>(xz, fw_cw, fw_cb, bw_cw, bw_cb,
                                                       xc0, xc1, xch, xcl);
        // xproj both dirs in ONE tensor-core launch (M=32768, N=160(pad 192), K=128)
        tcg_k<1,1><<<dim3(3, 512), 128>>>(xch, xcl, wc0Th, wc0Tl, wc1Th, wc1Tl,
                                          dt0, 2*MROWS, 160, 128,
                                          fw_dtb, bw_dtb, Bm0, Cm0);
        // chunked selective scan (smem-staged)
        scan_p1<<<dim3(4, NCHUNK, 32), 512>>>(dt0, dt1, xc0, xc1, Bm0, Bm1, A0, A1, Hc, Ec);
        scan_comb<<<256, 256>>>(Hc, Ec, h0arr);
        scan_p2<<<dim3(4, NCHUNK, 32), 512>>>(dt0, dt1, xc0, xc1, Bm0, Bm1, Cm0, Cm1,
                                              xz, A0, A1, fw_D, bw_D, h0arr, ycat);
        // x + [yf|yb]@Wocat, fused LN1 -> xln
        sgemm_k<7,0><<<dim3(1, 256), 256>>>(ycat, Wocat, xln, MROWS, 64, 256,
                                            xbuf, nullptr, (float*)ln1_g, (float*)ln1_b,
                                            nullptr, nullptr);
        // FFN1: relu(xln@W1 + b1)
        sgemm_k<2,0><<<dim3(4, 256), 256>>>(xln, ffn_w1, hbuf, MROWS, 256, 64,
                                            ffn_b1, nullptr, nullptr, nullptr, nullptr, nullptr);
        // FFN2 + residual + b2, fused LN2 -> xbuf
        sgemm_k<8,0><<<dim3(1, 256), 256>>>(hbuf, ffn_w2, xbuf, MROWS, 64, 256,
                                            xln, ffn_b2, (float*)ln2_g, (float*)ln2_b,
                                            nullptr, nullptr);
    }

    // graph part
    sup_k<<<NNODE, 256>>>(node_emb, sup);
    bfsplit_k<<<4096, 256>>>(sup, sup_hi, sup_lo, NNODE*NNODE);
    xall_k<<<4096, 256>>>(xbuf, xall);
    xallT_k<<<dim3(32, 16), 256>>>(xbuf, xaT_hi, xaT_lo);

    // XG1 = sup @ Xall  (tensor cores, split bf16)
    tcmma_k<1><<<dim3(16, 16), 128>>>(sup_hi, sup_lo, xaT_hi, xaT_lo, xg1, nullptr);
    tsplit_k<<<dim3(32, 32), dim3(32, 8)>>>(xg1, xg1t_hi, xg1t_lo);
    // XG2 = 2*sup@XG1 - Xall
    tcmma_k<2><<<dim3(16, 16), 128>>>(sup_hi, sup_lo, xg1t_hi, xg1t_lo, xg2, xall);

    wmix_k<<<dim3(48, 1024), 256>>>(node_emb, W_pool, Wbig);
    gconv_k<<<NNODE, 256>>>(xbuf, xg1, xg2, Wbig, node_emb, b_pool, go);
    sgemm_k<6,0><<<dim3(2, 256), 256>>>(go, proj_w, outp, MROWS, 96, 64,
                                        proj_b, nullptr, nullptr, nullptr, nullptr, nullptr);
}

// round 16
// speedup vs baseline: 1.4086x; 1.0043x over previous
#include <cuda_runtime.h>
#include <cuda_bf16.h>
#include <math.h>

// ---------------- problem constants ----------------
#define BATCH   16
#define LSEQ    1024
#define DMODEL  64
#define DINNER  128
#define SSTATE  16
#define MROWS   (BATCH*LSEQ)   // 16384
#define HFFN    256
#define NNODE   1024
#define EDIM    10
#define PLOUT   96
#define NCHUNK  8
#define CHLEN   128

// ---------------- scratch (single static device buffer) ----------------
__device__ float g_scratch[57315328];

__device__ __forceinline__ float silu_(float x) { return x / (1.f + __expf(-x)); }

// ---------------- prep ------------------------------------------------------------
__global__ void prep_k(const float* __restrict__ fw_in, const float* __restrict__ bw_in,
                       const float* __restrict__ fwx, const float* __restrict__ fwdt,
                       const float* __restrict__ bwx, const float* __restrict__ bwdt,
                       const float* __restrict__ fwA, const float* __restrict__ bwA,
                       const float* __restrict__ fw_out, const float* __restrict__ bw_out,
                       const float* __restrict__ ffn_w2,
                       const float* __restrict__ x_in,
                       float* __restrict__ Wcat,
                       __nv_bfloat16* __restrict__ wc0Th, __nv_bfloat16* __restrict__ wc0Tl,
                       __nv_bfloat16* __restrict__ wc1Th, __nv_bfloat16* __restrict__ wc1Tl,
                       float* __restrict__ A0, float* __restrict__ A1,
                       __nv_bfloat16* __restrict__ wocaTh, __nv_bfloat16* __restrict__ wocaTl,
                       __nv_bfloat16* __restrict__ w2Th, __nv_bfloat16* __restrict__ w2Tl,
                       float* __restrict__ xbuf)
{
    int g = blockIdx.x * 256 + threadIdx.x;
    if (g < 32768) {  // Wcat (64,512) fp32
        int k = g >> 9, j = g & 511;
        Wcat[g] = (j < 256) ? fw_in[k*256 + j] : bw_in[k*256 + (j-256)];
        return;
    }
    int h = g - 32768;
    if (h < 40960) {  // WcombT per dir: [160][128] bf16 hi/lo
        int dir = h / 20480; int r2 = h % 20480;
        int j = r2 >> 7, i = r2 & 127;
        const float* Wx  = dir ? bwx  : fwx;
        const float* Wdt = dir ? bwdt : fwdt;
        float v;
        if (j < 128) {
            v = 0.f;
            #pragma unroll
            for (int r = 0; r < 4; r++) v = fmaf(Wx[i*36 + r], Wdt[r*128 + j], v);
        } else {
            v = Wx[i*36 + 4 + (j - 128)];
        }
        __nv_bfloat16 hh = __float2bfloat16(v);
        __nv_bfloat16 ll = __float2bfloat16(v - __bfloat162float(hh));
        if (dir) { wc1Th[j*128 + i] = hh; wc1Tl[j*128 + i] = ll; }
        else     { wc0Th[j*128 + i] = hh; wc0Tl[j*128 + i] = ll; }
        return;
    }
    h -= 40960;
    if (h < 4096) {  // A
        int dir = h >> 11; int i = h & 2047;
        (dir ? A1 : A0)[i] = -__expf((dir ? bwA : fwA)[i]);
        return;
    }
    h -= 4096;
    if (h < 16384) {  // WocatT [64][256] bf16 hi/lo (transposed concat out weights)
        int c = h >> 8, k = h & 255;
        float v = (k < 128) ? fw_out[k*64 + c] : bw_out[(k-128)*64 + c];
        __nv_bfloat16 hh = __float2bfloat16(v);
        wocaTh[c*256 + k] = hh;
        wocaTl[c*256 + k] = __float2bfloat16(v - __bfloat162float(hh));
        return;
    }
    h -= 16384;
    if (h < 16384) {  // ffn_w2T [64][256] bf16 hi/lo
        int o = h >> 8, k = h & 255;
        float v = ffn_w2[k*64 + o];
        __nv_bfloat16 hh = __float2bfloat16(v);
        w2Th[o*256 + k] = hh;
        w2Tl[o*256 + k] = __float2bfloat16(v - __bfloat162float(hh));
        return;
    }
    h -= 16384;
    if (h < MROWS*DMODEL) xbuf[h] = x_in[h];
}

// ---------------- generic tiled SGEMM, 64x64 tiles, double-buffered (fp32) --------
// EPI: 0 store, 2 bias+relu -> bf16 hi/lo only, 6 +aux0(col)
template<int EPI, int SPLIT>
__global__ void __launch_bounds__(256) sgemm_k(
    const float* __restrict__ A, const float* __restrict__ B, float* __restrict__ C,
    int M, int N, int K,
    const float* __restrict__ aux0, const float* __restrict__ aux1,
    float* __restrict__ o1, float* __restrict__ o2,
    const float* __restrict__ B2, const float* __restrict__ aux0b,
    __nv_bfloat16* __restrict__ ohi, __nv_bfloat16* __restrict__ olo)
{
    __shared__ float As[2][16][64];
    __shared__ float Bs[2][16][64];
    int row0 = blockIdx.y * 64, col0 = blockIdx.x * 64;
    if (SPLIT && row0 >= (M >> 1)) { B = B2; aux0 = aux0b; }
    int tid = threadIdx.x;
    int tx = tid & 15, ty = tid >> 4;
    int a_m = tid >> 2, a_k = (tid & 3) * 4;
    int b_k = tid >> 4, b_n = (tid & 15) * 4;
    const float* Aptr = A + (size_t)(row0 + a_m) * K + a_k;
    int bc = col0 + b_n;
    bool bok = bc < N;
    const float* Bptr = B + (size_t)b_k * N + bc;

    float acc[4][4];
    #pragma unroll
    for (int i = 0; i < 4; i++)
        #pragma unroll
        for (int j = 0; j < 4; j++) acc[i][j] = 0.f;

    {
        float4 av = *(const float4*)(Aptr);
        float4 bv = bok ? *(const float4*)(Bptr) : make_float4(0.f,0.f,0.f,0.f);
        As[0][a_k+0][a_m] = av.x; As[0][a_k+1][a_m] = av.y;
        As[0][a_k+2][a_m] = av.z; As[0][a_k+3][a_m] = av.w;
        *(float4*)&Bs[0][b_k][b_n] = bv;
    }
    __syncthreads();

    int buf = 0;
    for (int k0 = 16; ; k0 += 16) {
        bool has = (k0 < K);
        float4 av2, bv2;
        if (has) {
            av2 = *(const float4*)(Aptr + k0);
            bv2 = bok ? *(const float4*)(Bptr + (size_t)k0 * N) : make_float4(0.f,0.f,0.f,0.f);
        }
        #pragma unroll
        for (int kk = 0; kk < 16; kk++) {
            float am[4], bn[4];
            *(float4*)am = *(const float4*)&As[buf][kk][ty*4];
            *(float4*)bn = *(const float4*)&Bs[buf][kk][tx*4];
            #pragma unroll
            for (int i = 0; i < 4; i++)
                #pragma unroll
                for (int j = 0; j < 4; j++)
                    acc[i][j] = fmaf(am[i], bn[j], acc[i][j]);
        }
        if (!has) break;
        int nb = buf ^ 1;
        As[nb][a_k+0][a_m] = av2.x; As[nb][a_k+1][a_m] = av2.y;
        As[nb][a_k+2][a_m] = av2.z; As[nb][a_k+3][a_m] = av2.w;
        *(float4*)&Bs[nb][b_k][b_n] = bv2;
        __syncthreads();
        buf = nb;
    }

    #pragma unroll
    for (int i = 0; i < 4; i++) {
        int row = row0 + ty*4 + i;
        #pragma unroll
        for (int j = 0; j < 4; j++) {
            int col = col0 + tx*4 + j;
            if (col >= N) continue;
            float v = acc[i][j];
            size_t idx = (size_t)row * N + col;
            if (EPI == 0) {
                C[idx] = v;
            } else if (EPI == 2) {
                float t = v + aux0[col];
                t = t > 0.f ? t : 0.f;
                __nv_bfloat16 hh = __float2bfloat16(t);
                ohi[idx] = hh;
                olo[idx] = __float2bfloat16(t - __bfloat162float(hh));
            } else if (EPI == 6) {
                C[idx] = v + aux0[col];
            }
        }
    }
}

// ================= generalized bf16 split GEMM via mma.sync =================
// EPI 1: xproj split epilogue (SPLIT selects dir weights/bias).
// EPI 2: +res(full) then LN(o1,o2)              [Nact==64, grid.x==1]
// EPI 3: +res(full)+bias(col) then LN(o1,o2)    [Nact==64, grid.x==1]
#define MMA_BF16(d, A0, A1, A2, A3, Bb0, Bb1) \
    asm volatile("mma.sync.aligned.m16n8k16.row.col.f32.bf16.bf16.f32 " \
                 "{%0,%1,%2,%3}, {%4,%5,%6,%7}, {%8,%9}, {%0,%1,%2,%3};" \
                 : "+f"((d)[0]), "+f"((d)[1]), "+f"((d)[2]), "+f"((d)[3]) \
                 : "r"(A0), "r"(A1), "r"(A2), "r"(A3), "r"(Bb0), "r"(Bb1))

template<int EPI, int SPLIT>
__global__ void __launch_bounds__(128) tcg_k(
    const __nv_bfloat16* __restrict__ Ahi, const __nv_bfloat16* __restrict__ Alo,
    const __nv_bfloat16* __restrict__ Bhi, const __nv_bfloat16* __restrict__ Blo,
    const __nv_bfloat16* __restrict__ B2hi, const __nv_bfloat16* __restrict__ B2lo,
    float* __restrict__ C, int M, int Nact, int K,
    const float* __restrict__ aux0, const float* __restrict__ aux0b,
    float* __restrict__ o1, float* __restrict__ o2,
    const float* __restrict__ bias)
{
    __shared__ __align__(16) __nv_bfloat16 As[2][2][64*16];
    __shared__ __align__(16) __nv_bfloat16 Bs[2][2][64*16];
    int tid = threadIdx.x, lane = tid & 31, warp = tid >> 5;
    int row0 = blockIdx.y * 64, col0 = blockIdx.x * 64;
    if (SPLIT && row0 >= (M >> 1)) { Bhi = B2hi; Blo = B2lo; aux0 = aux0b; }
    int wm = (warp & 1) * 32, wn = (warp >> 1) * 32;
    int lq = lane >> 2, kq = (lane & 3) * 2;

    float acc[2][4][4];
    #pragma unroll
    for (int mi = 0; mi < 2; mi++)
        #pragma unroll
        for (int ni = 0; ni < 4; ni++)
            #pragma unroll
            for (int q = 0; q < 4; q++) acc[mi][ni][q] = 0.f;

    int lr = tid >> 1, lseg = (tid & 1) * 8;
    const __nv_bfloat16* gAh = Ahi + (size_t)(row0 + lr)*K + lseg;
    const __nv_bfloat16* gAl = Alo + (size_t)(row0 + lr)*K + lseg;
    bool bok = (col0 + lr) < Nact;
    const __nv_bfloat16* gBh = Bhi + (size_t)(col0 + lr)*K + lseg;
    const __nv_bfloat16* gBl = Blo + (size_t)(col0 + lr)*K + lseg;
    int sidx = lr * 16 + lseg;
    uint4 z4 = make_uint4(0,0,0,0);

    *(uint4*)&As[0][0][sidx] = *(const uint4*)(gAh);
    *(uint4*)&As[0][1][sidx] = *(const uint4*)(gAl);
    *(uint4*)&Bs[0][0][sidx] = bok ? *(const uint4*)(gBh) : z4;
    *(uint4*)&Bs[0][1][sidx] = bok ? *(const uint4*)(gBl) : z4;
    __syncthreads();

    int nkc = K >> 4;
    int buf = 0;
    for (int kc = 1; ; kc++) {
        bool has = (kc < nkc);
        uint4 nAh, nAl, nBh = z4, nBl = z4;
        if (has) {
            int k0 = kc * 16;
            nAh = *(const uint4*)(gAh + k0);
            nAl = *(const uint4*)(gAl + k0);
            if (bok) { nBh = *(const uint4*)(gBh + k0); nBl = *(const uint4*)(gBl + k0); }
        }
        {
            const __nv_bfloat16* ah = As[buf][0];
            const __nv_bfloat16* al = As[buf][1];
            const __nv_bfloat16* bh = Bs[buf][0];
            const __nv_bfloat16* bl = Bs[buf][1];
            unsigned bfh[4][2], bfl[4][2];
            #pragma unroll
            for (int ni = 0; ni < 4; ni++) {
                int cb = (wn + ni*8 + lq) * 16;
                bfh[ni][0] = *(const unsigned*)(bh + cb + kq);
                bfh[ni][1] = *(const unsigned*)(bh + cb + kq + 8);
                bfl[ni][0] = *(const unsigned*)(bl + cb + kq);
                bfl[ni][1] = *(const unsigned*)(bl + cb + kq + 8);
            }
            #pragma unroll
            for (int mi = 0; mi < 2; mi++) {
                int rb = (wm + mi*16 + lq) * 16;
                unsigned ah0 = *(const unsigned*)(ah + rb + kq);
                unsigned ah1 = *(const unsigned*)(ah + rb + 128 + kq);
                unsigned ah2 = *(const unsigned*)(ah + rb + kq + 8);
                unsigned ah3 = *(const unsigned*)(ah + rb + 128 + kq + 8);
                unsigned al0 = *(const unsigned*)(al + rb + kq);
                unsigned al1 = *(const unsigned*)(al + rb + 128 + kq);
                unsigned al2 = *(const unsigned*)(al + rb + kq + 8);
                unsigned al3 = *(const unsigned*)(al + rb + 128 + kq + 8);
                #pragma unroll
                for (int ni = 0; ni < 4; ni++) {
                    MMA_BF16(acc[mi][ni], ah0, ah1, ah2, ah3, bfh[ni][0], bfh[ni][1]);
                    MMA_BF16(acc[mi][ni], ah0, ah1, ah2, ah3, bfl[ni][0], bfl[ni][1]);
                    MMA_BF16(acc[mi][ni], al0, al1, al2, al3, bfh[ni][0], bfh[ni][1]);
                }
            }
        }
        if (!has) break;
        int nb = buf ^ 1;
        *(uint4*)&As[nb][0][sidx] = nAh;
        *(uint4*)&As[nb][1][sidx] = nAl;
        *(uint4*)&Bs[nb][0][sidx] = nBh;
        *(uint4*)&Bs[nb][1][sidx] = nBl;
        __syncthreads();
        buf = nb;
    }

    if (EPI == 2 || EPI == 3) {
        // residual(+bias) -> smem tile -> row LayerNorm (Nact==64, 1 block per 64 rows)
        __shared__ float xt[64][65];
        __shared__ float red[64][2][2];
        #pragma unroll
        for (int mi = 0; mi < 2; mi++) {
            #pragma unroll
            for (int ni = 0; ni < 4; ni++) {
                #pragma unroll
                for (int q = 0; q < 4; q++) {
                    int rl = wm + mi*16 + lq + (q >> 1)*8;
                    int c  = wn + ni*8 + kq + (q & 1);
                    float v = acc[mi][ni][q] + aux0[(size_t)(row0 + rl)*64 + c];
                    if (EPI == 3) v += bias[c];
                    xt[rl][c] = v;
                }
            }
        }
        __syncthreads();
        int r = tid >> 1, half = tid & 1;
        float sm = 0.f, sq = 0.f;
        #pragma unroll
        for (int j = 0; j < 32; j++) {
            float v = xt[r][half*32 + j];
            sm += v; sq += v*v;
        }
        red[r][half][0] = sm; red[r][half][1] = sq;
        __syncthreads();
        sm = red[r][0][0] + red[r][1][0];
        sq = red[r][0][1] + red[r][1][1];
        float mean = sm * (1.f/64.f);
        float var  = sq * (1.f/64.f) - mean*mean;
        float rs = rsqrtf(var + 1e-5f);
        int row = row0 + r;
        #pragma unroll
        for (int j = 0; j < 32; j++) {
            int col = half*32 + j;
            C[(size_t)row*64 + col] = (xt[r][col] - mean) * rs * o1[col] + o2[col];
        }
        return;
    }

    #pragma unroll
    for (int mi = 0; mi < 2; mi++) {
        #pragma unroll
        for (int ni = 0; ni < 4; ni++) {
            int row = row0 + wm + mi*16 + lq;
            int col = col0 + wn + ni*8 + kq;
            float* d = acc[mi][ni];
            #pragma unroll
            for (int q = 0; q < 4; q++) {
                int r = row + (q >> 1) * 8;
                int c = col + (q & 1);
                float v = d[q];
                if (c < 128) {
                    float t = v + aux0[c];
                    C[(size_t)r*128 + c] = (t > 20.f) ? t : log1pf(__expf(t));
                } else if (c < 144) {
                    o1[(size_t)r*16 + (c - 128)] = v;
                } else if (c < 160) {
                    o2[(size_t)r*16 + (c - 144)] = v;
                }
            }
        }
    }
}

// ================= bf16 split GEMM for graph (fixed 1024^3) =================
template<int WHICH>
__global__ void __launch_bounds__(128) tcmma_k(
    const __nv_bfloat16* __restrict__ Ahi, const __nv_bfloat16* __restrict__ Alo,
    const __nv_bfloat16* __restrict__ Bhi, const __nv_bfloat16* __restrict__ Blo,
    float* __restrict__ C, const float* __restrict__ xall)
{
    __shared__ __align__(16) __nv_bfloat16 As[2][2][64*16];
    __shared__ __align__(16) __nv_bfloat16 Bs[2][2][64*16];
    int tid = threadIdx.x, lane = tid & 31, warp = tid >> 5;
    int row0 = blockIdx.y * 64, col0 = blockIdx.x * 64;
    int wm = (warp & 1) * 32, wn = (warp >> 1) * 32;
    int lq = lane >> 2, kq = (lane & 3) * 2;

    float acc[2][4][4];
    #pragma unroll
    for (int mi = 0; mi < 2; mi++)
        #pragma unroll
        for (int ni = 0; ni < 4; ni++)
            #pragma unroll
            for (int q = 0; q < 4; q++) acc[mi][ni][q] = 0.f;

    int lr = tid >> 1, lseg = (tid & 1) * 8;
    const __nv_bfloat16* gAh = Ahi + (size_t)(row0 + lr)*1024 + lseg;
    const __nv_bfloat16* gAl = Alo + (size_t)(row0 + lr)*1024 + lseg;
    const __nv_bfloat16* gBh = Bhi + (size_t)(col0 + lr)*1024 + lseg;
    const __nv_bfloat16* gBl = Blo + (size_t)(col0 + lr)*1024 + lseg;
    int sidx = lr * 16 + lseg;

    *(uint4*)&As[0][0][sidx] = *(const uint4*)(gAh);
    *(uint4*)&As[0][1][sidx] = *(const uint4*)(gAl);
    *(uint4*)&Bs[0][0][sidx] = *(const uint4*)(gBh);
    *(uint4*)&Bs[0][1][sidx] = *(const uint4*)(gBl);
    __syncthreads();

    int buf = 0;
    for (int kc = 1; ; kc++) {
        bool has = (kc < 64);
        uint4 nAh, nAl, nBh, nBl;
        if (has) {
            int k0 = kc * 16;
            nAh = *(const uint4*)(gAh + k0);
            nAl = *(const uint4*)(gAl + k0);
            nBh = *(const uint4*)(gBh + k0);
            nBl = *(const uint4*)(gBl + k0);
        }
        {
            const __nv_bfloat16* ah = As[buf][0];
            const __nv_bfloat16* al = As[buf][1];
            const __nv_bfloat16* bh = Bs[buf][0];
            const __nv_bfloat16* bl = Bs[buf][1];
            unsigned bfh[4][2], bfl[4][2];
            #pragma unroll
            for (int ni = 0; ni < 4; ni++) {
                int cb = (wn + ni*8 + lq) * 16;
                bfh[ni][0] = *(const unsigned*)(bh + cb + kq);
                bfh[ni][1] = *(const unsigned*)(bh + cb + kq + 8);
                bfl[ni][0] = *(const unsigned*)(bl + cb + kq);
                bfl[ni][1] = *(const unsigned*)(bl + cb + kq + 8);
            }
            #pragma unroll
            for (int mi = 0; mi < 2; mi++) {
                int rb = (wm + mi*16 + lq) * 16;
                unsigned ah0 = *(const unsigned*)(ah + rb + kq);
                unsigned ah1 = *(const unsigned*)(ah + rb + 128 + kq);
                unsigned ah2 = *(const unsigned*)(ah + rb + kq + 8);
                unsigned ah3 = *(const unsigned*)(ah + rb + 128 + kq + 8);
                unsigned al0 = *(const unsigned*)(al + rb + kq);
                unsigned al1 = *(const unsigned*)(al + rb + 128 + kq);
                unsigned al2 = *(const unsigned*)(al + rb + kq + 8);
                unsigned al3 = *(const unsigned*)(al + rb + 128 + kq + 8);
                #pragma unroll
                for (int ni = 0; ni < 4; ni++) {
                    MMA_BF16(acc[mi][ni], ah0, ah1, ah2, ah3, bfh[ni][0], bfh[ni][1]);
                    MMA_BF16(acc[mi][ni], ah0, ah1, ah2, ah3, bfl[ni][0], bfl[ni][1]);
                    MMA_BF16(acc[mi][ni], al0, al1, al2, al3, bfh[ni][0], bfh[ni][1]);
                }
            }
        }
        if (!has) break;
        int nb = buf ^ 1;
        *(uint4*)&As[nb][0][sidx] = nAh;
        *(uint4*)&As[nb][1][sidx] = nAl;
        *(uint4*)&Bs[nb][0][sidx] = nBh;
        *(uint4*)&Bs[nb][1][sidx] = nBl;
        __syncthreads();
        buf = nb;
    }

    #pragma unroll
    for (int mi = 0; mi < 2; mi++) {
        #pragma unroll
        for (int ni = 0; ni < 4; ni++) {
            int row = row0 + wm + mi*16 + lq;
            int col = col0 + wn + ni*8 + kq;
            float* d = acc[mi][ni];
            if (WHICH == 1) {
                C[(size_t)row*1024 + col]       = d[0];
                C[(size_t)row*1024 + col + 1]   = d[1];
                C[(size_t)(row+8)*1024 + col]   = d[2];
                C[(size_t)(row+8)*1024 + col+1] = d[3];
            } else {
                C[(size_t)row*1024 + col]       = 2.f*d[0] - xall[(size_t)row*1024 + col];
                C[(size_t)row*1024 + col + 1]   = 2.f*d[1] - xall[(size_t)row*1024 + col + 1];
                C[(size_t)(row+8)*1024 + col]   = 2.f*d[2] - xall[(size_t)(row+8)*1024 + col];
                C[(size_t)(row+8)*1024 + col+1] = 2.f*d[3] - xall[(size_t)(row+8)*1024 + col+1];
            }
        }
    }
}

// ---------------- bf16 hi/lo split (elementwise) ----------------
__global__ void bfsplit_k(const float* __restrict__ in, __nv_bfloat16* __restrict__ hi,
                          __nv_bfloat16* __restrict__ lo, int n)
{
    int g = blockIdx.x * 256 + threadIdx.x;
    if (g >= n) return;
    float v = in[g];
    __nv_bfloat16 h = __float2bfloat16(v);
    hi[g] = h;
    lo[g] = __float2bfloat16(v - __bfloat162float(h));
}

// ---------------- transpose + split: in fp32 [1024][1024] -> hi/lo [c][r] ----------
__global__ void tsplit_k(const float* __restrict__ in, __nv_bfloat16* __restrict__ hi,
                         __nv_bfloat16* __restrict__ lo)
{
    __shared__ float t[32][33];
    int r0 = blockIdx.y * 32, c0 = blockIdx.x * 32;
    int tx = threadIdx.x, ty = threadIdx.y;   // 32 x 8
    #pragma unroll
    for (int i = 0; i < 4; i++) {
        int r = ty + i*8;
        t[r][tx] = in[(size_t)(r0 + r)*1024 + c0 + tx];
    }
    __syncthreads();
    #pragma unroll
    for (int i = 0; i < 4; i++) {
        int c = ty + i*8;
        float v = t[tx][c];
        __nv_bfloat16 h = __float2bfloat16(v);
        size_t o = (size_t)(c0 + c)*1024 + r0 + tx;
        hi[o] = h;
        lo[o] = __float2bfloat16(v - __bfloat162float(h));
    }
}

// ---------------- x (B,N,D) -> XallT hi/lo [bd,node] bf16, tiled transpose ------
__global__ void xallT_k(const float* __restrict__ x, __nv_bfloat16* __restrict__ hi,
                        __nv_bfloat16* __restrict__ lo)
{
    __shared__ float t[64*33];
    int b = blockIdx.y, n0 = blockIdx.x * 32;
    int tid = threadIdx.x;
    for (int idx = tid; idx < 2048; idx += 256) {
        int ni = idx >> 6, c = idx & 63;
        t[c*33 + ni] = x[(size_t)b*65536 + (size_t)(n0 + ni)*64 + c];
    }
    __syncthreads();
    for (int idx = tid; idx < 2048; idx += 256) {
        int ni = idx & 31, c = idx >> 5;
        float v = t[c*33 + ni];
        __nv_bfloat16 h = __float2bfloat16(v);
        size_t o = (size_t)(b*64 + c)*1024 + n0 + ni;
        hi[o] = h;
        lo[o] = __float2bfloat16(v - __bfloat162float(h));
    }
}

// ---------------- causal conv (both directions) + silu (+ bf16 hi/lo out) --------
__global__ void conv_silu_k(const float* __restrict__ xz,
                            const float* __restrict__ cw0, const float* __restrict__ cb0,
                            const float* __restrict__ cw1, const float* __restrict__ cb1,
                            float* __restrict__ xc0, float* __restrict__ xc1,
                            __nv_bfloat16* __restrict__ xch, __nv_bfloat16* __restrict__ xcl)
{
    int dir = blockIdx.y;
    int g = blockIdx.x * 256 + threadIdx.x;
    int d = g & 127; int m = g >> 7; int l = m & 1023;
    const float* cw = dir ? cw1 : cw0;
    const float* cb = dir ? cb1 : cb0;
    const float* src = xz + dir * 256 + d;
    float acc = cb[d];
    #pragma unroll
    for (int k = 0; k < 4; k++) {
        int ll = dir ? (l + 3 - k) : (l - 3 + k);
        if (ll >= 0 && ll < 1024)
            acc = fmaf(src[(size_t)(m - l + ll) * 512], cw[d*4 + k], acc);
    }
    float v = silu_(acc);
    (dir ? xc1 : xc0)[g] = v;
    size_t o = (size_t)dir * 2097152 + g;
    __nv_bfloat16 hh = __float2bfloat16(v);
    xch[o] = hh;
    xcl[o] = __float2bfloat16(v - __bfloat162float(hh));
}

// ---------------- chunked selective scan: smem-staged ------------------------------
__global__ void __launch_bounds__(512) scan_p1(
    const float* __restrict__ dt0, const float* __restrict__ dt1,
    const float* __restrict__ xc0, const float* __restrict__ xc1,
    const float* __restrict__ B0,  const float* __restrict__ B1,
    const float* __restrict__ A0,  const float* __restrict__ A1,
    float* __restrict__ Hc, float* __restrict__ Ec)
{
    __shared__ float sdt[16][32], sxc[16][32], sB[16][16];
    int dir = blockIdx.z >> 4;
    int b   = blockIdx.z & 15;
    int c   = blockIdx.y;
    int t = threadIdx.x, s = t & 15, dl = t >> 4;
    int dbase = blockIdx.x * 32;
    int d = dbase + dl;
    const float* dt = (dir ? dt1 : dt0) + (size_t)b*131072 + dbase;
    const float* xc = (dir ? xc1 : xc0) + (size_t)b*131072 + dbase;
    const float* Bm = (dir ? B1 : B0)   + (size_t)b*16384;
    float Ads = (dir ? A1 : A0)[d*16 + s];
    int l0  = dir ? (1023 - c*CHLEN) : c*CHLEN;
    int stp = dir ? -1 : 1;

    int ltl = t >> 5, ldd = t & 31;
    int btl = t >> 4, bss = t & 15;

    {
        int l = l0 + stp * ltl;
        sdt[ltl][ldd] = dt[(size_t)l*128 + ldd];
        sxc[ltl][ldd] = xc[(size_t)l*128 + ldd];
        if (t < 256) {
            int l2 = l0 + stp * btl;
            sB[btl][bss] = Bm[(size_t)l2*16 + bss];
        }
    }
    __syncthreads();

    float h = 0.f, sacc = 0.f;
    for (int j = 0; j < 8; j++) {
        float pdt = 0.f, pxc = 0.f, pB = 0.f;
        if (j < 7) {
            int l = l0 + stp * ((j+1)*16 + ltl);
            pdt = dt[(size_t)l*128 + ldd];
            pxc = xc[(size_t)l*128 + ldd];
            if (t < 256) {
                int l2 = l0 + stp * ((j+1)*16 + btl);
                pB = Bm[(size_t)l2*16 + bss];
            }
        }
        #pragma unroll
        for (int tl = 0; tl < 16; tl++) {
            float dtv = sdt[tl][dl];
            float xcv = sxc[tl][dl];
            float Bv  = sB[tl][s];
            float e = __expf(dtv * Ads);
            h = fmaf(h, e, dtv * Bv * xcv);
            sacc += dtv;
        }
        __syncthreads();
        if (j < 7) {
            sdt[ltl][ldd] = pdt;
            sxc[ltl][ldd] = pxc;
            if (t < 256) sB[btl][bss] = pB;
        }
        __syncthreads();
    }
    size_t idx = ((((size_t)dir*16 + b)*NCHUNK + c)*128 + d)*16 + s;
    Hc[idx] = h;
    Ec[idx] = __expf(Ads * sacc);
}

__global__ void scan_comb(const float* __restrict__ Hc, const float* __restrict__ Ec,
                          float* __restrict__ h0arr)
{
    int g = blockIdx.x * 256 + threadIdx.x;
    int s = g & 15; int d = (g >> 4) & 127; int bb = g >> 11;
    float carry = 0.f;
    #pragma unroll
    for (int c = 0; c < NCHUNK; c++) {
        size_t idx = (((size_t)bb*NCHUNK + c)*128 + d)*16 + s;
        h0arr[idx] = carry;
        carry = fmaf(carry, Ec[idx], Hc[idx]);
    }
}

// Pass 2: replay; emits ycat as bf16 hi/lo for the out-proj tensor GEMM.
__global__ void __launch_bounds__(512) scan_p2(
    const float* __restrict__ dt0, const float* __restrict__ dt1,
    const float* __restrict__ xc0, const float* __restrict__ xc1,
    const float* __restrict__ B0,  const float* __restrict__ B1,
    const float* __restrict__ C0,  const float* __restrict__ C1,
    const float* __restrict__ xz,
    const float* __restrict__ A0,  const float* __restrict__ A1,
    const float* __restrict__ D0,  const float* __restrict__ D1,
    const float* __restrict__ h0arr,
    __nv_bfloat16* __restrict__ ych, __nv_bfloat16* __restrict__ ycl)
{
    __shared__ float sdt[16][32], sxc[16][32], sz[16][32], sB[16][16], sC[16][16];
    __shared__ float sy[16][32];
    int dir = blockIdx.z >> 4;
    int b   = blockIdx.z & 15;
    int c   = blockIdx.y;
    int t = threadIdx.x, s = t & 15, dl = t >> 4;
    int dbase = blockIdx.x * 32;
    int d = dbase + dl;
    const float* dt = (dir ? dt1 : dt0) + (size_t)b*131072 + dbase;
    const float* xc = (dir ? xc1 : xc0) + (size_t)b*131072 + dbase;
    const float* Bm = (dir ? B1 : B0)   + (size_t)b*16384;
    const float* Cm = (dir ? C1 : C0)   + (size_t)b*16384;
    const float* zb = xz + (size_t)b*524288 + dir*256 + 128 + dbase;
    __nv_bfloat16* ybh = ych + (size_t)b*262144 + dir*128 + dbase;
    __nv_bfloat16* ybl = ycl + (size_t)b*262144 + dir*128 + dbase;
    float Ads = (dir ? A1 : A0)[d*16 + s];
    float Dpd = (dir ? D1 : D0)[d];
    int l0  = dir ? (1023 - c*CHLEN) : c*CHLEN;
    int stp = dir ? -1 : 1;

    int ltl = t >> 5, ldd = t & 31;
    int btl = t >> 4, bss = t & 15;

    {
        int l = l0 + stp * ltl;
        sdt[ltl][ldd] = dt[(size_t)l*128 + ldd];
        sxc[ltl][ldd] = xc[(size_t)l*128 + ldd];
        sz[ltl][ldd]  = zb[(size_t)l*512 + ldd];
        if (t < 256) {
            int l2 = l0 + stp * btl;
            sB[btl][bss] = Bm[(size_t)l2*16 + bss];
            sC[btl][bss] = Cm[(size_t)l2*16 + bss];
        }
    }
    __syncthreads();

    size_t idx = ((((size_t)dir*16 + b)*NCHUNK + c)*128 + d)*16 + s;
    float h = h0arr[idx];

    for (int j = 0; j < 8; j++) {
        float pdt = 0.f, pxc = 0.f, pz = 0.f, pB = 0.f, pC = 0.f;
        if (j < 7) {
            int l = l0 + stp * ((j+1)*16 + ltl);
            pdt = dt[(size_t)l*128 + ldd];
            pxc = xc[(size_t)l*128 + ldd];
            pz  = zb[(size_t)l*512 + ldd];
            if (t < 256) {
                int l2 = l0 + stp * ((j+1)*16 + btl);
                pB = Bm[(size_t)l2*16 + bss];
                pC = Cm[(size_t)l2*16 + bss];
            }
        }
        #pragma unroll
        for (int tl = 0; tl < 16; tl++) {
            float dtv = sdt[tl][dl];
            float xcv = sxc[tl][dl];
            float Bv  = sB[tl][s];
            float Cv  = sC[tl][s];
            float e = __expf(dtv * Ads);
            h = fmaf(h, e, dtv * Bv * xcv);
            float part = h * Cv;
            part += __shfl_xor_sync(0xffffffffu, part, 8);
            part += __shfl_xor_sync(0xffffffffu, part, 4);
            part += __shfl_xor_sync(0xffffffffu, part, 2);
            part += __shfl_xor_sync(0xffffffffu, part, 1);
            if (s == 0)
                sy[tl][dl] = (part + Dpd * xcv) * silu_(sz[tl][dl]);
        }
        __syncthreads();
        {
            int l = l0 + stp * (j*16 + ltl);
            float v = sy[ltl][ldd];
            __nv_bfloat16 hh = __float2bfloat16(v);
            ybh[(size_t)l*256 + ldd] = hh;
            ybl[(size_t)l*256 + ldd] = __float2bfloat16(v - __bfloat162float(hh));
        }
        if (j < 7) {
            sdt[ltl][ldd] = pdt;
            sxc[ltl][ldd] = pxc;
            sz[ltl][ldd]  = pz;
            if (t < 256) { sB[btl][bss] = pB; sC[btl][bss] = pC; }
        }
        __syncthreads();
    }
}

// ---------------- support matrix: softmax(relu(E E^T)) ----------------
__global__ void __launch_bounds__(256) sup_k(const float* __restrict__ emb, float* __restrict__ sup)
{
    __shared__ float se[NNODE * EDIM];
    __shared__ float red[256];
    int n = blockIdx.x, tid = threadIdx.x;
    for (int i = tid; i < NNODE*EDIM; i += 256) se[i] = emb[i];
    __syncthreads();
    float en[EDIM];
    #pragma unroll
    for (int e = 0; e < EDIM; e++) en[e] = se[n*EDIM + e];
    float vals[4]; float mx = -1e30f;
    #pragma unroll
    for (int jj = 0; jj < 4; jj++) {
        int j = jj*256 + tid;
        float v = 0.f;
        #pragma unroll
        for (int e = 0; e < EDIM; e++) v = fmaf(en[e], se[j*EDIM + e], v);
        v = v > 0.f ? v : 0.f;
        vals[jj] = v; mx = fmaxf(mx, v);
    }
    red[tid] = mx; __syncthreads();
    for (int o = 128; o > 0; o >>= 1) { if (tid < o) red[tid] = fmaxf(red[tid], red[tid+o]); __syncthreads(); }
    mx = red[0]; __syncthreads();
    float s = 0.f;
    #pragma unroll
    for (int jj = 0; jj < 4; jj++) { vals[jj] = __expf(vals[jj] - mx); s += vals[jj]; }
    red[tid] = s; __syncthreads();
    for (int o = 128; o > 0; o >>= 1) { if (tid < o) red[tid] += red[tid+o]; __syncthreads(); }
    float inv = 1.f / red[0];
    #pragma unroll
    for (int jj = 0; jj < 4; jj++) sup[(size_t)n*1024 + jj*256 + tid] = vals[jj] * inv;
}

// ---------------- x (B,N,D) -> Xall (N, B*D) fp32 ----------------
__global__ void xall_k(const float* __restrict__ x, float* __restrict__ xall)
{
    int g = blockIdx.x * 256 + threadIdx.x;
    int c = g & 63, n = (g >> 6) & 1023, b = g >> 16;
    xall[(size_t)n*1024 + b*64 + c] = x[g];
}

// ---------------- W[n,k,c,o] = sum_e emb[n,e] W_pool[e,k,c,o] ----------------
__global__ void wmix_k(const float* __restrict__ emb, const float* __restrict__ wp,
                       float* __restrict__ W)
{
    int n = blockIdx.y;
    int j = blockIdx.x * 256 + threadIdx.x;
    float acc = 0.f;
    #pragma unroll
    for (int e = 0; e < EDIM; e++) acc = fmaf(emb[n*EDIM + e], wp[(size_t)e*12288 + j], acc);
    W[(size_t)n*12288 + j] = acc;
}

// ---------------- per-node graph conv ----------------
__global__ void __launch_bounds__(256) gconv_k(
    const float* __restrict__ x,  const float* __restrict__ xg1,
    const float* __restrict__ xg2, const float* __restrict__ W,
    const float* __restrict__ emb, const float* __restrict__ bp,
    float* __restrict__ go)
{
    __shared__ float xs[3072];
    __shared__ float bs[64];
    int n = blockIdx.x, tid = threadIdx.x;
    const float* Wn = W + (size_t)n * 12288;
    for (int i = tid; i < 3072; i += 256) {
        int k = i >> 10; int rem = i & 1023; int b = rem >> 6; int c = rem & 63;
        float v;
        if (k == 0) v = x[(size_t)b*65536 + (size_t)n*64 + c];
        else        v = (k == 1 ? xg1 : xg2)[(size_t)n*1024 + b*64 + c];
        xs[i] = v;
    }
    if (tid < 64) {
        float a = 0.f;
        #pragma unroll
        for (int e = 0; e < EDIM; e++) a = fmaf(emb[n*EDIM + e], bp[e*64 + tid], a);
        bs[tid] = a;
    }
    __syncthreads();
    int o = tid & 63, bq = tid >> 6;
    float acc[4];
    #pragma unroll
    for (int q = 0; q < 4; q++) acc[q] = bs[o];
    #pragma unroll 4
    for (int kc = 0; kc < 192; kc++) {
        float w = __ldg(Wn + kc*64 + o);
        int k = kc >> 6, c = kc & 63;
        #pragma unroll
        for (int q = 0; q < 4; q++)
            acc[q] = fmaf(xs[(k*16 + bq + q*4)*64 + c], w, acc[q]);
    }
    #pragma unroll
    for (int q = 0; q < 4; q++) {
        int b = bq + q*4;
        go[(size_t)b*65536 + (size_t)n*64 + o] = acc[q];
    }
}

// ---------------- launch ----------------
extern "C" void kernel_launch(void* const* d_in, const int* in_sizes, int n_in,
                              void* d_out, int out_size)
{
    const float* x_in     = (const float*)d_in[0];
    const float* fw_in    = (const float*)d_in[1];
    const float* fw_cw    = (const float*)d_in[2];
    const float* fw_cb    = (const float*)d_in[3];
    const float* fw_xp    = (const float*)d_in[4];
    const float* fw_dtw   = (const float*)d_in[5];
    const float* fw_dtb   = (const float*)d_in[6];
    const float* fw_Alog  = (const float*)d_in[7];
    const float* fw_D     = (const float*)d_in[8];
    const float* fw_out   = (const float*)d_in[9];
    const float* bw_in    = (const float*)d_in[10];
    const float* bw_cw    = (const float*)d_in[11];
    const float* bw_cb    = (const float*)d_in[12];
    const float* bw_xp    = (const float*)d_in[13];
    const float* bw_dtw   = (const float*)d_in[14];
    const float* bw_dtb   = (const float*)d_in[15];
    const float* bw_Alog  = (const float*)d_in[16];
    const float* bw_D     = (const float*)d_in[17];
    const float* bw_out   = (const float*)d_in[18];
    const float* ln1_g    = (const float*)d_in[19];
    const float* ln1_b    = (const float*)d_in[20];
    const float* ffn_w1   = (const float*)d_in[21];
    const float* ffn_b1   = (const float*)d_in[22];
    const float* ffn_w2   = (const float*)d_in[23];
    const float* ffn_b2   = (const float*)d_in[24];
    const float* ln2_g    = (const float*)d_in[25];
    const float* ln2_b    = (const float*)d_in[26];
    const float* node_emb = (const float*)d_in[27];
    const float* W_pool   = (const float*)d_in[28];
    const float* b_pool   = (const float*)d_in[29];
    const float* proj_w   = (const float*)d_in[30];
    const float* proj_b   = (const float*)d_in[31];
    float* outp = (float*)d_out;

    float* S = nullptr;
    cudaGetSymbolAddress((void**)&S, g_scratch);

    float* Wcat   = S;
    float* A0     = S + 73728;
    float* A1     = S + 75776;
    float* xz     = S + 77824;
    float* xc0    = S + 8466432;
    float* xc1    = S + 10563584;
    float* dt0    = S + 12660736;
    float* dt1    = S + 14757888;
    float* Bm0    = S + 16855040;
    float* Bm1    = S + 17117184;
    float* Cm0    = S + 17379328;
    float* Cm1    = S + 17641472;
    __nv_bfloat16* ych = (__nv_bfloat16*)(S + 17903616);   // (M,256) bf16
    __nv_bfloat16* ycl = (__nv_bfloat16*)(S + 20000768);
    float* xbuf   = S + 22097920;
    float* xln    = S + 23146496;
    float* xall   = S + 24195072;
    __nv_bfloat16* hbh = (__nv_bfloat16*)(S + 25243648);   // (M,256) bf16
    __nv_bfloat16* hbl = (__nv_bfloat16*)(S + 27340800);
    float* sup    = S + 29437952;
    float* xg1    = S + 31535104;
    float* xg2    = S + 32583680;
    float* Wbig   = S + 33632256;
    float* go     = S + 46215168;
    __nv_bfloat16* wocaTh = (__nv_bfloat16*)(S + 47263744);
    __nv_bfloat16* wocaTl = (__nv_bfloat16*)(S + 47271936);
    float* Hc     = S + 47280128;
    float* Ec     = S + 47804416;
    float* h0arr  = S + 48328704;
    __nv_bfloat16* sup_hi  = (__nv_bfloat16*)(S + 48852992);
    __nv_bfloat16* sup_lo  = (__nv_bfloat16*)(S + 49377280);
    __nv_bfloat16* xaT_hi  = (__nv_bfloat16*)(S + 49901568);
    __nv_bfloat16* xaT_lo  = (__nv_bfloat16*)(S + 50425856);
    __nv_bfloat16* xg1t_hi = (__nv_bfloat16*)(S + 50950144);
    __nv_bfloat16* xg1t_lo = (__nv_bfloat16*)(S + 51474432);
    __nv_bfloat16* wc0Th   = (__nv_bfloat16*)(S + 52031488);
    __nv_bfloat16* wc0Tl   = (__nv_bfloat16*)(S + 52041728);
    __nv_bfloat16* wc1Th   = (__nv_bfloat16*)(S + 52051968);
    __nv_bfloat16* wc1Tl   = (__nv_bfloat16*)(S + 52062208);
    __nv_bfloat16* w2Th    = (__nv_bfloat16*)(S + 52072448);
    __nv_bfloat16* w2Tl    = (__nv_bfloat16*)(S + 52080640);
    __nv_bfloat16* xch     = (__nv_bfloat16*)(S + 53121024);
    __nv_bfloat16* xcl     = (__nv_bfloat16*)(S + 55218176);

    // prep
    {
        int total = 32768 + 40960 + 4096 + 16384 + 16384 + MROWS*DMODEL;
        prep_k<<<(total + 255)/256, 256>>>(fw_in, bw_in, fw_xp, fw_dtw, bw_xp, bw_dtw,
                                           fw_Alog, bw_Alog, fw_out, bw_out, ffn_w2, x_in,
                                           Wcat, wc0Th, wc0Tl, wc1Th, wc1Tl,
                                           A0, A1, wocaTh, wocaTl, w2Th, w2Tl, xbuf);
    }

    for (int layer = 0; layer < 2; layer++) {
        // xz = x @ [fw_in | bw_in]  (fp32 engine — best for K=64)
        sgemm_k<0,0><<<dim3(8, 256), 256>>>(xbuf, Wcat, xz, MROWS, 512, 64,
                                            nullptr, nullptr, nullptr, nullptr,
                                            nullptr, nullptr, nullptr, nullptr);
        // conv + silu (+ bf16 hi/lo for xproj)
        conv_silu_k<<<dim3((MROWS*128)/256, 2), 256>>>(xz, fw_cw, fw_cb, bw_cw, bw_cb,
                                                       xc0, xc1, xch, xcl);
        // xproj both dirs (tensor cores)
        tcg_k<1,1><<<dim3(3, 512), 128>>>(xch, xcl, wc0Th, wc0Tl, wc1Th, wc1Tl,
                                          dt0, 2*MROWS, 160, 128,
                                          fw_dtb, bw_dtb, Bm0, Cm0, nullptr);
        // chunked selective scan (smem-staged); p2 emits ycat bf16 hi/lo
        scan_p1<<<dim3(4, NCHUNK, 32), 512>>>(dt0, dt1, xc0, xc1, Bm0, Bm1, A0, A1, Hc, Ec);
        scan_comb<<<256, 256>>>(Hc, Ec, h0arr);
        scan_p2<<<dim3(4, NCHUNK, 32), 512>>>(dt0, dt1, xc0, xc1, Bm0, Bm1, Cm0, Cm1,
                                              xz, A0, A1, fw_D, bw_D, h0arr, ych, ycl);
        // out-proj (tensor cores): x + ycat@Wocat, fused LN1 -> xln
        tcg_k<2,0><<<dim3(1, 256), 128>>>(ych, ycl, wocaTh, wocaTl, nullptr, nullptr,
                                          xln, MROWS, 64, 256,
                                          xbuf, nullptr, (float*)ln1_g, (float*)ln1_b, nullptr);
        // FFN1: relu(xln@W1 + b1) -> hbuf bf16 hi/lo (fp32 engine, K=64)
        sgemm_k<2,0><<<dim3(4, 256), 256>>>(xln, ffn_w1, nullptr, MROWS, 256, 64,
                                            ffn_b1, nullptr, nullptr, nullptr,
                                            nullptr, nullptr, hbh, hbl);
        // FFN2 (tensor cores): xln + hbuf@W2 + b2, fused LN2 -> xbuf
        tcg_k<3,0><<<dim3(1, 256), 128>>>(hbh, hbl, w2Th, w2Tl, nullptr, nullptr,
                                          xbuf, MROWS, 64, 256,
                                          xln, nullptr, (float*)ln2_g, (float*)ln2_b, ffn_b2);
    }

    // graph part
    sup_k<<<NNODE, 256>>>(node_emb, sup);
    bfsplit_k<<<4096, 256>>>(sup, sup_hi, sup_lo, NNODE*NNODE);
    xall_k<<<4096, 256>>>(xbuf, xall);
    xallT_k<<<dim3(32, 16), 256>>>(xbuf, xaT_hi, xaT_lo);

    tcmma_k<1><<<dim3(16, 16), 128>>>(sup_hi, sup_lo, xaT_hi, xaT_lo, xg1, nullptr);
    tsplit_k<<<dim3(32, 32), dim3(32, 8)>>>(xg1, xg1t_hi, xg1t_lo);
    tcmma_k<2><<<dim3(16, 16), 128>>>(sup_hi, sup_lo, xg1t_hi, xg1t_lo, xg2, xall);

    wmix_k<<<dim3(48, 1024), 256>>>(node_emb, W_pool, Wbig);
    gconv_k<<<NNODE, 256>>>(xbuf, xg1, xg2, Wbig, node_emb, b_pool, go);
    sgemm_k<6,0><<<dim3(2, 256), 256>>>(go, proj_w, outp, MROWS, 96, 64,
                                        proj_b, nullptr, nullptr, nullptr,
                                        nullptr, nullptr, nullptr, nullptr);
}

// round 17
// speedup vs baseline: 1.4400x; 1.0223x over previous
#include <cuda_runtime.h>
#include <cuda_bf16.h>
#include <math.h>

// ---------------- problem constants ----------------
#define BATCH   16
#define LSEQ    1024
#define DMODEL  64
#define DINNER  128
#define SSTATE  16
#define MROWS   (BATCH*LSEQ)   // 16384
#define HFFN    256
#define NNODE   1024
#define EDIM    10
#define PLOUT   96
#define NCHUNK  8
#define CHLEN   128
#define SSTR    24   // smem row stride (halves) for tc kernels: 48B, conflict-free

// ---------------- scratch (single static device buffer) ----------------
__device__ float g_scratch[57315328];

__device__ __forceinline__ float silu_(float x) { return x / (1.f + __expf(-x)); }

// ---------------- prep ------------------------------------------------------------
__global__ void prep_k(const float* __restrict__ fw_in, const float* __restrict__ bw_in,
                       const float* __restrict__ fwx, const float* __restrict__ fwdt,
                       const float* __restrict__ bwx, const float* __restrict__ bwdt,
                       const float* __restrict__ fwA, const float* __restrict__ bwA,
                       const float* __restrict__ fw_out, const float* __restrict__ bw_out,
                       const float* __restrict__ ffn_w2,
                       const float* __restrict__ x_in,
                       float* __restrict__ Wcat,
                       __nv_bfloat16* __restrict__ wc0Th, __nv_bfloat16* __restrict__ wc0Tl,
                       __nv_bfloat16* __restrict__ wc1Th, __nv_bfloat16* __restrict__ wc1Tl,
                       float* __restrict__ A0, float* __restrict__ A1,
                       __nv_bfloat16* __restrict__ wocaTh, __nv_bfloat16* __restrict__ wocaTl,
                       __nv_bfloat16* __restrict__ w2Th, __nv_bfloat16* __restrict__ w2Tl,
                       float* __restrict__ xbuf)
{
    int g = blockIdx.x * 256 + threadIdx.x;
    if (g < 32768) {  // Wcat (64,512) fp32
        int k = g >> 9, j = g & 511;
        Wcat[g] = (j < 256) ? fw_in[k*256 + j] : bw_in[k*256 + (j-256)];
        return;
    }
    int h = g - 32768;
    if (h < 40960) {  // WcombT per dir: [160][128] bf16 hi/lo
        int dir = h / 20480; int r2 = h % 20480;
        int j = r2 >> 7, i = r2 & 127;
        const float* Wx  = dir ? bwx  : fwx;
        const float* Wdt = dir ? bwdt : fwdt;
        float v;
        if (j < 128) {
            v = 0.f;
            #pragma unroll
            for (int r = 0; r < 4; r++) v = fmaf(Wx[i*36 + r], Wdt[r*128 + j], v);
        } else {
            v = Wx[i*36 + 4 + (j - 128)];
        }
        __nv_bfloat16 hh = __float2bfloat16(v);
        __nv_bfloat16 ll = __float2bfloat16(v - __bfloat162float(hh));
        if (dir) { wc1Th[j*128 + i] = hh; wc1Tl[j*128 + i] = ll; }
        else     { wc0Th[j*128 + i] = hh; wc0Tl[j*128 + i] = ll; }
        return;
    }
    h -= 40960;
    if (h < 4096) {  // A
        int dir = h >> 11; int i = h & 2047;
        (dir ? A1 : A0)[i] = -__expf((dir ? bwA : fwA)[i]);
        return;
    }
    h -= 4096;
    if (h < 16384) {  // WocatT [64][256] bf16 hi/lo
        int c = h >> 8, k = h & 255;
        float v = (k < 128) ? fw_out[k*64 + c] : bw_out[(k-128)*64 + c];
        __nv_bfloat16 hh = __float2bfloat16(v);
        wocaTh[c*256 + k] = hh;
        wocaTl[c*256 + k] = __float2bfloat16(v - __bfloat162float(hh));
        return;
    }
    h -= 16384;
    if (h < 16384) {  // ffn_w2T [64][256] bf16 hi/lo
        int o = h >> 8, k = h & 255;
        float v = ffn_w2[k*64 + o];
        __nv_bfloat16 hh = __float2bfloat16(v);
        w2Th[o*256 + k] = hh;
        w2Tl[o*256 + k] = __float2bfloat16(v - __bfloat162float(hh));
        return;
    }
    h -= 16384;
    if (h < MROWS*DMODEL) xbuf[h] = x_in[h];
}

// ---------------- generic tiled SGEMM, 64x64 tiles, double-buffered (fp32) --------
// EPI: 0 store, 2 bias+relu -> bf16 hi/lo only, 6 +aux0(col)
template<int EPI, int SPLIT>
__global__ void __launch_bounds__(256) sgemm_k(
    const float* __restrict__ A, const float* __restrict__ B, float* __restrict__ C,
    int M, int N, int K,
    const float* __restrict__ aux0, const float* __restrict__ aux1,
    float* __restrict__ o1, float* __restrict__ o2,
    const float* __restrict__ B2, const float* __restrict__ aux0b,
    __nv_bfloat16* __restrict__ ohi, __nv_bfloat16* __restrict__ olo)
{
    __shared__ float As[2][16][64];
    __shared__ float Bs[2][16][64];
    int row0 = blockIdx.y * 64, col0 = blockIdx.x * 64;
    if (SPLIT && row0 >= (M >> 1)) { B = B2; aux0 = aux0b; }
    int tid = threadIdx.x;
    int tx = tid & 15, ty = tid >> 4;
    int a_m = tid >> 2, a_k = (tid & 3) * 4;
    int b_k = tid >> 4, b_n = (tid & 15) * 4;
    const float* Aptr = A + (size_t)(row0 + a_m) * K + a_k;
    int bc = col0 + b_n;
    bool bok = bc < N;
    const float* Bptr = B + (size_t)b_k * N + bc;

    float acc[4][4];
    #pragma unroll
    for (int i = 0; i < 4; i++)
        #pragma unroll
        for (int j = 0; j < 4; j++) acc[i][j] = 0.f;

    {
        float4 av = *(const float4*)(Aptr);
        float4 bv = bok ? *(const float4*)(Bptr) : make_float4(0.f,0.f,0.f,0.f);
        As[0][a_k+0][a_m] = av.x; As[0][a_k+1][a_m] = av.y;
        As[0][a_k+2][a_m] = av.z; As[0][a_k+3][a_m] = av.w;
        *(float4*)&Bs[0][b_k][b_n] = bv;
    }
    __syncthreads();

    int buf = 0;
    for (int k0 = 16; ; k0 += 16) {
        bool has = (k0 < K);
        float4 av2, bv2;
        if (has) {
            av2 = *(const float4*)(Aptr + k0);
            bv2 = bok ? *(const float4*)(Bptr + (size_t)k0 * N) : make_float4(0.f,0.f,0.f,0.f);
        }
        #pragma unroll
        for (int kk = 0; kk < 16; kk++) {
            float am[4], bn[4];
            *(float4*)am = *(const float4*)&As[buf][kk][ty*4];
            *(float4*)bn = *(const float4*)&Bs[buf][kk][tx*4];
            #pragma unroll
            for (int i = 0; i < 4; i++)
                #pragma unroll
                for (int j = 0; j < 4; j++)
                    acc[i][j] = fmaf(am[i], bn[j], acc[i][j]);
        }
        if (!has) break;
        int nb = buf ^ 1;
        As[nb][a_k+0][a_m] = av2.x; As[nb][a_k+1][a_m] = av2.y;
        As[nb][a_k+2][a_m] = av2.z; As[nb][a_k+3][a_m] = av2.w;
        *(float4*)&Bs[nb][b_k][b_n] = bv2;
        __syncthreads();
        buf = nb;
    }

    #pragma unroll
    for (int i = 0; i < 4; i++) {
        int row = row0 + ty*4 + i;
        #pragma unroll
        for (int j = 0; j < 4; j++) {
            int col = col0 + tx*4 + j;
            if (col >= N) continue;
            float v = acc[i][j];
            size_t idx = (size_t)row * N + col;
            if (EPI == 0) {
                C[idx] = v;
            } else if (EPI == 2) {
                float t = v + aux0[col];
                t = t > 0.f ? t : 0.f;
                __nv_bfloat16 hh = __float2bfloat16(t);
                ohi[idx] = hh;
                olo[idx] = __float2bfloat16(t - __bfloat162float(hh));
            } else if (EPI == 6) {
                C[idx] = v + aux0[col];
            }
        }
    }
}

// ================= generalized bf16 split GEMM via mma.sync =================
// smem rows padded to SSTR=24 halves (48B) -> conflict-free fragment loads.
#define MMA_BF16(d, A0, A1, A2, A3, Bb0, Bb1) \
    asm volatile("mma.sync.aligned.m16n8k16.row.col.f32.bf16.bf16.f32 " \
                 "{%0,%1,%2,%3}, {%4,%5,%6,%7}, {%8,%9}, {%0,%1,%2,%3};" \
                 : "+f"((d)[0]), "+f"((d)[1]), "+f"((d)[2]), "+f"((d)[3]) \
                 : "r"(A0), "r"(A1), "r"(A2), "r"(A3), "r"(Bb0), "r"(Bb1))

template<int EPI, int SPLIT>
__global__ void __launch_bounds__(128) tcg_k(
    const __nv_bfloat16* __restrict__ Ahi, const __nv_bfloat16* __restrict__ Alo,
    const __nv_bfloat16* __restrict__ Bhi, const __nv_bfloat16* __restrict__ Blo,
    const __nv_bfloat16* __restrict__ B2hi, const __nv_bfloat16* __restrict__ B2lo,
    float* __restrict__ C, int M, int Nact, int K,
    const float* __restrict__ aux0, const float* __restrict__ aux0b,
    float* __restrict__ o1, float* __restrict__ o2,
    const float* __restrict__ bias)
{
    __shared__ __align__(16) __nv_bfloat16 As[2][2][64*SSTR];
    __shared__ __align__(16) __nv_bfloat16 Bs[2][2][64*SSTR];
    int tid = threadIdx.x, lane = tid & 31, warp = tid >> 5;
    int row0 = blockIdx.y * 64, col0 = blockIdx.x * 64;
    if (SPLIT && row0 >= (M >> 1)) { Bhi = B2hi; Blo = B2lo; aux0 = aux0b; }
    int wm = (warp & 1) * 32, wn = (warp >> 1) * 32;
    int lq = lane >> 2, kq = (lane & 3) * 2;

    float acc[2][4][4];
    #pragma unroll
    for (int mi = 0; mi < 2; mi++)
        #pragma unroll
        for (int ni = 0; ni < 4; ni++)
            #pragma unroll
            for (int q = 0; q < 4; q++) acc[mi][ni][q] = 0.f;

    int lr = tid >> 1, lseg = (tid & 1) * 8;
    const __nv_bfloat16* gAh = Ahi + (size_t)(row0 + lr)*K + lseg;
    const __nv_bfloat16* gAl = Alo + (size_t)(row0 + lr)*K + lseg;
    bool bok = (col0 + lr) < Nact;
    const __nv_bfloat16* gBh = Bhi + (size_t)(col0 + lr)*K + lseg;
    const __nv_bfloat16* gBl = Blo + (size_t)(col0 + lr)*K + lseg;
    int sidx = lr * SSTR + lseg;
    uint4 z4 = make_uint4(0,0,0,0);

    *(uint4*)&As[0][0][sidx] = *(const uint4*)(gAh);
    *(uint4*)&As[0][1][sidx] = *(const uint4*)(gAl);
    *(uint4*)&Bs[0][0][sidx] = bok ? *(const uint4*)(gBh) : z4;
    *(uint4*)&Bs[0][1][sidx] = bok ? *(const uint4*)(gBl) : z4;
    __syncthreads();

    int nkc = K >> 4;
    int buf = 0;
    for (int kc = 1; ; kc++) {
        bool has = (kc < nkc);
        uint4 nAh, nAl, nBh = z4, nBl = z4;
        if (has) {
            int k0 = kc * 16;
            nAh = *(const uint4*)(gAh + k0);
            nAl = *(const uint4*)(gAl + k0);
            if (bok) { nBh = *(const uint4*)(gBh + k0); nBl = *(const uint4*)(gBl + k0); }
        }
        {
            const __nv_bfloat16* ah = As[buf][0];
            const __nv_bfloat16* al = As[buf][1];
            const __nv_bfloat16* bh = Bs[buf][0];
            const __nv_bfloat16* bl = Bs[buf][1];
            unsigned bfh[4][2], bfl[4][2];
            #pragma unroll
            for (int ni = 0; ni < 4; ni++) {
                int cb = (wn + ni*8 + lq) * SSTR;
                bfh[ni][0] = *(const unsigned*)(bh + cb + kq);
                bfh[ni][1] = *(const unsigned*)(bh + cb + kq + 8);
                bfl[ni][0] = *(const unsigned*)(bl + cb + kq);
                bfl[ni][1] = *(const unsigned*)(bl + cb + kq + 8);
            }
            #pragma unroll
            for (int mi = 0; mi < 2; mi++) {
                int rb = (wm + mi*16 + lq) * SSTR;
                unsigned ah0 = *(const unsigned*)(ah + rb + kq);
                unsigned ah1 = *(const unsigned*)(ah + rb + 8*SSTR + kq);
                unsigned ah2 = *(const unsigned*)(ah + rb + kq + 8);
                unsigned ah3 = *(const unsigned*)(ah + rb + 8*SSTR + kq + 8);
                unsigned al0 = *(const unsigned*)(al + rb + kq);
                unsigned al1 = *(const unsigned*)(al + rb + 8*SSTR + kq);
                unsigned al2 = *(const unsigned*)(al + rb + kq + 8);
                unsigned al3 = *(const unsigned*)(al + rb + 8*SSTR + kq + 8);
                #pragma unroll
                for (int ni = 0; ni < 4; ni++) {
                    MMA_BF16(acc[mi][ni], ah0, ah1, ah2, ah3, bfh[ni][0], bfh[ni][1]);
                    MMA_BF16(acc[mi][ni], ah0, ah1, ah2, ah3, bfl[ni][0], bfl[ni][1]);
                    MMA_BF16(acc[mi][ni], al0, al1, al2, al3, bfh[ni][0], bfh[ni][1]);
                }
            }
        }
        if (!has) break;
        int nb = buf ^ 1;
        *(uint4*)&As[nb][0][sidx] = nAh;
        *(uint4*)&As[nb][1][sidx] = nAl;
        *(uint4*)&Bs[nb][0][sidx] = nBh;
        *(uint4*)&Bs[nb][1][sidx] = nBl;
        __syncthreads();
        buf = nb;
    }

    if (EPI == 2 || EPI == 3) {
        __shared__ float xt[64][65];
        __shared__ float red[64][2][2];
        #pragma unroll
        for (int mi = 0; mi < 2; mi++) {
            #pragma unroll
            for (int ni = 0; ni < 4; ni++) {
                #pragma unroll
                for (int q = 0; q < 4; q++) {
                    int rl = wm + mi*16 + lq + (q >> 1)*8;
                    int c  = wn + ni*8 + kq + (q & 1);
                    float v = acc[mi][ni][q] + aux0[(size_t)(row0 + rl)*64 + c];
                    if (EPI == 3) v += bias[c];
                    xt[rl][c] = v;
                }
            }
        }
        __syncthreads();
        int r = tid >> 1, half = tid & 1;
        float sm = 0.f, sq = 0.f;
        #pragma unroll
        for (int j = 0; j < 32; j++) {
            float v = xt[r][half*32 + j];
            sm += v; sq += v*v;
        }
        red[r][half][0] = sm; red[r][half][1] = sq;
        __syncthreads();
        sm = red[r][0][0] + red[r][1][0];
        sq = red[r][0][1] + red[r][1][1];
        float mean = sm * (1.f/64.f);
        float var  = sq * (1.f/64.f) - mean*mean;
        float rs = rsqrtf(var + 1e-5f);
        int row = row0 + r;
        #pragma unroll
        for (int j = 0; j < 32; j++) {
            int col = half*32 + j;
            C[(size_t)row*64 + col] = (xt[r][col] - mean) * rs * o1[col] + o2[col];
        }
        return;
    }

    #pragma unroll
    for (int mi = 0; mi < 2; mi++) {
        #pragma unroll
        for (int ni = 0; ni < 4; ni++) {
            int row = row0 + wm + mi*16 + lq;
            int col = col0 + wn + ni*8 + kq;
            float* d = acc[mi][ni];
            #pragma unroll
            for (int q = 0; q < 4; q++) {
                int r = row + (q >> 1) * 8;
                int c = col + (q & 1);
                float v = d[q];
                if (c < 128) {
                    float t = v + aux0[c];
                    C[(size_t)r*128 + c] = (t > 20.f) ? t : log1pf(__expf(t));
                } else if (c < 144) {
                    o1[(size_t)r*16 + (c - 128)] = v;
                } else if (c < 160) {
                    o2[(size_t)r*16 + (c - 144)] = v;
                }
            }
        }
    }
}

// ================= bf16 split GEMM for graph (fixed 1024^3) =================
template<int WHICH>
__global__ void __launch_bounds__(128) tcmma_k(
    const __nv_bfloat16* __restrict__ Ahi, const __nv_bfloat16* __restrict__ Alo,
    const __nv_bfloat16* __restrict__ Bhi, const __nv_bfloat16* __restrict__ Blo,
    float* __restrict__ C, const float* __restrict__ xall)
{
    __shared__ __align__(16) __nv_bfloat16 As[2][2][64*SSTR];
    __shared__ __align__(16) __nv_bfloat16 Bs[2][2][64*SSTR];
    int tid = threadIdx.x, lane = tid & 31, warp = tid >> 5;
    int row0 = blockIdx.y * 64, col0 = blockIdx.x * 64;
    int wm = (warp & 1) * 32, wn = (warp >> 1) * 32;
    int lq = lane >> 2, kq = (lane & 3) * 2;

    float acc[2][4][4];
    #pragma unroll
    for (int mi = 0; mi < 2; mi++)
        #pragma unroll
        for (int ni = 0; ni < 4; ni++)
            #pragma unroll
            for (int q = 0; q < 4; q++) acc[mi][ni][q] = 0.f;

    int lr = tid >> 1, lseg = (tid & 1) * 8;
    const __nv_bfloat16* gAh = Ahi + (size_t)(row0 + lr)*1024 + lseg;
    const __nv_bfloat16* gAl = Alo + (size_t)(row0 + lr)*1024 + lseg;
    const __nv_bfloat16* gBh = Bhi + (size_t)(col0 + lr)*1024 + lseg;
    const __nv_bfloat16* gBl = Blo + (size_t)(col0 + lr)*1024 + lseg;
    int sidx = lr * SSTR + lseg;

    *(uint4*)&As[0][0][sidx] = *(const uint4*)(gAh);
    *(uint4*)&As[0][1][sidx] = *(const uint4*)(gAl);
    *(uint4*)&Bs[0][0][sidx] = *(const uint4*)(gBh);
    *(uint4*)&Bs[0][1][sidx] = *(const uint4*)(gBl);
    __syncthreads();

    int buf = 0;
    for (int kc = 1; ; kc++) {
        bool has = (kc < 64);
        uint4 nAh, nAl, nBh, nBl;
        if (has) {
            int k0 = kc * 16;
            nAh = *(const uint4*)(gAh + k0);
            nAl = *(const uint4*)(gAl + k0);
            nBh = *(const uint4*)(gBh + k0);
            nBl = *(const uint4*)(gBl + k0);
        }
        {
            const __nv_bfloat16* ah = As[buf][0];
            const __nv_bfloat16* al = As[buf][1];
            const __nv_bfloat16* bh = Bs[buf][0];
            const __nv_bfloat16* bl = Bs[buf][1];
            unsigned bfh[4][2], bfl[4][2];
            #pragma unroll
            for (int ni = 0; ni < 4; ni++) {
                int cb = (wn + ni*8 + lq) * SSTR;
                bfh[ni][0] = *(const unsigned*)(bh + cb + kq);
                bfh[ni][1] = *(const unsigned*)(bh + cb + kq + 8);
                bfl[ni][0] = *(const unsigned*)(bl + cb + kq);
                bfl[ni][1] = *(const unsigned*)(bl + cb + kq + 8);
            }
            #pragma unroll
            for (int mi = 0; mi < 2; mi++) {
                int rb = (wm + mi*16 + lq) * SSTR;
                unsigned ah0 = *(const unsigned*)(ah + rb + kq);
                unsigned ah1 = *(const unsigned*)(ah + rb + 8*SSTR + kq);
                unsigned ah2 = *(const unsigned*)(ah + rb + kq + 8);
                unsigned ah3 = *(const unsigned*)(ah + rb + 8*SSTR + kq + 8);
                unsigned al0 = *(const unsigned*)(al + rb + kq);
                unsigned al1 = *(const unsigned*)(al + rb + 8*SSTR + kq);
                unsigned al2 = *(const unsigned*)(al + rb + kq + 8);
                unsigned al3 = *(const unsigned*)(al + rb + 8*SSTR + kq + 8);
                #pragma unroll
                for (int ni = 0; ni < 4; ni++) {
                    MMA_BF16(acc[mi][ni], ah0, ah1, ah2, ah3, bfh[ni][0], bfh[ni][1]);
                    MMA_BF16(acc[mi][ni], ah0, ah1, ah2, ah3, bfl[ni][0], bfl[ni][1]);
                    MMA_BF16(acc[mi][ni], al0, al1, al2, al3, bfh[ni][0], bfh[ni][1]);
                }
            }
        }
        if (!has) break;
        int nb = buf ^ 1;
        *(uint4*)&As[nb][0][sidx] = nAh;
        *(uint4*)&As[nb][1][sidx] = nAl;
        *(uint4*)&Bs[nb][0][sidx] = nBh;
        *(uint4*)&Bs[nb][1][sidx] = nBl;
        __syncthreads();
        buf = nb;
    }

    #pragma unroll
    for (int mi = 0; mi < 2; mi++) {
        #pragma unroll
        for (int ni = 0; ni < 4; ni++) {
            int row = row0 + wm + mi*16 + lq;
            int col = col0 + wn + ni*8 + kq;
            float* d = acc[mi][ni];
            if (WHICH == 1) {
                C[(size_t)row*1024 + col]       = d[0];
                C[(size_t)row*1024 + col + 1]   = d[1];
                C[(size_t)(row+8)*1024 + col]   = d[2];
                C[(size_t)(row+8)*1024 + col+1] = d[3];
            } else {
                C[(size_t)row*1024 + col]       = 2.f*d[0] - xall[(size_t)row*1024 + col];
                C[(size_t)row*1024 + col + 1]   = 2.f*d[1] - xall[(size_t)row*1024 + col + 1];
                C[(size_t)(row+8)*1024 + col]   = 2.f*d[2] - xall[(size_t)(row+8)*1024 + col];
                C[(size_t)(row+8)*1024 + col+1] = 2.f*d[3] - xall[(size_t)(row+8)*1024 + col+1];
            }
        }
    }
}

// ---------------- transpose + split: in fp32 [1024][1024] -> hi/lo [c][r] ----------
__global__ void tsplit_k(const float* __restrict__ in, __nv_bfloat16* __restrict__ hi,
                         __nv_bfloat16* __restrict__ lo)
{
    __shared__ float t[32][33];
    int r0 = blockIdx.y * 32, c0 = blockIdx.x * 32;
    int tx = threadIdx.x, ty = threadIdx.y;   // 32 x 8
    #pragma unroll
    for (int i = 0; i < 4; i++) {
        int r = ty + i*8;
        t[r][tx] = in[(size_t)(r0 + r)*1024 + c0 + tx];
    }
    __syncthreads();
    #pragma unroll
    for (int i = 0; i < 4; i++) {
        int c = ty + i*8;
        float v = t[tx][c];
        __nv_bfloat16 h = __float2bfloat16(v);
        size_t o = (size_t)(c0 + c)*1024 + r0 + tx;
        hi[o] = h;
        lo[o] = __float2bfloat16(v - __bfloat162float(h));
    }
}

// ---------------- x (B,N,D) -> XallT hi/lo [bd,node] bf16, tiled transpose ------
__global__ void xallT_k(const float* __restrict__ x, __nv_bfloat16* __restrict__ hi,
                        __nv_bfloat16* __restrict__ lo)
{
    __shared__ float t[64*33];
    int b = blockIdx.y, n0 = blockIdx.x * 32;
    int tid = threadIdx.x;
    for (int idx = tid; idx < 2048; idx += 256) {
        int ni = idx >> 6, c = idx & 63;
        t[c*33 + ni] = x[(size_t)b*65536 + (size_t)(n0 + ni)*64 + c];
    }
    __syncthreads();
    for (int idx = tid; idx < 2048; idx += 256) {
        int ni = idx & 31, c = idx >> 5;
        float v = t[c*33 + ni];
        __nv_bfloat16 h = __float2bfloat16(v);
        size_t o = (size_t)(b*64 + c)*1024 + n0 + ni;
        hi[o] = h;
        lo[o] = __float2bfloat16(v - __bfloat162float(h));
    }
}

// ---------------- causal conv (both directions) + silu (+ bf16 hi/lo out) --------
__global__ void conv_silu_k(const float* __restrict__ xz,
                            const float* __restrict__ cw0, const float* __restrict__ cb0,
                            const float* __restrict__ cw1, const float* __restrict__ cb1,
                            float* __restrict__ xc0, float* __restrict__ xc1,
                            __nv_bfloat16* __restrict__ xch, __nv_bfloat16* __restrict__ xcl)
{
    int dir = blockIdx.y;
    int g = blockIdx.x * 256 + threadIdx.x;
    int d = g & 127; int m = g >> 7; int l = m & 1023;
    const float* cw = dir ? cw1 : cw0;
    const float* cb = dir ? cb1 : cb0;
    const float* src = xz + dir * 256 + d;
    float acc = cb[d];
    #pragma unroll
    for (int k = 0; k < 4; k++) {
        int ll = dir ? (l + 3 - k) : (l - 3 + k);
        if (ll >= 0 && ll < 1024)
            acc = fmaf(src[(size_t)(m - l + ll) * 512], cw[d*4 + k], acc);
    }
    float v = silu_(acc);
    (dir ? xc1 : xc0)[g] = v;
    size_t o = (size_t)dir * 2097152 + g;
    __nv_bfloat16 hh = __float2bfloat16(v);
    xch[o] = hh;
    xcl[o] = __float2bfloat16(v - __bfloat162float(hh));
}

// ---------------- chunked selective scan: smem-staged ------------------------------
__global__ void __launch_bounds__(512) scan_p1(
    const float* __restrict__ dt0, const float* __restrict__ dt1,
    const float* __restrict__ xc0, const float* __restrict__ xc1,
    const float* __restrict__ B0,  const float* __restrict__ B1,
    const float* __restrict__ A0,  const float* __restrict__ A1,
    float* __restrict__ Hc, float* __restrict__ Ec)
{
    __shared__ float sdt[16][32], sxc[16][32], sB[16][16];
    int dir = blockIdx.z >> 4;
    int b   = blockIdx.z & 15;
    int c   = blockIdx.y;
    int t = threadIdx.x, s = t & 15, dl = t >> 4;
    int dbase = blockIdx.x * 32;
    int d = dbase + dl;
    const float* dt = (dir ? dt1 : dt0) + (size_t)b*131072 + dbase;
    const float* xc = (dir ? xc1 : xc0) + (size_t)b*131072 + dbase;
    const float* Bm = (dir ? B1 : B0)   + (size_t)b*16384;
    float Ads = (dir ? A1 : A0)[d*16 + s];
    int l0  = dir ? (1023 - c*CHLEN) : c*CHLEN;
    int stp = dir ? -1 : 1;

    int ltl = t >> 5, ldd = t & 31;
    int btl = t >> 4, bss = t & 15;

    {
        int l = l0 + stp * ltl;
        sdt[ltl][ldd] = dt[(size_t)l*128 + ldd];
        sxc[ltl][ldd] = xc[(size_t)l*128 + ldd];
        if (t < 256) {
            int l2 = l0 + stp * btl;
            sB[btl][bss] = Bm[(size_t)l2*16 + bss];
        }
    }
    __syncthreads();

    float h = 0.f, sacc = 0.f;
    for (int j = 0; j < 8; j++) {
        float pdt = 0.f, pxc = 0.f, pB = 0.f;
        if (j < 7) {
            int l = l0 + stp * ((j+1)*16 + ltl);
            pdt = dt[(size_t)l*128 + ldd];
            pxc = xc[(size_t)l*128 + ldd];
            if (t < 256) {
                int l2 = l0 + stp * ((j+1)*16 + btl);
                pB = Bm[(size_t)l2*16 + bss];
            }
        }
        #pragma unroll
        for (int tl = 0; tl < 16; tl++) {
            float dtv = sdt[tl][dl];
            float xcv = sxc[tl][dl];
            float Bv  = sB[tl][s];
            float e = __expf(dtv * Ads);
            h = fmaf(h, e, dtv * Bv * xcv);
            sacc += dtv;
        }
        __syncthreads();
        if (j < 7) {
            sdt[ltl][ldd] = pdt;
            sxc[ltl][ldd] = pxc;
            if (t < 256) sB[btl][bss] = pB;
        }
        __syncthreads();
    }
    size_t idx = ((((size_t)dir*16 + b)*NCHUNK + c)*128 + d)*16 + s;
    Hc[idx] = h;
    Ec[idx] = __expf(Ads * sacc);
}

__global__ void scan_comb(const float* __restrict__ Hc, const float* __restrict__ Ec,
                          float* __restrict__ h0arr)
{
    int g = blockIdx.x * 256 + threadIdx.x;
    int s = g & 15; int d = (g >> 4) & 127; int bb = g >> 11;
    float carry = 0.f;
    #pragma unroll
    for (int c = 0; c < NCHUNK; c++) {
        size_t idx = (((size_t)bb*NCHUNK + c)*128 + d)*16 + s;
        h0arr[idx] = carry;
        carry = fmaf(carry, Ec[idx], Hc[idx]);
    }
}

// Pass 2: replay; emits ycat as bf16 hi/lo.
__global__ void __launch_bounds__(512) scan_p2(
    const float* __restrict__ dt0, const float* __restrict__ dt1,
    const float* __restrict__ xc0, const float* __restrict__ xc1,
    const float* __restrict__ B0,  const float* __restrict__ B1,
    const float* __restrict__ C0,  const float* __restrict__ C1,
    const float* __restrict__ xz,
    const float* __restrict__ A0,  const float* __restrict__ A1,
    const float* __restrict__ D0,  const float* __restrict__ D1,
    const float* __restrict__ h0arr,
    __nv_bfloat16* __restrict__ ych, __nv_bfloat16* __restrict__ ycl)
{
    __shared__ float sdt[16][32], sxc[16][32], sz[16][32], sB[16][16], sC[16][16];
    __shared__ float sy[16][32];
    int dir = blockIdx.z >> 4;
    int b   = blockIdx.z & 15;
    int c   = blockIdx.y;
    int t = threadIdx.x, s = t & 15, dl = t >> 4;
    int dbase = blockIdx.x * 32;
    int d = dbase + dl;
    const float* dt = (dir ? dt1 : dt0) + (size_t)b*131072 + dbase;
    const float* xc = (dir ? xc1 : xc0) + (size_t)b*131072 + dbase;
    const float* Bm = (dir ? B1 : B0)   + (size_t)b*16384;
    const float* Cm = (dir ? C1 : C0)   + (size_t)b*16384;
    const float* zb = xz + (size_t)b*524288 + dir*256 + 128 + dbase;
    __nv_bfloat16* ybh = ych + (size_t)b*262144 + dir*128 + dbase;
    __nv_bfloat16* ybl = ycl + (size_t)b*262144 + dir*128 + dbase;
    float Ads = (dir ? A1 : A0)[d*16 + s];
    float Dpd = (dir ? D1 : D0)[d];
    int l0  = dir ? (1023 - c*CHLEN) : c*CHLEN;
    int stp = dir ? -1 : 1;

    int ltl = t >> 5, ldd = t & 31;
    int btl = t >> 4, bss = t & 15;

    {
        int l = l0 + stp * ltl;
        sdt[ltl][ldd] = dt[(size_t)l*128 + ldd];
        sxc[ltl][ldd] = xc[(size_t)l*128 + ldd];
        sz[ltl][ldd]  = zb[(size_t)l*512 + ldd];
        if (t < 256) {
            int l2 = l0 + stp * btl;
            sB[btl][bss] = Bm[(size_t)l2*16 + bss];
            sC[btl][bss] = Cm[(size_t)l2*16 + bss];
        }
    }
    __syncthreads();

    size_t idx = ((((size_t)dir*16 + b)*NCHUNK + c)*128 + d)*16 + s;
    float h = h0arr[idx];

    for (int j = 0; j < 8; j++) {
        float pdt = 0.f, pxc = 0.f, pz = 0.f, pB = 0.f, pC = 0.f;
        if (j < 7) {
            int l = l0 + stp * ((j+1)*16 + ltl);
            pdt = dt[(size_t)l*128 + ldd];
            pxc = xc[(size_t)l*128 + ldd];
            pz  = zb[(size_t)l*512 + ldd];
            if (t < 256) {
                int l2 = l0 + stp * ((j+1)*16 + btl);
                pB = Bm[(size_t)l2*16 + bss];
                pC = Cm[(size_t)l2*16 + bss];
            }
        }
        #pragma unroll
        for (int tl = 0; tl < 16; tl++) {
            float dtv = sdt[tl][dl];
            float xcv = sxc[tl][dl];
            float Bv  = sB[tl][s];
            float Cv  = sC[tl][s];
            float e = __expf(dtv * Ads);
            h = fmaf(h, e, dtv * Bv * xcv);
            float part = h * Cv;
            part += __shfl_xor_sync(0xffffffffu, part, 8);
            part += __shfl_xor_sync(0xffffffffu, part, 4);
            part += __shfl_xor_sync(0xffffffffu, part, 2);
            part += __shfl_xor_sync(0xffffffffu, part, 1);
            if (s == 0)
                sy[tl][dl] = (part + Dpd * xcv) * silu_(sz[tl][dl]);
        }
        __syncthreads();
        {
            int l = l0 + stp * (j*16 + ltl);
            float v = sy[ltl][ldd];
            __nv_bfloat16 hh = __float2bfloat16(v);
            ybh[(size_t)l*256 + ldd] = hh;
            ybl[(size_t)l*256 + ldd] = __float2bfloat16(v - __bfloat162float(hh));
        }
        if (j < 7) {
            sdt[ltl][ldd] = pdt;
            sxc[ltl][ldd] = pxc;
            sz[ltl][ldd]  = pz;
            if (t < 256) { sB[btl][bss] = pB; sC[btl][bss] = pC; }
        }
        __syncthreads();
    }
}

// ---------------- support matrix: softmax(relu(E E^T)) -> bf16 hi/lo --------------
__global__ void __launch_bounds__(256) sup_k(const float* __restrict__ emb,
                                             __nv_bfloat16* __restrict__ sup_hi,
                                             __nv_bfloat16* __restrict__ sup_lo)
{
    __shared__ float se[NNODE * EDIM];
    __shared__ float red[256];
    int n = blockIdx.x, tid = threadIdx.x;
    for (int i = tid; i < NNODE*EDIM; i += 256) se[i] = emb[i];
    __syncthreads();
    float en[EDIM];
    #pragma unroll
    for (int e = 0; e < EDIM; e++) en[e] = se[n*EDIM + e];
    float vals[4]; float mx = -1e30f;
    #pragma unroll
    for (int jj = 0; jj < 4; jj++) {
        int j = jj*256 + tid;
        float v = 0.f;
        #pragma unroll
        for (int e = 0; e < EDIM; e++) v = fmaf(en[e], se[j*EDIM + e], v);
        v = v > 0.f ? v : 0.f;
        vals[jj] = v; mx = fmaxf(mx, v);
    }
    red[tid] = mx; __syncthreads();
    for (int o = 128; o > 0; o >>= 1) { if (tid < o) red[tid] = fmaxf(red[tid], red[tid+o]); __syncthreads(); }
    mx = red[0]; __syncthreads();
    float s = 0.f;
    #pragma unroll
    for (int jj = 0; jj < 4; jj++) { vals[jj] = __expf(vals[jj] - mx); s += vals[jj]; }
    red[tid] = s; __syncthreads();
    for (int o = 128; o > 0; o >>= 1) { if (tid < o) red[tid] += red[tid+o]; __syncthreads(); }
    float inv = 1.f / red[0];
    #pragma unroll
    for (int jj = 0; jj < 4; jj++) {
        float v = vals[jj] * inv;
        __nv_bfloat16 hh = __float2bfloat16(v);
        size_t o = (size_t)n*1024 + jj*256 + tid;
        sup_hi[o] = hh;
        sup_lo[o] = __float2bfloat16(v - __bfloat162float(hh));
    }
}

// ---------------- x (B,N,D) -> Xall (N, B*D) fp32 ----------------
__global__ void xall_k(const float* __restrict__ x, float* __restrict__ xall)
{
    int g = blockIdx.x * 256 + threadIdx.x;
    int c = g & 63, n = (g >> 6) & 1023, b = g >> 16;
    xall[(size_t)n*1024 + b*64 + c] = x[g];
}

// ---------------- W[n,k,c,o] = sum_e emb[n,e] W_pool[e,k,c,o] ----------------
__global__ void wmix_k(const float* __restrict__ emb, const float* __restrict__ wp,
                       float* __restrict__ W)
{
    int n = blockIdx.y;
    int j = blockIdx.x * 256 + threadIdx.x;
    float acc = 0.f;
    #pragma unroll
    for (int e = 0; e < EDIM; e++) acc = fmaf(emb[n*EDIM + e], wp[(size_t)e*12288 + j], acc);
    W[(size_t)n*12288 + j] = acc;
}

// ---------------- per-node graph conv ----------------
__global__ void __launch_bounds__(256) gconv_k(
    const float* __restrict__ x,  const float* __restrict__ xg1,
    const float* __restrict__ xg2, const float* __restrict__ W,
    const float* __restrict__ emb, const float* __restrict__ bp,
    float* __restrict__ go)
{
    __shared__ float xs[3072];
    __shared__ float bs[64];
    int n = blockIdx.x, tid = threadIdx.x;
    const float* Wn = W + (size_t)n * 12288;
    for (int i = tid; i < 3072; i += 256) {
        int k = i >> 10; int rem = i & 1023; int b = rem >> 6; int c = rem & 63;
        float v;
        if (k == 0) v = x[(size_t)b*65536 + (size_t)n*64 + c];
        else        v = (k == 1 ? xg1 : xg2)[(size_t)n*1024 + b*64 + c];
        xs[i] = v;
    }
    if (tid < 64) {
        float a = 0.f;
        #pragma unroll
        for (int e = 0; e < EDIM; e++) a = fmaf(emb[n*EDIM + e], bp[e*64 + tid], a);
        bs[tid] = a;
    }
    __syncthreads();
    int o = tid & 63, bq = tid >> 6;
    float acc[4];
    #pragma unroll
    for (int q = 0; q < 4; q++) acc[q] = bs[o];
    #pragma unroll 4
    for (int kc = 0; kc < 192; kc++) {
        float w = __ldg(Wn + kc*64 + o);
        int k = kc >> 6, c = kc & 63;
        #pragma unroll
        for (int q = 0; q < 4; q++)
            acc[q] = fmaf(xs[(k*16 + bq + q*4)*64 + c], w, acc[q]);
    }
    #pragma unroll
    for (int q = 0; q < 4; q++) {
        int b = bq + q*4;
        go[(size_t)b*65536 + (size_t)n*64 + o] = acc[q];
    }
}

// ---------------- launch ----------------
extern "C" void kernel_launch(void* const* d_in, const int* in_sizes, int n_in,
                              void* d_out, int out_size)
{
    const float* x_in     = (const float*)d_in[0];
    const float* fw_in    = (const float*)d_in[1];
    const float* fw_cw    = (const float*)d_in[2];
    const float* fw_cb    = (const float*)d_in[3];
    const float* fw_xp    = (const float*)d_in[4];
    const float* fw_dtw   = (const float*)d_in[5];
    const float* fw_dtb   = (const float*)d_in[6];
    const float* fw_Alog  = (const float*)d_in[7];
    const float* fw_D     = (const float*)d_in[8];
    const float* fw_out   = (const float*)d_in[9];
    const float* bw_in    = (const float*)d_in[10];
    const float* bw_cw    = (const float*)d_in[11];
    const float* bw_cb    = (const float*)d_in[12];
    const float* bw_xp    = (const float*)d_in[13];
    const float* bw_dtw   = (const float*)d_in[14];
    const float* bw_dtb   = (const float*)d_in[15];
    const float* bw_Alog  = (const float*)d_in[16];
    const float* bw_D     = (const float*)d_in[17];
    const float* bw_out   = (const float*)d_in[18];
    const float* ln1_g    = (const float*)d_in[19];
    const float* ln1_b    = (const float*)d_in[20];
    const float* ffn_w1   = (const float*)d_in[21];
    const float* ffn_b1   = (const float*)d_in[22];
    const float* ffn_w2   = (const float*)d_in[23];
    const float* ffn_b2   = (const float*)d_in[24];
    const float* ln2_g    = (const float*)d_in[25];
    const float* ln2_b    = (const float*)d_in[26];
    const float* node_emb = (const float*)d_in[27];
    const float* W_pool   = (const float*)d_in[28];
    const float* b_pool   = (const float*)d_in[29];
    const float* proj_w   = (const float*)d_in[30];
    const float* proj_b   = (const float*)d_in[31];
    float* outp = (float*)d_out;

    float* S = nullptr;
    cudaGetSymbolAddress((void**)&S, g_scratch);

    float* Wcat   = S;
    float* A0     = S + 73728;
    float* A1     = S + 75776;
    float* xz     = S + 77824;
    float* xc0    = S + 8466432;
    float* xc1    = S + 10563584;
    float* dt0    = S + 12660736;
    float* dt1    = S + 14757888;
    float* Bm0    = S + 16855040;
    float* Bm1    = S + 17117184;
    float* Cm0    = S + 17379328;
    float* Cm1    = S + 17641472;
    __nv_bfloat16* ych = (__nv_bfloat16*)(S + 17903616);
    __nv_bfloat16* ycl = (__nv_bfloat16*)(S + 20000768);
    float* xbuf   = S + 22097920;
    float* xln    = S + 23146496;
    float* xall   = S + 24195072;
    __nv_bfloat16* hbh = (__nv_bfloat16*)(S + 25243648);
    __nv_bfloat16* hbl = (__nv_bfloat16*)(S + 27340800);
    float* xg1    = S + 31535104;
    float* xg2    = S + 32583680;
    float* Wbig   = S + 33632256;
    float* go     = S + 46215168;
    __nv_bfloat16* wocaTh = (__nv_bfloat16*)(S + 47263744);
    __nv_bfloat16* wocaTl = (__nv_bfloat16*)(S + 47271936);
    float* Hc     = S + 47280128;
    float* Ec     = S + 47804416;
    float* h0arr  = S + 48328704;
    __nv_bfloat16* sup_hi  = (__nv_bfloat16*)(S + 48852992);
    __nv_bfloat16* sup_lo  = (__nv_bfloat16*)(S + 49377280);
    __nv_bfloat16* xaT_hi  = (__nv_bfloat16*)(S + 49901568);
    __nv_bfloat16* xaT_lo  = (__nv_bfloat16*)(S + 50425856);
    __nv_bfloat16* xg1t_hi = (__nv_bfloat16*)(S + 50950144);
    __nv_bfloat16* xg1t_lo = (__nv_bfloat16*)(S + 51474432);
    __nv_bfloat16* wc0Th   = (__nv_bfloat16*)(S + 52031488);
    __nv_bfloat16* wc0Tl   = (__nv_bfloat16*)(S + 52041728);
    __nv_bfloat16* wc1Th   = (__nv_bfloat16*)(S + 52051968);
    __nv_bfloat16* wc1Tl   = (__nv_bfloat16*)(S + 52062208);
    __nv_bfloat16* w2Th    = (__nv_bfloat16*)(S + 52072448);
    __nv_bfloat16* w2Tl    = (__nv_bfloat16*)(S + 52080640);
    __nv_bfloat16* xch     = (__nv_bfloat16*)(S + 53121024);
    __nv_bfloat16* xcl     = (__nv_bfloat16*)(S + 55218176);

    // prep
    {
        int total = 32768 + 40960 + 4096 + 16384 + 16384 + MROWS*DMODEL;
        prep_k<<<(total + 255)/256, 256>>>(fw_in, bw_in, fw_xp, fw_dtw, bw_xp, bw_dtw,
                                           fw_Alog, bw_Alog, fw_out, bw_out, ffn_w2, x_in,
                                           Wcat, wc0Th, wc0Tl, wc1Th, wc1Tl,
                                           A0, A1, wocaTh, wocaTl, w2Th, w2Tl, xbuf);
    }

    for (int layer = 0; layer < 2; layer++) {
        sgemm_k<0,0><<<dim3(8, 256), 256>>>(xbuf, Wcat, xz, MROWS, 512, 64,
                                            nullptr, nullptr, nullptr, nullptr,
                                            nullptr, nullptr, nullptr, nullptr);
        conv_silu_k<<<dim3((MROWS*128)/256, 2), 256>>>(xz, fw_cw, fw_cb, bw_cw, bw_cb,
                                                       xc0, xc1, xch, xcl);
        tcg_k<1,1><<<dim3(3, 512), 128>>>(xch, xcl, wc0Th, wc0Tl, wc1Th, wc1Tl,
                                          dt0, 2*MROWS, 160, 128,
                                          fw_dtb, bw_dtb, Bm0, Cm0, nullptr);
        scan_p1<<<dim3(4, NCHUNK, 32), 512>>>(dt0, dt1, xc0, xc1, Bm0, Bm1, A0, A1, Hc, Ec);
        scan_comb<<<256, 256>>>(Hc, Ec, h0arr);
        scan_p2<<<dim3(4, NCHUNK, 32), 512>>>(dt0, dt1, xc0, xc1, Bm0, Bm1, Cm0, Cm1,
                                              xz, A0, A1, fw_D, bw_D, h0arr, ych, ycl);
        tcg_k<2,0><<<dim3(1, 256), 128>>>(ych, ycl, wocaTh, wocaTl, nullptr, nullptr,
                                          xln, MROWS, 64, 256,
                                          xbuf, nullptr, (float*)ln1_g, (float*)ln1_b, nullptr);
        sgemm_k<2,0><<<dim3(4, 256), 256>>>(xln, ffn_w1, nullptr, MROWS, 256, 64,
                                            ffn_b1, nullptr, nullptr, nullptr,
                                            nullptr, nullptr, hbh, hbl);
        tcg_k<3,0><<<dim3(1, 256), 128>>>(hbh, hbl, w2Th, w2Tl, nullptr, nullptr,
                                          xbuf, MROWS, 64, 256,
                                          xln, nullptr, (float*)ln2_g, (float*)ln2_b, ffn_b2);
    }

    // graph part
    sup_k<<<NNODE, 256>>>(node_emb, sup_hi, sup_lo);
    xall_k<<<4096, 256>>>(xbuf, xall);
    xallT_k<<<dim3(32, 16), 256>>>(xbuf, xaT_hi, xaT_lo);

    tcmma_k<1><<<dim3(16, 16), 128>>>(sup_hi, sup_lo, xaT_hi, xaT_lo, xg1, nullptr);
    tsplit_k<<<dim3(32, 32), dim3(32, 8)>>>(xg1, xg1t_hi, xg1t_lo);
    tcmma_k<2><<<dim3(16, 16), 128>>>(sup_hi, sup_lo, xg1t_hi, xg1t_lo, xg2, xall);

    wmix_k<<<dim3(48, 1024), 256>>>(node_emb, W_pool, Wbig);
    gconv_k<<<NNODE, 256>>>(xbuf, xg1, xg2, Wbig, node_emb, b_pool, go);
    sgemm_k<6,0><<<dim3(2, 256), 256>>>(go, proj_w, outp, MROWS, 96, 64,
                                        proj_b, nullptr, nullptr, nullptr,
                                        nullptr, nullptr, nullptr, nullptr);
}